// round 10
// baseline (speedup 1.0000x reference)
#include <cuda_runtime.h>
#include <math.h>
#include <stdint.h>

// Problem constants
#define NV 1024
#define NE 32768
#define EMBD 128
#define HIDD 64
#define REPD 32

// ---------------- scratch (static device globals) ----------------
__device__ float g_A[2][3][NV][NV];
__device__ float g_p1[2][16][512][512];
__device__ float g_p2[2][4][257][257];
__device__ float g_att[2][3][NV][NV];
__device__ float g_M[2][NV][NV];
__device__ float g_Mt[2][NV][NV];
__device__ float g_An[NV][NV];
__device__ float g_dinv[6][NV];
__device__ float g_deg[5][NV];
__device__ float g_diag[5][NV];
__device__ float g_XW[NV][HIDD];
__device__ float g_H[NV][HIDD];
__device__ float g_HW[NV][REPD];

// ---------------- param structs ----------------
struct Sc5 { const int* e[5]; float* A[5]; float* degz; };
struct PathPtrs {
    const float* in[2]; const float* w[2]; const float* b[2]; float* out[2];
};
struct FAtt {
    const float* p2[2]; const float* w1[2]; const float* b1[2];
    const float* w2[2]; const float* b2[2]; const float* A[2]; float* att[2];
    float* deg[2]; float* diag[2];
};
struct GemS {
    const float* A[2]; const float* B[2]; float* C[2];
    const float* degIn[2]; const float* diagIn[2];
    float* deg[2]; float* diag[2];
};

// ---------------- helpers ----------------
__device__ __forceinline__ uint32_t f2tf(float f) {
    uint32_t r;
    asm("cvt.rna.tf32.f32 %0, %1;" : "=r"(r) : "f"(f));
    return r;
}

__device__ __forceinline__ void mma_tf32(float* c, const uint32_t* a, uint32_t b0, uint32_t b1) {
    asm volatile(
        "mma.sync.aligned.m16n8k8.row.col.f32.tf32.tf32.f32 "
        "{%0,%1,%2,%3}, {%4,%5,%6,%7}, {%8,%9}, {%0,%1,%2,%3};"
        : "+f"(c[0]), "+f"(c[1]), "+f"(c[2]), "+f"(c[3])
        : "r"(a[0]), "r"(a[1]), "r"(a[2]), "r"(a[3]), "r"(b0), "r"(b1));
}

// ---------------- kernels ----------------

__global__ void scatter_all(Sc5 s) {
    int j = blockIdx.y;
    int k = blockIdx.x * blockDim.x + threadIdx.x;
    if (j == 0 && k < 5 * NV) s.degz[k] = 0.0f;
    if (k < NE) {
        const int* e = s.e[j];
        atomicAdd(&s.A[j][e[k] * NV + e[NE + k]], 1.0f);
    }
}

// ---- conv1 (3x3, pad1, L->16) + relu + maxpool2 via tf32 MMA (fp32-exact hi/lo) ----
template <int L>
__device__ __forceinline__ void conv1mma_impl(const float* __restrict__ A,
                                              const float* __restrict__ w,
                                              const float* __restrict__ b,
                                              float* __restrict__ p1,
                                              float* __restrict__ tile,
                                              float* __restrict__ whi,
                                              float* __restrict__ wlo,
                                              float* __restrict__ sb) {
    constexpr int KS = (L * 9 + 7) / 8;
    int t = threadIdx.y * 16 + threadIdx.x;
    int lane = t & 31, wid = t >> 5;

    for (int i = t; i < 512; i += 256) {
        int oc = i >> 5, k = i & 31;
        float wv = (k < L * 9) ? w[oc * L * 9 + k] : 0.0f;
        float hi = __uint_as_float(f2tf(wv));
        whi[i] = hi;
        wlo[i] = __uint_as_float(f2tf(wv - hi));
    }
    if (t < 16) sb[t] = b[t];

    int gy0 = blockIdx.y * 32 - 1, gx0 = blockIdx.x * 32 - 1;
    for (int l = 0; l < L; l++)
        for (int i = t; i < 34 * 34; i += 256) {
            int r = i / 34, c = i % 34;
            int gy = gy0 + r, gx = gx0 + c;
            tile[(l * 34 + r) * 36 + c] = (gy >= 0 && gy < NV && gx >= 0 && gx < NV)
                                              ? A[((size_t)l * NV + gy) * NV + gx] : 0.0f;
        }
    __syncthreads();

    uint32_t ahi[KS][4], alo[KS][4];
    int r0 = (lane >> 2) * 32, r1 = ((lane >> 2) + 8) * 32;
#pragma unroll
    for (int s = 0; s < KS; s++) {
        int c0 = 8 * s + (lane & 3);
        ahi[s][0] = __float_as_uint(whi[r0 + c0]);
        ahi[s][1] = __float_as_uint(whi[r1 + c0]);
        ahi[s][2] = __float_as_uint(whi[r0 + c0 + 4]);
        ahi[s][3] = __float_as_uint(whi[r1 + c0 + 4]);
        alo[s][0] = __float_as_uint(wlo[r0 + c0]);
        alo[s][1] = __float_as_uint(wlo[r1 + c0]);
        alo[s][2] = __float_as_uint(wlo[r0 + c0 + 4]);
        alo[s][3] = __float_as_uint(wlo[r1 + c0 + 4]);
    }

    int boff[KS][2];
#pragma unroll
    for (int s = 0; s < KS; s++)
#pragma unroll
        for (int h = 0; h < 2; h++) {
            int k = 8 * s + (lane & 3) + 4 * h;
            if (k >= L * 9) k = 0;
            int l = k / 9, r = k % 9;
            boff[s][h] = (l * 34 + r / 3) * 36 + (r % 3) + (lane >> 2);
        }

    for (int u = wid; u < 64; u += 8) {
        int py = u >> 2, ux = u & 3;
        int base0 = (2 * py) * 36 + 8 * ux;
        int base1 = base0 + 36;
        float acc0[4] = {0.f, 0.f, 0.f, 0.f};
        float acc1[4] = {0.f, 0.f, 0.f, 0.f};
#pragma unroll
        for (int s = 0; s < KS; s++) {
            uint32_t b00 = __float_as_uint(tile[boff[s][0] + base0]);
            uint32_t b01 = __float_as_uint(tile[boff[s][1] + base0]);
            mma_tf32(acc0, ahi[s], b00, b01);
            mma_tf32(acc0, alo[s], b00, b01);
            uint32_t b10 = __float_as_uint(tile[boff[s][0] + base1]);
            uint32_t b11 = __float_as_uint(tile[boff[s][1] + base1]);
            mma_tf32(acc1, ahi[s], b10, b11);
            mma_tf32(acc1, alo[s], b10, b11);
        }
        int oc0 = lane >> 2, oc1 = oc0 + 8;
        int ox = blockIdx.x * 16 + 4 * ux + (lane & 3);
        int oy = blockIdx.y * 16 + py;
        float m0 = fmaxf(fmaxf(acc0[0], acc0[1]), fmaxf(acc1[0], acc1[1]));
        float m1 = fmaxf(fmaxf(acc0[2], acc0[3]), fmaxf(acc1[2], acc1[3]));
        p1[((size_t)oc0 * 512 + oy) * 512 + ox] = fmaxf(m0 + sb[oc0], 0.0f);
        p1[((size_t)oc1 * 512 + oy) * 512 + ox] = fmaxf(m1 + sb[oc1], 0.0f);
    }
}

__global__ void __launch_bounds__(256) conv1mma_both(PathPtrs p) {
    __shared__ float tile[3 * 34 * 36];
    __shared__ float whi[512], wlo[512];
    __shared__ float sb[16];
    int path = blockIdx.z;
    if (path == 0)
        conv1mma_impl<2>(p.in[0], p.w[0], p.b[0], p.out[0], tile, whi, wlo, sb);
    else
        conv1mma_impl<3>(p.in[1], p.w[1], p.b[1], p.out[1], tile, whi, wlo, sb);
}

// ---- conv2 (3x3, pad2, 16->4) + relu + maxpool2 ----
// 8 channels staged per smem phase (43.8KB): syncs drop 32 -> 4; staging loops
// have no per-slot register state so regs stay low; 4 CTAs/SM = single wave.
__global__ void __launch_bounds__(256) conv2pool_both(PathPtrs pp) {
    __shared__ float tile[8 * 1368];   // 8 ch x 36 rows x 38 stride
    __shared__ float sw[576];
    __shared__ float sb[4];
    int path = blockIdx.z;
    const float* p1 = pp.in[path];
    float* p2 = pp.out[path];
    int tx = threadIdx.x, ty = threadIdx.y;
    int t = ty * 16 + tx;
    for (int i = t; i < 576; i += 256) sw[i] = pp.w[path][i];
    if (t < 4) sb[t] = pp.b[path][t];

    int gy0 = blockIdx.y * 32 - 2, gx0 = blockIdx.x * 32 - 2;

    float acc[4][2][2];
#pragma unroll
    for (int oc = 0; oc < 4; oc++)
#pragma unroll
        for (int py = 0; py < 2; py++)
#pragma unroll
            for (int px = 0; px < 2; px++) acc[oc][py][px] = 0.0f;

    for (int g = 0; g < 2; g++) {
        __syncthreads();
        // stage channels 8g .. 8g+7 (plain strided copy; LDGs pipeline freely)
        for (int ch = 0; ch < 8; ch++) {
            const float* src = p1 + (size_t)(g * 8 + ch) * 512 * 512;
            float* dst = tile + ch * 1368;
            for (int i = t; i < 1296; i += 256) {
                int row = i / 36, col = i - row * 36;
                int gy = gy0 + row, gx = gx0 + col;
                dst[row * 38 + col] = (gy >= 0 && gy < 512 && gx >= 0 && gx < 512)
                                          ? src[(size_t)gy * 512 + gx] : 0.0f;
            }
        }
        __syncthreads();
#pragma unroll
        for (int cc = 0; cc < 8; cc++) {
            int ci = g * 8 + cc;
            float patch[4][4];
#pragma unroll
            for (int rw = 0; rw < 4; rw++)
#pragma unroll
                for (int c = 0; c < 4; c++)
                    patch[rw][c] = tile[cc * 1368 + (2 * ty + rw) * 38 + 2 * tx + c];
#pragma unroll
            for (int oc = 0; oc < 4; oc++)
#pragma unroll
                for (int ky = 0; ky < 3; ky++)
#pragma unroll
                    for (int kx = 0; kx < 3; kx++) {
                        float wv = sw[((oc * 16 + ci) * 3 + ky) * 3 + kx];
                        acc[oc][0][0] += wv * patch[ky][kx];
                        acc[oc][0][1] += wv * patch[ky][kx + 1];
                        acc[oc][1][0] += wv * patch[ky + 1][kx];
                        acc[oc][1][1] += wv * patch[ky + 1][kx + 1];
                    }
        }
    }
    int x = blockIdx.x * 16 + tx, y = blockIdx.y * 16 + ty;
    if (x < 257 && y < 257) {
#pragma unroll
        for (int oc = 0; oc < 4; oc++) {
            float m = fmaxf(fmaxf(acc[oc][0][0], acc[oc][0][1]),
                            fmaxf(acc[oc][1][0], acc[oc][1][1])) + sb[oc];
            p2[((size_t)oc * 257 + y) * 257 + x] = fmaxf(m, 0.0f);
        }
    }
}

// ---- fused tconv1 + tconv2 + sigmoid + crop + adjacency multiply + att0 deg/diag ----
template <int L>
__device__ __forceinline__ void ftconv4_impl(const float* __restrict__ p2,
                                             const float* __restrict__ sw1,
                                             const float* __restrict__ sb1,
                                             const float* __restrict__ sw2,
                                             const float* __restrict__ sb2,
                                             const float* __restrict__ A,
                                             float* __restrict__ att,
                                             float* __restrict__ deg,
                                             float* __restrict__ diag,
                                             int q, int y) {
    int ky2 = (y + 1) & 1;
    int iy1 = (y - 1 + ky2) >> 1;
    int ky1 = (iy1 + 1) & 1;
    int iy0 = (iy1 - 1 + ky1) >> 1;

    float p[4];
#pragma unroll
    for (int cj = 0; cj < 4; cj++) p[cj] = p2[((size_t)cj * 257 + iy0) * 257 + q];

    float tA[16], tB[16];
#pragma unroll
    for (int ci = 0; ci < 16; ci++) {
        float sA = sb1[ci], sB = sb1[ci];
#pragma unroll
        for (int cj = 0; cj < 4; cj++) {
            int base = ((ci * 4 + cj) * 2 + ky1) * 2;
            sA += sw1[base + 1] * p[cj];
            sB += sw1[base + 0] * p[cj];
        }
        tA[ci] = fmaxf(sA, 0.0f);
        tB[ci] = fmaxf(sB, 0.0f);
    }

    float d0 = 0.f, d1 = 0.f, d2 = 0.f, d3 = 0.f;
#pragma unroll
    for (int l = 0; l < L; l++) {
        float s0A = sb2[l], s1A = sb2[l], s0B = sb2[l], s1B = sb2[l];
#pragma unroll
        for (int ci = 0; ci < 16; ci++) {
            int base = ((l * 16 + ci) * 2 + ky2) * 2;
            float w1v = sw2[base + 1], w0v = sw2[base + 0];
            s0A += w1v * tA[ci]; s1A += w0v * tA[ci];
            s0B += w1v * tB[ci]; s1B += w0v * tB[ci];
        }
        float g0 = 1.0f / (1.0f + expf(-s0A));
        float g1 = 1.0f / (1.0f + expf(-s1A));
        float g2 = 1.0f / (1.0f + expf(-s0B));
        float g3 = 1.0f / (1.0f + expf(-s1B));
        size_t off = (size_t)l * NV * NV + (size_t)y * NV + 4 * q;
        float4 a = *(const float4*)&A[off];
        float4 v = make_float4(a.x * g0, a.y * g1, a.z * g2, a.w * g3);
        *(float4*)&att[off] = v;
        if (l == 0) { d0 = v.x; d1 = v.y; d2 = v.z; d3 = v.w; }
    }

    float s = (d0 + d1) + (d2 + d3);
#pragma unroll
    for (int o = 16; o > 0; o >>= 1) s += __shfl_xor_sync(0xFFFFFFFF, s, o);
    if ((threadIdx.x & 31) == 0) atomicAdd(&deg[y], s);
    if ((y >> 2) == q) {
        int sel = y & 3;
        diag[y] = sel == 0 ? d0 : sel == 1 ? d1 : sel == 2 ? d2 : d3;
    }
}

__global__ void ftconv_att_both(FAtt fa) {
    __shared__ float sw1[256], sb1[16], sw2[192], sb2[3];
    int gidx = blockIdx.x * blockDim.x + threadIdx.x;
    const int PL = NV * 256;
    int path = gidx / PL;
    int idx = gidx - path * PL;
    int q = idx & 255, y = idx >> 8;
    const int L = (path == 0) ? 2 : 3;
    int t = threadIdx.x;
    if (t < 256) sw1[t] = fa.w1[path][t];
    if (t < 16) sb1[t] = fa.b1[path][t];
    for (int i = t; i < L * 64; i += 256) sw2[i] = fa.w2[path][i];
    if (t < L) sb2[t] = fa.b2[path][t];
    __syncthreads();
    if (path == 0)
        ftconv4_impl<2>(fa.p2[0], sw1, sb1, sw2, sb2, fa.A[0], fa.att[0],
                        fa.deg[0], fa.diag[0], q, y);
    else
        ftconv4_impl<3>(fa.p2[1], sw1, sb1, sw2, sb2, fa.A[1], fa.att[1],
                        fa.deg[1], fa.diag[1], q, y);
}

// ---- dinv from accumulated deg/diag ----
__global__ void dinv_fix(const float* __restrict__ deg, const float* __restrict__ diag,
                         float* __restrict__ dv, int n) {
    int i = blockIdx.x * blockDim.x + threadIdx.x;
    if (i < n) {
        float d = deg[i];
        if (diag[i] == 0.0f) d += 1.0f;
        dv[i] = d > 0.0f ? rsqrtf(d) : 0.0f;
    }
}

// ---- scaled max-merge + row-sum/dinv ----
__global__ void emax_dinv(const float* __restrict__ a, const float* __restrict__ dva,
                          const float* __restrict__ b, const float* __restrict__ dvb,
                          float* __restrict__ o, float* __restrict__ dv) {
    int row = blockIdx.x;
    float dar = dva[row], dbr = dvb[row];
    __shared__ float sh[256];
    __shared__ float sdiag;
    float s = 0.0f;
    for (int j = threadIdx.x; j < NV; j += 256) {
        float va = a[(size_t)row * NV + j];
        if (j == row && va == 0.0f) va = 1.0f;
        va *= dar * dva[j];
        float vb = b[(size_t)row * NV + j];
        if (j == row && vb == 0.0f) vb = 1.0f;
        vb *= dbr * dvb[j];
        float v = fmaxf(va, vb);
        o[(size_t)row * NV + j] = v;
        if (j == row) sdiag = v;
        s += v;
    }
    sh[threadIdx.x] = s;
    __syncthreads();
    for (int off = 128; off > 0; off >>= 1) {
        if (threadIdx.x < off) sh[threadIdx.x] += sh[threadIdx.x + off];
        __syncthreads();
    }
    if (threadIdx.x == 0) {
        float d = sh[0];
        if (sdiag == 0.0f) d += 1.0f;
        dv[row] = d > 0.0f ? rsqrtf(d) : 0.0f;
    }
}

// ---------------- tf32 GEMM: dv computed in prologue from deg/diag; norm fused ----
__device__ __forceinline__ void fix_scale4(float4& v, int row, int kc, float dvr,
                                           const float* __restrict__ dv) {
    float4 dk = *(const float4*)&dv[kc];
    float* p = &v.x;
#pragma unroll
    for (int q = 0; q < 4; q++)
        if (row == kc + q && p[q] == 0.0f) p[q] = 1.0f;
    v.x *= dvr * dk.x; v.y *= dvr * dk.y; v.z *= dvr * dk.z; v.w *= dvr * dk.w;
}

__global__ void __launch_bounds__(256) tf32gemm_s(GemS g) {
    const float* __restrict__ A = g.A[blockIdx.z];
    const float* __restrict__ B = g.B[blockIdx.z];
    float* __restrict__ C = g.C[blockIdx.z];
    const float* __restrict__ degIn = g.degIn[blockIdx.z];
    const float* __restrict__ diagIn = g.diagIn[blockIdx.z];
    float* __restrict__ deg = g.deg[blockIdx.z];
    float* __restrict__ diag = g.diag[blockIdx.z];
    const int Nn = NV, K = NV;

    __shared__ float As[2][16][136];
    __shared__ float Bs[2][16][72];
    __shared__ __align__(16) float sdv[NV];

    const int tid = threadIdx.x;
    const int lane = tid & 31;
    const int wid = tid >> 5;
    const int wr = wid & 3;
    const int wc = wid >> 2;
    const int m0 = blockIdx.y * 128;
    const int n0 = blockIdx.x * 64;

    for (int i = tid; i < NV; i += 256) {
        float d = degIn[i];
        if (diagIn[i] == 0.0f) d += 1.0f;
        sdv[i] = d > 0.0f ? rsqrtf(d) : 0.0f;
    }
    __syncthreads();

    float acc[2][4][4];
#pragma unroll
    for (int mi = 0; mi < 2; mi++)
#pragma unroll
        for (int ni = 0; ni < 4; ni++)
#pragma unroll
            for (int r = 0; r < 4; r++) acc[mi][ni][r] = 0.0f;

    const int ar = tid >> 2;
    const int ac4 = (tid & 3) << 2;
    const int bk = tid >> 4;
    const int bn4 = (tid & 15) << 2;
    const int rowA0 = m0 + ar, rowA1 = m0 + 64 + ar;
    const float dvr0 = sdv[rowA0], dvr1 = sdv[rowA1];

    float4 av0, av1, bv;
    const int T = K >> 4;

    av0 = *(const float4*)&A[(size_t)rowA0 * K + ac4];
    av1 = *(const float4*)&A[(size_t)rowA1 * K + ac4];
    bv  = *(const float4*)&B[(size_t)bk * Nn + n0 + bn4];
    fix_scale4(av0, rowA0, ac4, dvr0, sdv);
    fix_scale4(av1, rowA1, ac4, dvr1, sdv);

    As[0][ac4 + 0][ar] = __uint_as_float(f2tf(av0.x));
    As[0][ac4 + 1][ar] = __uint_as_float(f2tf(av0.y));
    As[0][ac4 + 2][ar] = __uint_as_float(f2tf(av0.z));
    As[0][ac4 + 3][ar] = __uint_as_float(f2tf(av0.w));
    As[0][ac4 + 0][ar + 64] = __uint_as_float(f2tf(av1.x));
    As[0][ac4 + 1][ar + 64] = __uint_as_float(f2tf(av1.y));
    As[0][ac4 + 2][ar + 64] = __uint_as_float(f2tf(av1.z));
    As[0][ac4 + 3][ar + 64] = __uint_as_float(f2tf(av1.w));
    {
        float4 bt;
        bt.x = __uint_as_float(f2tf(bv.x));
        bt.y = __uint_as_float(f2tf(bv.y));
        bt.z = __uint_as_float(f2tf(bv.z));
        bt.w = __uint_as_float(f2tf(bv.w));
        *(float4*)&Bs[0][bk][bn4] = bt;
    }
    __syncthreads();

    for (int t = 0; t < T; t++) {
        int cur = t & 1;
        if (t + 1 < T) {
            int kb = (t + 1) << 4;
            av0 = *(const float4*)&A[(size_t)rowA0 * K + kb + ac4];
            av1 = *(const float4*)&A[(size_t)rowA1 * K + kb + ac4];
            bv  = *(const float4*)&B[(size_t)(kb + bk) * Nn + n0 + bn4];
            fix_scale4(av0, rowA0, kb + ac4, dvr0, sdv);
            fix_scale4(av1, rowA1, kb + ac4, dvr1, sdv);
        }
#pragma unroll
        for (int ks = 0; ks < 2; ks++) {
            const int k0 = ks * 8;
            uint32_t a[2][4], b[4][2];
            const int kl = k0 + (lane & 3);
            const int rl = lane >> 2;
#pragma unroll
            for (int mi = 0; mi < 2; mi++) {
                int m = wr * 32 + mi * 16 + rl;
                a[mi][0] = __float_as_uint(As[cur][kl][m]);
                a[mi][1] = __float_as_uint(As[cur][kl][m + 8]);
                a[mi][2] = __float_as_uint(As[cur][kl + 4][m]);
                a[mi][3] = __float_as_uint(As[cur][kl + 4][m + 8]);
            }
#pragma unroll
            for (int ni = 0; ni < 4; ni++) {
                int n = wc * 32 + ni * 8 + rl;
                b[ni][0] = __float_as_uint(Bs[cur][kl][n]);
                b[ni][1] = __float_as_uint(Bs[cur][kl + 4][n]);
            }
#pragma unroll
            for (int mi = 0; mi < 2; mi++)
#pragma unroll
                for (int ni = 0; ni < 4; ni++) {
                    asm volatile(
                        "mma.sync.aligned.m16n8k8.row.col.f32.tf32.tf32.f32 "
                        "{%0,%1,%2,%3}, {%4,%5,%6,%7}, {%8,%9}, {%0,%1,%2,%3};"
                        : "+f"(acc[mi][ni][0]), "+f"(acc[mi][ni][1]),
                          "+f"(acc[mi][ni][2]), "+f"(acc[mi][ni][3])
                        : "r"(a[mi][0]), "r"(a[mi][1]), "r"(a[mi][2]), "r"(a[mi][3]),
                          "r"(b[ni][0]), "r"(b[ni][1]));
                }
        }
        if (t + 1 < T) {
            int nxt = (t + 1) & 1;
            As[nxt][ac4 + 0][ar] = __uint_as_float(f2tf(av0.x));
            As[nxt][ac4 + 1][ar] = __uint_as_float(f2tf(av0.y));
            As[nxt][ac4 + 2][ar] = __uint_as_float(f2tf(av0.z));
            As[nxt][ac4 + 3][ar] = __uint_as_float(f2tf(av0.w));
            As[nxt][ac4 + 0][ar + 64] = __uint_as_float(f2tf(av1.x));
            As[nxt][ac4 + 1][ar + 64] = __uint_as_float(f2tf(av1.y));
            As[nxt][ac4 + 2][ar + 64] = __uint_as_float(f2tf(av1.z));
            As[nxt][ac4 + 3][ar + 64] = __uint_as_float(f2tf(av1.w));
            float4 bt;
            bt.x = __uint_as_float(f2tf(bv.x));
            bt.y = __uint_as_float(f2tf(bv.y));
            bt.z = __uint_as_float(f2tf(bv.z));
            bt.w = __uint_as_float(f2tf(bv.w));
            *(float4*)&Bs[nxt][bk][bn4] = bt;
            __syncthreads();
        }
    }

    const int rl = lane >> 2;
#pragma unroll
    for (int mi = 0; mi < 2; mi++) {
        int row = m0 + wr * 32 + mi * 16 + rl;
#pragma unroll
        for (int ni = 0; ni < 4; ni++) {
            int col = n0 + wc * 32 + ni * 8 + ((lane & 3) << 1);
            if (row == col) diag[row] = acc[mi][ni][0];
            if (row == col + 1) diag[row] = acc[mi][ni][1];
            if (row + 8 == col) diag[row + 8] = acc[mi][ni][2];
            if (row + 8 == col + 1) diag[row + 8] = acc[mi][ni][3];
            *(float2*)&C[(size_t)row * Nn + col] = make_float2(acc[mi][ni][0], acc[mi][ni][1]);
            *(float2*)&C[(size_t)(row + 8) * Nn + col] = make_float2(acc[mi][ni][2], acc[mi][ni][3]);
        }
    }
    float rs[4] = {0.0f, 0.0f, 0.0f, 0.0f};
#pragma unroll
    for (int mi = 0; mi < 2; mi++)
#pragma unroll
        for (int ni = 0; ni < 4; ni++) {
            rs[mi * 2 + 0] += acc[mi][ni][0] + acc[mi][ni][1];
            rs[mi * 2 + 1] += acc[mi][ni][2] + acc[mi][ni][3];
        }
#pragma unroll
    for (int q = 0; q < 4; q++) {
        rs[q] += __shfl_xor_sync(0xFFFFFFFF, rs[q], 1);
        rs[q] += __shfl_xor_sync(0xFFFFFFFF, rs[q], 2);
    }
    if ((lane & 3) == 0) {
        int rbase = m0 + wr * 32 + rl;
        atomicAdd(&deg[rbase], rs[0]);
        atomicAdd(&deg[rbase + 8], rs[1]);
        atomicAdd(&deg[rbase + 16], rs[2]);
        atomicAdd(&deg[rbase + 24], rs[3]);
    }
}

// plain fp32 64x64 tile GEMM; optional bias+relu applied to A-operand on load.
__global__ void sgemm64(const float* __restrict__ A, const float* __restrict__ B,
                        float* __restrict__ C, int M, int Nn, int K,
                        const float* __restrict__ abias) {
    __shared__ float As[16][64];
    __shared__ float Bs[16][64];
    int tx = threadIdx.x, ty = threadIdx.y;
    int tid = ty * 16 + tx;
    int m0 = blockIdx.y * 64, n0 = blockIdx.x * 64;
    float acc[4][4];
#pragma unroll
    for (int i = 0; i < 4; i++)
#pragma unroll
        for (int j = 0; j < 4; j++) acc[i][j] = 0.0f;
    int la_r = tid / 16, la_k = tid % 16;
    int lb_k = tid / 64, lb_n = tid % 64;
    for (int k0 = 0; k0 < K; k0 += 16) {
#pragma unroll
        for (int r = 0; r < 4; r++) {
            float v = A[(size_t)(m0 + la_r + 16 * r) * K + k0 + la_k];
            if (abias != nullptr) v = fmaxf(v + abias[k0 + la_k], 0.0f);
            As[la_k][la_r + 16 * r] = v;
        }
#pragma unroll
        for (int r = 0; r < 4; r++) {
            int kk = lb_k + 4 * r;
            Bs[kk][lb_n] = (n0 + lb_n < Nn) ? B[(size_t)(k0 + kk) * Nn + n0 + lb_n] : 0.0f;
        }
        __syncthreads();
#pragma unroll
        for (int k = 0; k < 16; k++) {
            float a[4], b[4];
#pragma unroll
            for (int i = 0; i < 4; i++) a[i] = As[k][ty * 4 + i];
#pragma unroll
            for (int j = 0; j < 4; j++) b[j] = Bs[k][tx * 4 + j];
#pragma unroll
            for (int i = 0; i < 4; i++)
#pragma unroll
                for (int j = 0; j < 4; j++) acc[i][j] += a[i] * b[j];
        }
        __syncthreads();
    }
#pragma unroll
    for (int i = 0; i < 4; i++) {
        int row = m0 + ty * 4 + i;
#pragma unroll
        for (int j = 0; j < 4; j++) {
            int col = n0 + tx * 4 + j;
            if (col < Nn) C[(size_t)row * Nn + col] = acc[i][j];
        }
    }
}

// split-K fp32 GEMM with fused gcn-norm on A: C += (Dv fix(A) Dv) @ B.
__global__ void sgemmKS(const float* __restrict__ A, const float* __restrict__ dv,
                        const float* __restrict__ B, float* __restrict__ C,
                        int Nn, int K, int KS, const float* __restrict__ bias) {
    __shared__ float As[16][64];
    __shared__ float Bs[16][64];
    int tx = threadIdx.x, ty = threadIdx.y;
    int tid = ty * 16 + tx;
    int m0 = blockIdx.y * 64;
    int kLen = K / KS;
    int kStart = blockIdx.x * kLen;
    float acc[4][4];
#pragma unroll
    for (int i = 0; i < 4; i++)
#pragma unroll
        for (int j = 0; j < 4; j++) acc[i][j] = 0.0f;
    int la_r = tid / 16, la_k = tid % 16;
    int lb_k = tid / 64, lb_n = tid % 64;
    for (int k0 = kStart; k0 < kStart + kLen; k0 += 16) {
#pragma unroll
        for (int r = 0; r < 4; r++) {
            int row = m0 + la_r + 16 * r;
            int kc = k0 + la_k;
            float v = A[(size_t)row * K + kc];
            if (row == kc && v == 0.0f) v = 1.0f;
            As[la_k][la_r + 16 * r] = v * dv[row] * dv[kc];
        }
#pragma unroll
        for (int r = 0; r < 4; r++) {
            int kk = lb_k + 4 * r;
            Bs[kk][lb_n] = (lb_n < Nn) ? B[(size_t)(k0 + kk) * Nn + lb_n] : 0.0f;
        }
        __syncthreads();
#pragma unroll
        for (int k = 0; k < 16; k++) {
            float a[4], b[4];
#pragma unroll
            for (int i = 0; i < 4; i++) a[i] = As[k][ty * 4 + i];
#pragma unroll
            for (int j = 0; j < 4; j++) b[j] = Bs[k][tx * 4 + j];
#pragma unroll
            for (int i = 0; i < 4; i++)
#pragma unroll
                for (int j = 0; j < 4; j++) acc[i][j] += a[i] * b[j];
        }
        __syncthreads();
    }
#pragma unroll
    for (int i = 0; i < 4; i++) {
        int row = m0 + ty * 4 + i;
#pragma unroll
        for (int j = 0; j < 4; j++) {
            int col = tx * 4 + j;
            if (col < Nn) {
                float v = acc[i][j];
                if (bias != nullptr && kStart == 0) v += bias[col];
                atomicAdd(&C[(size_t)row * Nn + col], v);
            }
        }
    }
}

// ---------------- host orchestration ----------------

extern "C" void kernel_launch(void* const* d_in, const int* in_sizes, int n_in,
                              void* d_out, int out_size) {
    const float* x = (const float*)d_in[0];
    const int* edges[5];
    for (int i = 0; i < 5; i++) edges[i] = (const int*)d_in[1 + i];
    const float* pbp[2][8];
    for (int b = 0; b < 2; b++)
        for (int i = 0; i < 8; i++) pbp[b][i] = (const float*)d_in[6 + b * 8 + i];
    const float* w1    = (const float*)d_in[22];
    const float* bias1 = (const float*)d_in[23];
    const float* w2    = (const float*)d_in[24];
    const float* bias2 = (const float*)d_in[25];
    float* out = (float*)d_out;

    float *A_, *p1_, *p2_, *att_, *M_, *Mt_, *An_, *dinv_, *deg_, *diag_, *XW_, *H_, *HW_;
    cudaGetSymbolAddress((void**)&A_,    g_A);
    cudaGetSymbolAddress((void**)&p1_,   g_p1);
    cudaGetSymbolAddress((void**)&p2_,   g_p2);
    cudaGetSymbolAddress((void**)&att_,  g_att);
    cudaGetSymbolAddress((void**)&M_,    g_M);
    cudaGetSymbolAddress((void**)&Mt_,   g_Mt);
    cudaGetSymbolAddress((void**)&An_,   g_An);
    cudaGetSymbolAddress((void**)&dinv_, g_dinv);
    cudaGetSymbolAddress((void**)&deg_,  g_deg);
    cudaGetSymbolAddress((void**)&diag_, g_diag);
    cudaGetSymbolAddress((void**)&XW_,   g_XW);
    cudaGetSymbolAddress((void**)&H_,    g_H);
    cudaGetSymbolAddress((void**)&HW_,   g_HW);

    const size_t PLANE = (size_t)NV * NV;
    dim3 blk16(16, 16);

    float* Ab[2]   = { A_,   A_   + 3 * PLANE };
    float* p1b[2]  = { p1_,  p1_  + (size_t)16 * 512 * 512 };
    float* p2b[2]  = { p2_,  p2_  + (size_t)4 * 257 * 257 };
    float* attb[2] = { att_, att_ + 3 * PLANE };
    float* Mb[2]   = { M_,   M_   + PLANE };
    float* Mtb[2]  = { Mt_,  Mt_  + PLANE };

    // -------- setup --------
    cudaMemsetAsync(A_, 0, 6 * PLANE * sizeof(float), 0);
    cudaMemsetAsync(H_, 0, (size_t)NV * HIDD * sizeof(float), 0);
    cudaMemsetAsync(out, 0, (size_t)NV * REPD * sizeof(float), 0);
    sgemm64<<<dim3(1, NV / 64), blk16>>>(x, w1, XW_, NV, HIDD, EMBD, nullptr);

    // -------- scatter all 5 edge lists (also zeros deg) --------
    Sc5 sc;
    sc.e[0] = edges[0]; sc.A[0] = Ab[0];
    sc.e[1] = edges[1]; sc.A[1] = Ab[0] + PLANE;
    sc.e[2] = edges[2]; sc.A[2] = Ab[1];
    sc.e[3] = edges[3]; sc.A[3] = Ab[1] + PLANE;
    sc.e[4] = edges[4]; sc.A[4] = Ab[1] + 2 * PLANE;
    sc.degz = deg_;
    scatter_all<<<dim3((NE + 255) / 256, 5), 256>>>(sc);

    // -------- conv encoder (both paths batched) --------
    PathPtrs c1 = {{Ab[0], Ab[1]}, {pbp[0][0], pbp[1][0]}, {pbp[0][1], pbp[1][1]}, {p1b[0], p1b[1]}};
    conv1mma_both<<<dim3(32, 32, 2), blk16>>>(c1);

    PathPtrs c2 = {{p1b[0], p1b[1]}, {pbp[0][2], pbp[1][2]}, {pbp[0][3], pbp[1][3]}, {p2b[0], p2b[1]}};
    conv2pool_both<<<dim3(17, 17, 2), blk16>>>(c2);

    // fused tconv1 + tconv2 + sigmoid + adjacency multiply + att0 deg/diag (4-wide)
    FAtt fa;
    for (int p = 0; p < 2; p++) {
        fa.p2[p] = p2b[p];
        fa.w1[p] = pbp[p][4]; fa.b1[p] = pbp[p][5];
        fa.w2[p] = pbp[p][6]; fa.b2[p] = pbp[p][7];
        fa.A[p] = Ab[p]; fa.att[p] = attb[p];
        fa.deg[p] = deg_ + p * NV; fa.diag[p] = diag_ + p * NV;
    }
    ftconv_att_both<<<2 * NV, 256>>>(fa);

    // -------- M-chain, norms + dv computed inside GEMMs --------
    {
        GemS gs;
        gs.A[0] = attb[0];          gs.A[1] = attb[1];
        gs.B[0] = attb[0] + PLANE;  gs.B[1] = attb[1] + PLANE;
        gs.C[0] = Mtb[0];           gs.C[1] = Mtb[1];
        gs.degIn[0] = deg_;         gs.degIn[1] = deg_ + NV;
        gs.diagIn[0] = diag_;       gs.diagIn[1] = diag_ + NV;
        gs.deg[0] = deg_ + 2 * NV;  gs.deg[1] = deg_ + 3 * NV;
        gs.diag[0] = diag_ + 2 * NV; gs.diag[1] = diag_ + 3 * NV;
        tf32gemm_s<<<dim3(NV / 64, NV / 128, 2), 256>>>(gs);
    }
    {
        GemS gs;
        gs.A[0] = Mtb[1];
        gs.B[0] = attb[1] + 2 * PLANE;
        gs.C[0] = Mb[1];
        gs.degIn[0] = deg_ + 3 * NV;
        gs.diagIn[0] = diag_ + 3 * NV;
        gs.deg[0] = deg_ + 4 * NV;
        gs.diag[0] = diag_ + 4 * NV;
        gs.A[1] = gs.A[0]; gs.B[1] = gs.B[0]; gs.C[1] = gs.C[0];
        gs.degIn[1] = gs.degIn[0]; gs.diagIn[1] = gs.diagIn[0];
        gs.deg[1] = gs.deg[0]; gs.diag[1] = gs.diag[0];
        tf32gemm_s<<<dim3(NV / 64, NV / 128, 1), 256>>>(gs);
    }
    dinv_fix<<<(3 * NV + 255) / 256, 256>>>(deg_ + 2 * NV, diag_ + 2 * NV, dinv_ + 2 * NV, 3 * NV);

    // -------- scaled merge + final dinv --------
    emax_dinv<<<NV, 256>>>(Mtb[0], dinv_ + 2 * NV, Mb[1], dinv_ + 4 * NV, An_, dinv_ + 5 * NV);

    // -------- GCN layers, final norm fused into A-loads --------
    sgemmKS<<<dim3(8, NV / 64), blk16>>>(An_, dinv_ + 5 * NV, XW_, H_, HIDD, NV, 8, nullptr);
    sgemm64<<<dim3(1, NV / 64), blk16>>>(H_, w2, HW_, NV, REPD, HIDD, bias1);  // relu(H+bias1) @ w2
    sgemmKS<<<dim3(8, NV / 64), blk16>>>(An_, dinv_ + 5 * NV, HW_, out, REPD, NV, 8, bias2);
}

// round 11
// speedup vs baseline: 1.0381x; 1.0381x over previous
#include <cuda_runtime.h>
#include <math.h>
#include <stdint.h>

// Problem constants
#define NV 1024
#define NE 32768
#define EMBD 128
#define HIDD 64
#define REPD 32

// ---------------- scratch (static device globals) ----------------
__device__ float g_A[2][3][NV][NV];
__device__ float g_p1[2][16][512][512];
__device__ float g_p2[2][4][257][257];
__device__ float g_att[2][3][NV][NV];
__device__ float g_M[2][NV][NV];
__device__ float g_Mt[2][NV][NV];
__device__ float g_An[NV][NV];
__device__ float g_dinv[6][NV];
__device__ float g_deg[5][NV];
__device__ float g_diag[5][NV];
__device__ float g_XW[NV][HIDD];
__device__ float g_H[NV][HIDD];
__device__ float g_HW[NV][REPD];

// ---------------- param structs ----------------
struct Sc5 { const int* e[5]; float* A[5]; float* degz; };
struct PathPtrs {
    const float* in[2]; const float* w[2]; const float* b[2]; float* out[2];
};
struct FAtt {
    const float* p2[2]; const float* w1[2]; const float* b1[2];
    const float* w2[2]; const float* b2[2]; const float* A[2]; float* att[2];
    float* deg[2]; float* diag[2];
};
struct GemS {
    const float* A[2]; const float* B[2]; float* C[2];
    const float* degIn[2]; const float* diagIn[2];
    float* deg[2]; float* diag[2];
};

// ---------------- helpers ----------------
__device__ __forceinline__ uint32_t f2tf(float f) {
    uint32_t r;
    asm("cvt.rna.tf32.f32 %0, %1;" : "=r"(r) : "f"(f));
    return r;
}

__device__ __forceinline__ void mma_tf32(float* c, const uint32_t* a, uint32_t b0, uint32_t b1) {
    asm volatile(
        "mma.sync.aligned.m16n8k8.row.col.f32.tf32.tf32.f32 "
        "{%0,%1,%2,%3}, {%4,%5,%6,%7}, {%8,%9}, {%0,%1,%2,%3};"
        : "+f"(c[0]), "+f"(c[1]), "+f"(c[2]), "+f"(c[3])
        : "r"(a[0]), "r"(a[1]), "r"(a[2]), "r"(a[3]), "r"(b0), "r"(b1));
}

// ---------------- kernels ----------------

__global__ void scatter_all(Sc5 s) {
    int j = blockIdx.y;
    int k = blockIdx.x * blockDim.x + threadIdx.x;
    if (j == 0 && k < 5 * NV) s.degz[k] = 0.0f;
    if (k < NE) {
        const int* e = s.e[j];
        atomicAdd(&s.A[j][e[k] * NV + e[NE + k]], 1.0f);
    }
}

// ---- conv1 (3x3, pad1, L->16) + relu + maxpool2 via tf32 MMA (fp32-exact hi/lo) ----
template <int L>
__device__ __forceinline__ void conv1mma_impl(const float* __restrict__ A,
                                              const float* __restrict__ w,
                                              const float* __restrict__ b,
                                              float* __restrict__ p1,
                                              float* __restrict__ tile,
                                              float* __restrict__ whi,
                                              float* __restrict__ wlo,
                                              float* __restrict__ sb) {
    constexpr int KS = (L * 9 + 7) / 8;
    int t = threadIdx.y * 16 + threadIdx.x;
    int lane = t & 31, wid = t >> 5;

    for (int i = t; i < 512; i += 256) {
        int oc = i >> 5, k = i & 31;
        float wv = (k < L * 9) ? w[oc * L * 9 + k] : 0.0f;
        float hi = __uint_as_float(f2tf(wv));
        whi[i] = hi;
        wlo[i] = __uint_as_float(f2tf(wv - hi));
    }
    if (t < 16) sb[t] = b[t];

    int gy0 = blockIdx.y * 32 - 1, gx0 = blockIdx.x * 32 - 1;
    for (int l = 0; l < L; l++)
        for (int i = t; i < 34 * 34; i += 256) {
            int r = i / 34, c = i % 34;
            int gy = gy0 + r, gx = gx0 + c;
            tile[(l * 34 + r) * 36 + c] = (gy >= 0 && gy < NV && gx >= 0 && gx < NV)
                                              ? A[((size_t)l * NV + gy) * NV + gx] : 0.0f;
        }
    __syncthreads();

    uint32_t ahi[KS][4], alo[KS][4];
    int r0 = (lane >> 2) * 32, r1 = ((lane >> 2) + 8) * 32;
#pragma unroll
    for (int s = 0; s < KS; s++) {
        int c0 = 8 * s + (lane & 3);
        ahi[s][0] = __float_as_uint(whi[r0 + c0]);
        ahi[s][1] = __float_as_uint(whi[r1 + c0]);
        ahi[s][2] = __float_as_uint(whi[r0 + c0 + 4]);
        ahi[s][3] = __float_as_uint(whi[r1 + c0 + 4]);
        alo[s][0] = __float_as_uint(wlo[r0 + c0]);
        alo[s][1] = __float_as_uint(wlo[r1 + c0]);
        alo[s][2] = __float_as_uint(wlo[r0 + c0 + 4]);
        alo[s][3] = __float_as_uint(wlo[r1 + c0 + 4]);
    }

    int boff[KS][2];
#pragma unroll
    for (int s = 0; s < KS; s++)
#pragma unroll
        for (int h = 0; h < 2; h++) {
            int k = 8 * s + (lane & 3) + 4 * h;
            if (k >= L * 9) k = 0;
            int l = k / 9, r = k % 9;
            boff[s][h] = (l * 34 + r / 3) * 36 + (r % 3) + (lane >> 2);
        }

    for (int u = wid; u < 64; u += 8) {
        int py = u >> 2, ux = u & 3;
        int base0 = (2 * py) * 36 + 8 * ux;
        int base1 = base0 + 36;
        float acc0[4] = {0.f, 0.f, 0.f, 0.f};
        float acc1[4] = {0.f, 0.f, 0.f, 0.f};
#pragma unroll
        for (int s = 0; s < KS; s++) {
            uint32_t b00 = __float_as_uint(tile[boff[s][0] + base0]);
            uint32_t b01 = __float_as_uint(tile[boff[s][1] + base0]);
            mma_tf32(acc0, ahi[s], b00, b01);
            mma_tf32(acc0, alo[s], b00, b01);
            uint32_t b10 = __float_as_uint(tile[boff[s][0] + base1]);
            uint32_t b11 = __float_as_uint(tile[boff[s][1] + base1]);
            mma_tf32(acc1, ahi[s], b10, b11);
            mma_tf32(acc1, alo[s], b10, b11);
        }
        int oc0 = lane >> 2, oc1 = oc0 + 8;
        int ox = blockIdx.x * 16 + 4 * ux + (lane & 3);
        int oy = blockIdx.y * 16 + py;
        float m0 = fmaxf(fmaxf(acc0[0], acc0[1]), fmaxf(acc1[0], acc1[1]));
        float m1 = fmaxf(fmaxf(acc0[2], acc0[3]), fmaxf(acc1[2], acc1[3]));
        p1[((size_t)oc0 * 512 + oy) * 512 + ox] = fmaxf(m0 + sb[oc0], 0.0f);
        p1[((size_t)oc1 * 512 + oy) * 512 + ox] = fmaxf(m1 + sb[oc1], 0.0f);
    }
}

__global__ void __launch_bounds__(256) conv1mma_both(PathPtrs p) {
    __shared__ float tile[3 * 34 * 36];
    __shared__ float whi[512], wlo[512];
    __shared__ float sb[16];
    int path = blockIdx.z;
    if (path == 0)
        conv1mma_impl<2>(p.in[0], p.w[0], p.b[0], p.out[0], tile, whi, wlo, sb);
    else
        conv1mma_impl<3>(p.in[1], p.w[1], p.b[1], p.out[1], tile, whi, wlo, sb);
}

// ---- conv2 (3x3, pad2, 16->4) + relu + maxpool2 ----
// Round-6 structure + DOUBLE-BUFFERED smem tile: 16 syncs instead of 32;
// LDG of ci+1 issued before compute(ci), STS of ci+1 after compute(ci).
__global__ void conv2pool_both(PathPtrs pp) {
    __shared__ float tile[2][1368];    // 2 x (36 rows x 38 stride)
    __shared__ float sw[576];
    __shared__ float sb[4];
    int path = blockIdx.z;
    const float* p1 = pp.in[path];
    float* p2 = pp.out[path];
    int tx = threadIdx.x, ty = threadIdx.y;
    int t = ty * 16 + tx;
    for (int i = t; i < 576; i += 256) sw[i] = pp.w[path][i];
    if (t < 4) sb[t] = pp.b[path][t];

    int gy0 = blockIdx.y * 32 - 2, gx0 = blockIdx.x * 32 - 2;

    int srow[6], scol[6], sok[6];
    float r[6];
#pragma unroll
    for (int s = 0; s < 6; s++) {
        int i = t + s * 256;
        srow[s] = i / 36; scol[s] = i % 36;
        sok[s] = (i < 1296);
    }
    // prefetch ci = 0
#pragma unroll
    for (int s = 0; s < 6; s++) {
        if (sok[s]) {
            int gy = gy0 + srow[s], gx = gx0 + scol[s];
            r[s] = (gy >= 0 && gy < 512 && gx >= 0 && gx < 512)
                       ? p1[(size_t)gy * 512 + gx] : 0.0f;
        }
    }
    // store ci=0 into buffer 0
#pragma unroll
    for (int s = 0; s < 6; s++)
        if (sok[s]) tile[0][srow[s] * 38 + scol[s]] = r[s];

    float acc[4][2][2];
#pragma unroll
    for (int oc = 0; oc < 4; oc++)
#pragma unroll
        for (int py = 0; py < 2; py++)
#pragma unroll
            for (int px = 0; px < 2; px++) acc[oc][py][px] = 0.0f;

    __syncthreads();   // weights + buffer 0 ready

    for (int ci = 0; ci < 16; ci++) {
        // issue next channel's global loads first (latency hidden by compute)
        if (ci < 15) {
#pragma unroll
            for (int s = 0; s < 6; s++) {
                if (sok[s]) {
                    int gy = gy0 + srow[s], gx = gx0 + scol[s];
                    r[s] = (gy >= 0 && gy < 512 && gx >= 0 && gx < 512)
                               ? p1[((size_t)(ci + 1) * 512 + gy) * 512 + gx] : 0.0f;
                }
            }
        }
        const float* buf = tile[ci & 1];
        float patch[4][4];
#pragma unroll
        for (int rw = 0; rw < 4; rw++)
#pragma unroll
            for (int c = 0; c < 4; c++)
                patch[rw][c] = buf[(2 * ty + rw) * 38 + 2 * tx + c];
#pragma unroll
        for (int oc = 0; oc < 4; oc++)
#pragma unroll
            for (int ky = 0; ky < 3; ky++)
#pragma unroll
                for (int kx = 0; kx < 3; kx++) {
                    float wv = sw[((oc * 16 + ci) * 3 + ky) * 3 + kx];
                    acc[oc][0][0] += wv * patch[ky][kx];
                    acc[oc][0][1] += wv * patch[ky][kx + 1];
                    acc[oc][1][0] += wv * patch[ky + 1][kx];
                    acc[oc][1][1] += wv * patch[ky + 1][kx + 1];
                }
        if (ci < 15) {
            float* nbuf = tile[(ci + 1) & 1];
#pragma unroll
            for (int s = 0; s < 6; s++)
                if (sok[s]) nbuf[srow[s] * 38 + scol[s]] = r[s];
            __syncthreads();   // single sync per iteration
        }
    }
    int x = blockIdx.x * 16 + tx, y = blockIdx.y * 16 + ty;
    if (x < 257 && y < 257) {
#pragma unroll
        for (int oc = 0; oc < 4; oc++) {
            float m = fmaxf(fmaxf(acc[oc][0][0], acc[oc][0][1]),
                            fmaxf(acc[oc][1][0], acc[oc][1][1])) + sb[oc];
            p2[((size_t)oc * 257 + y) * 257 + x] = fmaxf(m, 0.0f);
        }
    }
}

// ---- fused tconv1 + tconv2 + sigmoid + crop + adjacency multiply + att0 deg/diag ----
template <int L>
__device__ __forceinline__ void ftconv4_impl(const float* __restrict__ p2,
                                             const float* __restrict__ sw1,
                                             const float* __restrict__ sb1,
                                             const float* __restrict__ sw2,
                                             const float* __restrict__ sb2,
                                             const float* __restrict__ A,
                                             float* __restrict__ att,
                                             float* __restrict__ deg,
                                             float* __restrict__ diag,
                                             int q, int y) {
    int ky2 = (y + 1) & 1;
    int iy1 = (y - 1 + ky2) >> 1;
    int ky1 = (iy1 + 1) & 1;
    int iy0 = (iy1 - 1 + ky1) >> 1;

    float p[4];
#pragma unroll
    for (int cj = 0; cj < 4; cj++) p[cj] = p2[((size_t)cj * 257 + iy0) * 257 + q];

    float tA[16], tB[16];
#pragma unroll
    for (int ci = 0; ci < 16; ci++) {
        float sA = sb1[ci], sB = sb1[ci];
#pragma unroll
        for (int cj = 0; cj < 4; cj++) {
            int base = ((ci * 4 + cj) * 2 + ky1) * 2;
            sA += sw1[base + 1] * p[cj];
            sB += sw1[base + 0] * p[cj];
        }
        tA[ci] = fmaxf(sA, 0.0f);
        tB[ci] = fmaxf(sB, 0.0f);
    }

    float d0 = 0.f, d1 = 0.f, d2 = 0.f, d3 = 0.f;
#pragma unroll
    for (int l = 0; l < L; l++) {
        float s0A = sb2[l], s1A = sb2[l], s0B = sb2[l], s1B = sb2[l];
#pragma unroll
        for (int ci = 0; ci < 16; ci++) {
            int base = ((l * 16 + ci) * 2 + ky2) * 2;
            float w1v = sw2[base + 1], w0v = sw2[base + 0];
            s0A += w1v * tA[ci]; s1A += w0v * tA[ci];
            s0B += w1v * tB[ci]; s1B += w0v * tB[ci];
        }
        float g0 = 1.0f / (1.0f + expf(-s0A));
        float g1 = 1.0f / (1.0f + expf(-s1A));
        float g2 = 1.0f / (1.0f + expf(-s0B));
        float g3 = 1.0f / (1.0f + expf(-s1B));
        size_t off = (size_t)l * NV * NV + (size_t)y * NV + 4 * q;
        float4 a = *(const float4*)&A[off];
        float4 v = make_float4(a.x * g0, a.y * g1, a.z * g2, a.w * g3);
        *(float4*)&att[off] = v;
        if (l == 0) { d0 = v.x; d1 = v.y; d2 = v.z; d3 = v.w; }
    }

    float s = (d0 + d1) + (d2 + d3);
#pragma unroll
    for (int o = 16; o > 0; o >>= 1) s += __shfl_xor_sync(0xFFFFFFFF, s, o);
    if ((threadIdx.x & 31) == 0) atomicAdd(&deg[y], s);
    if ((y >> 2) == q) {
        int sel = y & 3;
        diag[y] = sel == 0 ? d0 : sel == 1 ? d1 : sel == 2 ? d2 : d3;
    }
}

__global__ void ftconv_att_both(FAtt fa) {
    __shared__ float sw1[256], sb1[16], sw2[192], sb2[3];
    int gidx = blockIdx.x * blockDim.x + threadIdx.x;
    const int PL = NV * 256;
    int path = gidx / PL;
    int idx = gidx - path * PL;
    int q = idx & 255, y = idx >> 8;
    const int L = (path == 0) ? 2 : 3;
    int t = threadIdx.x;
    if (t < 256) sw1[t] = fa.w1[path][t];
    if (t < 16) sb1[t] = fa.b1[path][t];
    for (int i = t; i < L * 64; i += 256) sw2[i] = fa.w2[path][i];
    if (t < L) sb2[t] = fa.b2[path][t];
    __syncthreads();
    if (path == 0)
        ftconv4_impl<2>(fa.p2[0], sw1, sb1, sw2, sb2, fa.A[0], fa.att[0],
                        fa.deg[0], fa.diag[0], q, y);
    else
        ftconv4_impl<3>(fa.p2[1], sw1, sb1, sw2, sb2, fa.A[1], fa.att[1],
                        fa.deg[1], fa.diag[1], q, y);
}

// ---- dinv from accumulated deg/diag ----
__global__ void dinv_fix(const float* __restrict__ deg, const float* __restrict__ diag,
                         float* __restrict__ dv, int n) {
    int i = blockIdx.x * blockDim.x + threadIdx.x;
    if (i < n) {
        float d = deg[i];
        if (diag[i] == 0.0f) d += 1.0f;
        dv[i] = d > 0.0f ? rsqrtf(d) : 0.0f;
    }
}

// ---- scaled max-merge + row-sum/dinv ----
__global__ void emax_dinv(const float* __restrict__ a, const float* __restrict__ dva,
                          const float* __restrict__ b, const float* __restrict__ dvb,
                          float* __restrict__ o, float* __restrict__ dv) {
    int row = blockIdx.x;
    float dar = dva[row], dbr = dvb[row];
    __shared__ float sh[256];
    __shared__ float sdiag;
    float s = 0.0f;
    for (int j = threadIdx.x; j < NV; j += 256) {
        float va = a[(size_t)row * NV + j];
        if (j == row && va == 0.0f) va = 1.0f;
        va *= dar * dva[j];
        float vb = b[(size_t)row * NV + j];
        if (j == row && vb == 0.0f) vb = 1.0f;
        vb *= dbr * dvb[j];
        float v = fmaxf(va, vb);
        o[(size_t)row * NV + j] = v;
        if (j == row) sdiag = v;
        s += v;
    }
    sh[threadIdx.x] = s;
    __syncthreads();
    for (int off = 128; off > 0; off >>= 1) {
        if (threadIdx.x < off) sh[threadIdx.x] += sh[threadIdx.x + off];
        __syncthreads();
    }
    if (threadIdx.x == 0) {
        float d = sh[0];
        if (sdiag == 0.0f) d += 1.0f;
        dv[row] = d > 0.0f ? rsqrtf(d) : 0.0f;
    }
}

// ---------------- tf32 GEMM: dv computed in prologue from deg/diag; norm fused ----
__device__ __forceinline__ void fix_scale4(float4& v, int row, int kc, float dvr,
                                           const float* __restrict__ dv) {
    float4 dk = *(const float4*)&dv[kc];
    float* p = &v.x;
#pragma unroll
    for (int q = 0; q < 4; q++)
        if (row == kc + q && p[q] == 0.0f) p[q] = 1.0f;
    v.x *= dvr * dk.x; v.y *= dvr * dk.y; v.z *= dvr * dk.z; v.w *= dvr * dk.w;
}

__global__ void __launch_bounds__(256) tf32gemm_s(GemS g) {
    const float* __restrict__ A = g.A[blockIdx.z];
    const float* __restrict__ B = g.B[blockIdx.z];
    float* __restrict__ C = g.C[blockIdx.z];
    const float* __restrict__ degIn = g.degIn[blockIdx.z];
    const float* __restrict__ diagIn = g.diagIn[blockIdx.z];
    float* __restrict__ deg = g.deg[blockIdx.z];
    float* __restrict__ diag = g.diag[blockIdx.z];
    const int Nn = NV, K = NV;

    __shared__ float As[2][16][136];
    __shared__ float Bs[2][16][72];
    __shared__ __align__(16) float sdv[NV];

    const int tid = threadIdx.x;
    const int lane = tid & 31;
    const int wid = tid >> 5;
    const int wr = wid & 3;
    const int wc = wid >> 2;
    const int m0 = blockIdx.y * 128;
    const int n0 = blockIdx.x * 64;

    for (int i = tid; i < NV; i += 256) {
        float d = degIn[i];
        if (diagIn[i] == 0.0f) d += 1.0f;
        sdv[i] = d > 0.0f ? rsqrtf(d) : 0.0f;
    }
    __syncthreads();

    float acc[2][4][4];
#pragma unroll
    for (int mi = 0; mi < 2; mi++)
#pragma unroll
        for (int ni = 0; ni < 4; ni++)
#pragma unroll
            for (int r = 0; r < 4; r++) acc[mi][ni][r] = 0.0f;

    const int ar = tid >> 2;
    const int ac4 = (tid & 3) << 2;
    const int bk = tid >> 4;
    const int bn4 = (tid & 15) << 2;
    const int rowA0 = m0 + ar, rowA1 = m0 + 64 + ar;
    const float dvr0 = sdv[rowA0], dvr1 = sdv[rowA1];

    float4 av0, av1, bv;
    const int T = K >> 4;

    av0 = *(const float4*)&A[(size_t)rowA0 * K + ac4];
    av1 = *(const float4*)&A[(size_t)rowA1 * K + ac4];
    bv  = *(const float4*)&B[(size_t)bk * Nn + n0 + bn4];
    fix_scale4(av0, rowA0, ac4, dvr0, sdv);
    fix_scale4(av1, rowA1, ac4, dvr1, sdv);

    As[0][ac4 + 0][ar] = __uint_as_float(f2tf(av0.x));
    As[0][ac4 + 1][ar] = __uint_as_float(f2tf(av0.y));
    As[0][ac4 + 2][ar] = __uint_as_float(f2tf(av0.z));
    As[0][ac4 + 3][ar] = __uint_as_float(f2tf(av0.w));
    As[0][ac4 + 0][ar + 64] = __uint_as_float(f2tf(av1.x));
    As[0][ac4 + 1][ar + 64] = __uint_as_float(f2tf(av1.y));
    As[0][ac4 + 2][ar + 64] = __uint_as_float(f2tf(av1.z));
    As[0][ac4 + 3][ar + 64] = __uint_as_float(f2tf(av1.w));
    {
        float4 bt;
        bt.x = __uint_as_float(f2tf(bv.x));
        bt.y = __uint_as_float(f2tf(bv.y));
        bt.z = __uint_as_float(f2tf(bv.z));
        bt.w = __uint_as_float(f2tf(bv.w));
        *(float4*)&Bs[0][bk][bn4] = bt;
    }
    __syncthreads();

    for (int t = 0; t < T; t++) {
        int cur = t & 1;
        if (t + 1 < T) {
            int kb = (t + 1) << 4;
            av0 = *(const float4*)&A[(size_t)rowA0 * K + kb + ac4];
            av1 = *(const float4*)&A[(size_t)rowA1 * K + kb + ac4];
            bv  = *(const float4*)&B[(size_t)(kb + bk) * Nn + n0 + bn4];
            fix_scale4(av0, rowA0, kb + ac4, dvr0, sdv);
            fix_scale4(av1, rowA1, kb + ac4, dvr1, sdv);
        }
#pragma unroll
        for (int ks = 0; ks < 2; ks++) {
            const int k0 = ks * 8;
            uint32_t a[2][4], b[4][2];
            const int kl = k0 + (lane & 3);
            const int rl = lane >> 2;
#pragma unroll
            for (int mi = 0; mi < 2; mi++) {
                int m = wr * 32 + mi * 16 + rl;
                a[mi][0] = __float_as_uint(As[cur][kl][m]);
                a[mi][1] = __float_as_uint(As[cur][kl][m + 8]);
                a[mi][2] = __float_as_uint(As[cur][kl + 4][m]);
                a[mi][3] = __float_as_uint(As[cur][kl + 4][m + 8]);
            }
#pragma unroll
            for (int ni = 0; ni < 4; ni++) {
                int n = wc * 32 + ni * 8 + rl;
                b[ni][0] = __float_as_uint(Bs[cur][kl][n]);
                b[ni][1] = __float_as_uint(Bs[cur][kl + 4][n]);
            }
#pragma unroll
            for (int mi = 0; mi < 2; mi++)
#pragma unroll
                for (int ni = 0; ni < 4; ni++) {
                    asm volatile(
                        "mma.sync.aligned.m16n8k8.row.col.f32.tf32.tf32.f32 "
                        "{%0,%1,%2,%3}, {%4,%5,%6,%7}, {%8,%9}, {%0,%1,%2,%3};"
                        : "+f"(acc[mi][ni][0]), "+f"(acc[mi][ni][1]),
                          "+f"(acc[mi][ni][2]), "+f"(acc[mi][ni][3])
                        : "r"(a[mi][0]), "r"(a[mi][1]), "r"(a[mi][2]), "r"(a[mi][3]),
                          "r"(b[ni][0]), "r"(b[ni][1]));
                }
        }
        if (t + 1 < T) {
            int nxt = (t + 1) & 1;
            As[nxt][ac4 + 0][ar] = __uint_as_float(f2tf(av0.x));
            As[nxt][ac4 + 1][ar] = __uint_as_float(f2tf(av0.y));
            As[nxt][ac4 + 2][ar] = __uint_as_float(f2tf(av0.z));
            As[nxt][ac4 + 3][ar] = __uint_as_float(f2tf(av0.w));
            As[nxt][ac4 + 0][ar + 64] = __uint_as_float(f2tf(av1.x));
            As[nxt][ac4 + 1][ar + 64] = __uint_as_float(f2tf(av1.y));
            As[nxt][ac4 + 2][ar + 64] = __uint_as_float(f2tf(av1.z));
            As[nxt][ac4 + 3][ar + 64] = __uint_as_float(f2tf(av1.w));
            float4 bt;
            bt.x = __uint_as_float(f2tf(bv.x));
            bt.y = __uint_as_float(f2tf(bv.y));
            bt.z = __uint_as_float(f2tf(bv.z));
            bt.w = __uint_as_float(f2tf(bv.w));
            *(float4*)&Bs[nxt][bk][bn4] = bt;
            __syncthreads();
        }
    }

    const int rl = lane >> 2;
#pragma unroll
    for (int mi = 0; mi < 2; mi++) {
        int row = m0 + wr * 32 + mi * 16 + rl;
#pragma unroll
        for (int ni = 0; ni < 4; ni++) {
            int col = n0 + wc * 32 + ni * 8 + ((lane & 3) << 1);
            if (row == col) diag[row] = acc[mi][ni][0];
            if (row == col + 1) diag[row] = acc[mi][ni][1];
            if (row + 8 == col) diag[row + 8] = acc[mi][ni][2];
            if (row + 8 == col + 1) diag[row + 8] = acc[mi][ni][3];
            *(float2*)&C[(size_t)row * Nn + col] = make_float2(acc[mi][ni][0], acc[mi][ni][1]);
            *(float2*)&C[(size_t)(row + 8) * Nn + col] = make_float2(acc[mi][ni][2], acc[mi][ni][3]);
        }
    }
    float rs[4] = {0.0f, 0.0f, 0.0f, 0.0f};
#pragma unroll
    for (int mi = 0; mi < 2; mi++)
#pragma unroll
        for (int ni = 0; ni < 4; ni++) {
            rs[mi * 2 + 0] += acc[mi][ni][0] + acc[mi][ni][1];
            rs[mi * 2 + 1] += acc[mi][ni][2] + acc[mi][ni][3];
        }
#pragma unroll
    for (int q = 0; q < 4; q++) {
        rs[q] += __shfl_xor_sync(0xFFFFFFFF, rs[q], 1);
        rs[q] += __shfl_xor_sync(0xFFFFFFFF, rs[q], 2);
    }
    if ((lane & 3) == 0) {
        int rbase = m0 + wr * 32 + rl;
        atomicAdd(&deg[rbase], rs[0]);
        atomicAdd(&deg[rbase + 8], rs[1]);
        atomicAdd(&deg[rbase + 16], rs[2]);
        atomicAdd(&deg[rbase + 24], rs[3]);
    }
}

// plain fp32 64x64 tile GEMM; optional bias+relu applied to A-operand on load.
__global__ void sgemm64(const float* __restrict__ A, const float* __restrict__ B,
                        float* __restrict__ C, int M, int Nn, int K,
                        const float* __restrict__ abias) {
    __shared__ float As[16][64];
    __shared__ float Bs[16][64];
    int tx = threadIdx.x, ty = threadIdx.y;
    int tid = ty * 16 + tx;
    int m0 = blockIdx.y * 64, n0 = blockIdx.x * 64;
    float acc[4][4];
#pragma unroll
    for (int i = 0; i < 4; i++)
#pragma unroll
        for (int j = 0; j < 4; j++) acc[i][j] = 0.0f;
    int la_r = tid / 16, la_k = tid % 16;
    int lb_k = tid / 64, lb_n = tid % 64;
    for (int k0 = 0; k0 < K; k0 += 16) {
#pragma unroll
        for (int r = 0; r < 4; r++) {
            float v = A[(size_t)(m0 + la_r + 16 * r) * K + k0 + la_k];
            if (abias != nullptr) v = fmaxf(v + abias[k0 + la_k], 0.0f);
            As[la_k][la_r + 16 * r] = v;
        }
#pragma unroll
        for (int r = 0; r < 4; r++) {
            int kk = lb_k + 4 * r;
            Bs[kk][lb_n] = (n0 + lb_n < Nn) ? B[(size_t)(k0 + kk) * Nn + n0 + lb_n] : 0.0f;
        }
        __syncthreads();
#pragma unroll
        for (int k = 0; k < 16; k++) {
            float a[4], b[4];
#pragma unroll
            for (int i = 0; i < 4; i++) a[i] = As[k][ty * 4 + i];
#pragma unroll
            for (int j = 0; j < 4; j++) b[j] = Bs[k][tx * 4 + j];
#pragma unroll
            for (int i = 0; i < 4; i++)
#pragma unroll
                for (int j = 0; j < 4; j++) acc[i][j] += a[i] * b[j];
        }
        __syncthreads();
    }
#pragma unroll
    for (int i = 0; i < 4; i++) {
        int row = m0 + ty * 4 + i;
#pragma unroll
        for (int j = 0; j < 4; j++) {
            int col = n0 + tx * 4 + j;
            if (col < Nn) C[(size_t)row * Nn + col] = acc[i][j];
        }
    }
}

// split-K fp32 GEMM with fused gcn-norm on A: C += (Dv fix(A) Dv) @ B.
__global__ void sgemmKS(const float* __restrict__ A, const float* __restrict__ dv,
                        const float* __restrict__ B, float* __restrict__ C,
                        int Nn, int K, int KS, const float* __restrict__ bias) {
    __shared__ float As[16][64];
    __shared__ float Bs[16][64];
    int tx = threadIdx.x, ty = threadIdx.y;
    int tid = ty * 16 + tx;
    int m0 = blockIdx.y * 64;
    int kLen = K / KS;
    int kStart = blockIdx.x * kLen;
    float acc[4][4];
#pragma unroll
    for (int i = 0; i < 4; i++)
#pragma unroll
        for (int j = 0; j < 4; j++) acc[i][j] = 0.0f;
    int la_r = tid / 16, la_k = tid % 16;
    int lb_k = tid / 64, lb_n = tid % 64;
    for (int k0 = kStart; k0 < kStart + kLen; k0 += 16) {
#pragma unroll
        for (int r = 0; r < 4; r++) {
            int row = m0 + la_r + 16 * r;
            int kc = k0 + la_k;
            float v = A[(size_t)row * K + kc];
            if (row == kc && v == 0.0f) v = 1.0f;
            As[la_k][la_r + 16 * r] = v * dv[row] * dv[kc];
        }
#pragma unroll
        for (int r = 0; r < 4; r++) {
            int kk = lb_k + 4 * r;
            Bs[kk][lb_n] = (lb_n < Nn) ? B[(size_t)(k0 + kk) * Nn + lb_n] : 0.0f;
        }
        __syncthreads();
#pragma unroll
        for (int k = 0; k < 16; k++) {
            float a[4], b[4];
#pragma unroll
            for (int i = 0; i < 4; i++) a[i] = As[k][ty * 4 + i];
#pragma unroll
            for (int j = 0; j < 4; j++) b[j] = Bs[k][tx * 4 + j];
#pragma unroll
            for (int i = 0; i < 4; i++)
#pragma unroll
                for (int j = 0; j < 4; j++) acc[i][j] += a[i] * b[j];
        }
        __syncthreads();
    }
#pragma unroll
    for (int i = 0; i < 4; i++) {
        int row = m0 + ty * 4 + i;
#pragma unroll
        for (int j = 0; j < 4; j++) {
            int col = tx * 4 + j;
            if (col < Nn) {
                float v = acc[i][j];
                if (bias != nullptr && kStart == 0) v += bias[col];
                atomicAdd(&C[(size_t)row * Nn + col], v);
            }
        }
    }
}

// ---------------- host orchestration ----------------

extern "C" void kernel_launch(void* const* d_in, const int* in_sizes, int n_in,
                              void* d_out, int out_size) {
    const float* x = (const float*)d_in[0];
    const int* edges[5];
    for (int i = 0; i < 5; i++) edges[i] = (const int*)d_in[1 + i];
    const float* pbp[2][8];
    for (int b = 0; b < 2; b++)
        for (int i = 0; i < 8; i++) pbp[b][i] = (const float*)d_in[6 + b * 8 + i];
    const float* w1    = (const float*)d_in[22];
    const float* bias1 = (const float*)d_in[23];
    const float* w2    = (const float*)d_in[24];
    const float* bias2 = (const float*)d_in[25];
    float* out = (float*)d_out;

    float *A_, *p1_, *p2_, *att_, *M_, *Mt_, *An_, *dinv_, *deg_, *diag_, *XW_, *H_, *HW_;
    cudaGetSymbolAddress((void**)&A_,    g_A);
    cudaGetSymbolAddress((void**)&p1_,   g_p1);
    cudaGetSymbolAddress((void**)&p2_,   g_p2);
    cudaGetSymbolAddress((void**)&att_,  g_att);
    cudaGetSymbolAddress((void**)&M_,    g_M);
    cudaGetSymbolAddress((void**)&Mt_,   g_Mt);
    cudaGetSymbolAddress((void**)&An_,   g_An);
    cudaGetSymbolAddress((void**)&dinv_, g_dinv);
    cudaGetSymbolAddress((void**)&deg_,  g_deg);
    cudaGetSymbolAddress((void**)&diag_, g_diag);
    cudaGetSymbolAddress((void**)&XW_,   g_XW);
    cudaGetSymbolAddress((void**)&H_,    g_H);
    cudaGetSymbolAddress((void**)&HW_,   g_HW);

    const size_t PLANE = (size_t)NV * NV;
    dim3 blk16(16, 16);

    float* Ab[2]   = { A_,   A_   + 3 * PLANE };
    float* p1b[2]  = { p1_,  p1_  + (size_t)16 * 512 * 512 };
    float* p2b[2]  = { p2_,  p2_  + (size_t)4 * 257 * 257 };
    float* attb[2] = { att_, att_ + 3 * PLANE };
    float* Mb[2]   = { M_,   M_   + PLANE };
    float* Mtb[2]  = { Mt_,  Mt_  + PLANE };

    // -------- setup --------
    cudaMemsetAsync(A_, 0, 6 * PLANE * sizeof(float), 0);
    cudaMemsetAsync(H_, 0, (size_t)NV * HIDD * sizeof(float), 0);
    cudaMemsetAsync(out, 0, (size_t)NV * REPD * sizeof(float), 0);
    sgemm64<<<dim3(1, NV / 64), blk16>>>(x, w1, XW_, NV, HIDD, EMBD, nullptr);

    // -------- scatter all 5 edge lists (also zeros deg) --------
    Sc5 sc;
    sc.e[0] = edges[0]; sc.A[0] = Ab[0];
    sc.e[1] = edges[1]; sc.A[1] = Ab[0] + PLANE;
    sc.e[2] = edges[2]; sc.A[2] = Ab[1];
    sc.e[3] = edges[3]; sc.A[3] = Ab[1] + PLANE;
    sc.e[4] = edges[4]; sc.A[4] = Ab[1] + 2 * PLANE;
    sc.degz = deg_;
    scatter_all<<<dim3((NE + 255) / 256, 5), 256>>>(sc);

    // -------- conv encoder (both paths batched) --------
    PathPtrs c1 = {{Ab[0], Ab[1]}, {pbp[0][0], pbp[1][0]}, {pbp[0][1], pbp[1][1]}, {p1b[0], p1b[1]}};
    conv1mma_both<<<dim3(32, 32, 2), blk16>>>(c1);

    PathPtrs c2 = {{p1b[0], p1b[1]}, {pbp[0][2], pbp[1][2]}, {pbp[0][3], pbp[1][3]}, {p2b[0], p2b[1]}};
    conv2pool_both<<<dim3(17, 17, 2), blk16>>>(c2);

    // fused tconv1 + tconv2 + sigmoid + adjacency multiply + att0 deg/diag (4-wide)
    FAtt fa;
    for (int p = 0; p < 2; p++) {
        fa.p2[p] = p2b[p];
        fa.w1[p] = pbp[p][4]; fa.b1[p] = pbp[p][5];
        fa.w2[p] = pbp[p][6]; fa.b2[p] = pbp[p][7];
        fa.A[p] = Ab[p]; fa.att[p] = attb[p];
        fa.deg[p] = deg_ + p * NV; fa.diag[p] = diag_ + p * NV;
    }
    ftconv_att_both<<<2 * NV, 256>>>(fa);

    // -------- M-chain, norms + dv computed inside GEMMs --------
    {
        GemS gs;
        gs.A[0] = attb[0];          gs.A[1] = attb[1];
        gs.B[0] = attb[0] + PLANE;  gs.B[1] = attb[1] + PLANE;
        gs.C[0] = Mtb[0];           gs.C[1] = Mtb[1];
        gs.degIn[0] = deg_;         gs.degIn[1] = deg_ + NV;
        gs.diagIn[0] = diag_;       gs.diagIn[1] = diag_ + NV;
        gs.deg[0] = deg_ + 2 * NV;  gs.deg[1] = deg_ + 3 * NV;
        gs.diag[0] = diag_ + 2 * NV; gs.diag[1] = diag_ + 3 * NV;
        tf32gemm_s<<<dim3(NV / 64, NV / 128, 2), 256>>>(gs);
    }
    {
        GemS gs;
        gs.A[0] = Mtb[1];
        gs.B[0] = attb[1] + 2 * PLANE;
        gs.C[0] = Mb[1];
        gs.degIn[0] = deg_ + 3 * NV;
        gs.diagIn[0] = diag_ + 3 * NV;
        gs.deg[0] = deg_ + 4 * NV;
        gs.diag[0] = diag_ + 4 * NV;
        gs.A[1] = gs.A[0]; gs.B[1] = gs.B[0]; gs.C[1] = gs.C[0];
        gs.degIn[1] = gs.degIn[0]; gs.diagIn[1] = gs.diagIn[0];
        gs.deg[1] = gs.deg[0]; gs.diag[1] = gs.diag[0];
        tf32gemm_s<<<dim3(NV / 64, NV / 128, 1), 256>>>(gs);
    }
    dinv_fix<<<(3 * NV + 255) / 256, 256>>>(deg_ + 2 * NV, diag_ + 2 * NV, dinv_ + 2 * NV, 3 * NV);

    // -------- scaled merge + final dinv --------
    emax_dinv<<<NV, 256>>>(Mtb[0], dinv_ + 2 * NV, Mb[1], dinv_ + 4 * NV, An_, dinv_ + 5 * NV);

    // -------- GCN layers, final norm fused into A-loads --------
    sgemmKS<<<dim3(8, NV / 64), blk16>>>(An_, dinv_ + 5 * NV, XW_, H_, HIDD, NV, 8, nullptr);
    sgemm64<<<dim3(1, NV / 64), blk16>>>(H_, w2, HW_, NV, REPD, HIDD, bias1);  // relu(H+bias1) @ w2
    sgemmKS<<<dim3(8, NV / 64), blk16>>>(An_, dinv_ + 5 * NV, HW_, out, REPD, NV, 8, bias2);
}

// round 12
// speedup vs baseline: 1.0516x; 1.0130x over previous
#include <cuda_runtime.h>
#include <math.h>
#include <stdint.h>

// Problem constants
#define NV 1024
#define NE 32768
#define EMBD 128
#define HIDD 64
#define REPD 32

// ---------------- scratch (static device globals) ----------------
__device__ float g_A[2][3][NV][NV];
__device__ float g_p1[2][16][512][512];
__device__ float g_p2[2][4][257][257];
__device__ float g_att[2][3][NV][NV];
__device__ float g_M[2][NV][NV];
__device__ float g_Mt[2][NV][NV];
__device__ float g_An[NV][NV];
__device__ float g_dinv[6][NV];
__device__ float g_deg[5][NV];
__device__ float g_diag[5][NV];
__device__ float g_XW[NV][HIDD];
__device__ float g_H[NV][HIDD];
__device__ float g_HW[NV][REPD];

// ---------------- param structs ----------------
struct Sc5 { const int* e[5]; float* A[5]; float* degz; };
struct PathPtrs {
    const float* in[2]; const float* w[2]; const float* b[2]; float* out[2];
};
struct FAtt {
    const float* p2[2]; const float* w1[2]; const float* b1[2];
    const float* w2[2]; const float* b2[2]; const float* A[2]; float* att[2];
    float* deg[2]; float* diag[2];
};
struct GemS {
    const float* A[2]; const float* B[2]; float* C[2];
    const float* degIn[2]; const float* diagIn[2];
    float* deg[2]; float* diag[2];
};

// ---------------- helpers ----------------
__device__ __forceinline__ uint32_t f2tf(float f) {
    uint32_t r;
    asm("cvt.rna.tf32.f32 %0, %1;" : "=r"(r) : "f"(f));
    return r;
}

__device__ __forceinline__ void mma_tf32(float* c, const uint32_t* a, uint32_t b0, uint32_t b1) {
    asm volatile(
        "mma.sync.aligned.m16n8k8.row.col.f32.tf32.tf32.f32 "
        "{%0,%1,%2,%3}, {%4,%5,%6,%7}, {%8,%9}, {%0,%1,%2,%3};"
        : "+f"(c[0]), "+f"(c[1]), "+f"(c[2]), "+f"(c[3])
        : "r"(a[0]), "r"(a[1]), "r"(a[2]), "r"(a[3]), "r"(b0), "r"(b1));
}

// ---------------- kernels ----------------

__global__ void scatter_all(Sc5 s) {
    int j = blockIdx.y;
    int k = blockIdx.x * blockDim.x + threadIdx.x;
    if (j == 0 && k < 5 * NV) s.degz[k] = 0.0f;
    if (k < NE) {
        const int* e = s.e[j];
        atomicAdd(&s.A[j][e[k] * NV + e[NE + k]], 1.0f);
    }
}

// ---- conv1 (3x3, pad1, L->16) + relu + maxpool2 via tf32 MMA (fp32-exact hi/lo) ----
template <int L>
__device__ __forceinline__ void conv1mma_impl(const float* __restrict__ A,
                                              const float* __restrict__ w,
                                              const float* __restrict__ b,
                                              float* __restrict__ p1,
                                              float* __restrict__ tile,
                                              float* __restrict__ whi,
                                              float* __restrict__ wlo,
                                              float* __restrict__ sb) {
    constexpr int KS = (L * 9 + 7) / 8;
    int t = threadIdx.y * 16 + threadIdx.x;
    int lane = t & 31, wid = t >> 5;

    for (int i = t; i < 512; i += 256) {
        int oc = i >> 5, k = i & 31;
        float wv = (k < L * 9) ? w[oc * L * 9 + k] : 0.0f;
        float hi = __uint_as_float(f2tf(wv));
        whi[i] = hi;
        wlo[i] = __uint_as_float(f2tf(wv - hi));
    }
    if (t < 16) sb[t] = b[t];

    int gy0 = blockIdx.y * 32 - 1, gx0 = blockIdx.x * 32 - 1;
    for (int l = 0; l < L; l++)
        for (int i = t; i < 34 * 34; i += 256) {
            int r = i / 34, c = i % 34;
            int gy = gy0 + r, gx = gx0 + c;
            tile[(l * 34 + r) * 36 + c] = (gy >= 0 && gy < NV && gx >= 0 && gx < NV)
                                              ? A[((size_t)l * NV + gy) * NV + gx] : 0.0f;
        }
    __syncthreads();

    uint32_t ahi[KS][4], alo[KS][4];
    int r0 = (lane >> 2) * 32, r1 = ((lane >> 2) + 8) * 32;
#pragma unroll
    for (int s = 0; s < KS; s++) {
        int c0 = 8 * s + (lane & 3);
        ahi[s][0] = __float_as_uint(whi[r0 + c0]);
        ahi[s][1] = __float_as_uint(whi[r1 + c0]);
        ahi[s][2] = __float_as_uint(whi[r0 + c0 + 4]);
        ahi[s][3] = __float_as_uint(whi[r1 + c0 + 4]);
        alo[s][0] = __float_as_uint(wlo[r0 + c0]);
        alo[s][1] = __float_as_uint(wlo[r1 + c0]);
        alo[s][2] = __float_as_uint(wlo[r0 + c0 + 4]);
        alo[s][3] = __float_as_uint(wlo[r1 + c0 + 4]);
    }

    int boff[KS][2];
#pragma unroll
    for (int s = 0; s < KS; s++)
#pragma unroll
        for (int h = 0; h < 2; h++) {
            int k = 8 * s + (lane & 3) + 4 * h;
            if (k >= L * 9) k = 0;
            int l = k / 9, r = k % 9;
            boff[s][h] = (l * 34 + r / 3) * 36 + (r % 3) + (lane >> 2);
        }

    for (int u = wid; u < 64; u += 8) {
        int py = u >> 2, ux = u & 3;
        int base0 = (2 * py) * 36 + 8 * ux;
        int base1 = base0 + 36;
        float acc0[4] = {0.f, 0.f, 0.f, 0.f};
        float acc1[4] = {0.f, 0.f, 0.f, 0.f};
#pragma unroll
        for (int s = 0; s < KS; s++) {
            uint32_t b00 = __float_as_uint(tile[boff[s][0] + base0]);
            uint32_t b01 = __float_as_uint(tile[boff[s][1] + base0]);
            mma_tf32(acc0, ahi[s], b00, b01);
            mma_tf32(acc0, alo[s], b00, b01);
            uint32_t b10 = __float_as_uint(tile[boff[s][0] + base1]);
            uint32_t b11 = __float_as_uint(tile[boff[s][1] + base1]);
            mma_tf32(acc1, ahi[s], b10, b11);
            mma_tf32(acc1, alo[s], b10, b11);
        }
        int oc0 = lane >> 2, oc1 = oc0 + 8;
        int ox = blockIdx.x * 16 + 4 * ux + (lane & 3);
        int oy = blockIdx.y * 16 + py;
        float m0 = fmaxf(fmaxf(acc0[0], acc0[1]), fmaxf(acc1[0], acc1[1]));
        float m1 = fmaxf(fmaxf(acc0[2], acc0[3]), fmaxf(acc1[2], acc1[3]));
        p1[((size_t)oc0 * 512 + oy) * 512 + ox] = fmaxf(m0 + sb[oc0], 0.0f);
        p1[((size_t)oc1 * 512 + oy) * 512 + ox] = fmaxf(m1 + sb[oc1], 0.0f);
    }
}

__global__ void __launch_bounds__(256) conv1mma_both(PathPtrs p) {
    __shared__ float tile[3 * 34 * 36];
    __shared__ float whi[512], wlo[512];
    __shared__ float sb[16];
    int path = blockIdx.z;
    if (path == 0)
        conv1mma_impl<2>(p.in[0], p.w[0], p.b[0], p.out[0], tile, whi, wlo, sb);
    else
        conv1mma_impl<3>(p.in[1], p.w[1], p.b[1], p.out[1], tile, whi, wlo, sb);
}

// ---- conv2 (3x3, pad2, 16->4) + relu + maxpool2 ----
// Round-6 structure with row stride 40 (even float2 alignment): patch loads
// become 8 LDS.64 per channel instead of 16 LDS.32.
__global__ void conv2pool_both(PathPtrs pp) {
    __shared__ float tile[36 * 40];
    __shared__ float sw[576];
    __shared__ float sb[4];
    int path = blockIdx.z;
    const float* p1 = pp.in[path];
    float* p2 = pp.out[path];
    int tx = threadIdx.x, ty = threadIdx.y;
    int t = ty * 16 + tx;
    for (int i = t; i < 576; i += 256) sw[i] = pp.w[path][i];
    if (t < 4) sb[t] = pp.b[path][t];

    int gy0 = blockIdx.y * 32 - 2, gx0 = blockIdx.x * 32 - 2;

    int srow[6], scol[6], sok[6];
    float r[6];
#pragma unroll
    for (int s = 0; s < 6; s++) {
        int i = t + s * 256;
        srow[s] = i / 36; scol[s] = i % 36;
        sok[s] = (i < 1296);
    }
#pragma unroll
    for (int s = 0; s < 6; s++) {
        if (sok[s]) {
            int gy = gy0 + srow[s], gx = gx0 + scol[s];
            r[s] = (gy >= 0 && gy < 512 && gx >= 0 && gx < 512)
                       ? p1[(size_t)gy * 512 + gx] : 0.0f;
        }
    }

    float acc[4][2][2];
#pragma unroll
    for (int oc = 0; oc < 4; oc++)
#pragma unroll
        for (int py = 0; py < 2; py++)
#pragma unroll
            for (int px = 0; px < 2; px++) acc[oc][py][px] = 0.0f;

    __syncthreads();

    for (int ci = 0; ci < 16; ci++) {
#pragma unroll
        for (int s = 0; s < 6; s++)
            if (sok[s]) tile[srow[s] * 40 + scol[s]] = r[s];
        __syncthreads();
        if (ci < 15) {
#pragma unroll
            for (int s = 0; s < 6; s++) {
                if (sok[s]) {
                    int gy = gy0 + srow[s], gx = gx0 + scol[s];
                    r[s] = (gy >= 0 && gy < 512 && gx >= 0 && gx < 512)
                               ? p1[((size_t)(ci + 1) * 512 + gy) * 512 + gx] : 0.0f;
                }
            }
        }
        // patch via float2 loads (addresses (2ty+rw)*40 + 2tx are even)
        float patch[4][4];
#pragma unroll
        for (int rw = 0; rw < 4; rw++) {
            const float2* rp = (const float2*)&tile[(2 * ty + rw) * 40 + 2 * tx];
            float2 a = rp[0], b = rp[1];
            patch[rw][0] = a.x; patch[rw][1] = a.y;
            patch[rw][2] = b.x; patch[rw][3] = b.y;
        }
#pragma unroll
        for (int oc = 0; oc < 4; oc++)
#pragma unroll
            for (int ky = 0; ky < 3; ky++)
#pragma unroll
                for (int kx = 0; kx < 3; kx++) {
                    float wv = sw[((oc * 16 + ci) * 3 + ky) * 3 + kx];
                    acc[oc][0][0] += wv * patch[ky][kx];
                    acc[oc][0][1] += wv * patch[ky][kx + 1];
                    acc[oc][1][0] += wv * patch[ky + 1][kx];
                    acc[oc][1][1] += wv * patch[ky + 1][kx + 1];
                }
        __syncthreads();
    }
    int x = blockIdx.x * 16 + tx, y = blockIdx.y * 16 + ty;
    if (x < 257 && y < 257) {
#pragma unroll
        for (int oc = 0; oc < 4; oc++) {
            float m = fmaxf(fmaxf(acc[oc][0][0], acc[oc][0][1]),
                            fmaxf(acc[oc][1][0], acc[oc][1][1])) + sb[oc];
            p2[((size_t)oc * 257 + y) * 257 + x] = fmaxf(m, 0.0f);
        }
    }
}

// ---- fused tconv1 + tconv2 + sigmoid + crop + adjacency multiply + att0 deg/diag ----
template <int L>
__device__ __forceinline__ void ftconv4_impl(const float* __restrict__ p2,
                                             const float* __restrict__ sw1,
                                             const float* __restrict__ sb1,
                                             const float* __restrict__ sw2,
                                             const float* __restrict__ sb2,
                                             const float* __restrict__ A,
                                             float* __restrict__ att,
                                             float* __restrict__ deg,
                                             float* __restrict__ diag,
                                             int q, int y) {
    int ky2 = (y + 1) & 1;
    int iy1 = (y - 1 + ky2) >> 1;
    int ky1 = (iy1 + 1) & 1;
    int iy0 = (iy1 - 1 + ky1) >> 1;

    float p[4];
#pragma unroll
    for (int cj = 0; cj < 4; cj++) p[cj] = p2[((size_t)cj * 257 + iy0) * 257 + q];

    float tA[16], tB[16];
#pragma unroll
    for (int ci = 0; ci < 16; ci++) {
        float sA = sb1[ci], sB = sb1[ci];
#pragma unroll
        for (int cj = 0; cj < 4; cj++) {
            int base = ((ci * 4 + cj) * 2 + ky1) * 2;
            sA += sw1[base + 1] * p[cj];
            sB += sw1[base + 0] * p[cj];
        }
        tA[ci] = fmaxf(sA, 0.0f);
        tB[ci] = fmaxf(sB, 0.0f);
    }

    float d0 = 0.f, d1 = 0.f, d2 = 0.f, d3 = 0.f;
#pragma unroll
    for (int l = 0; l < L; l++) {
        float s0A = sb2[l], s1A = sb2[l], s0B = sb2[l], s1B = sb2[l];
#pragma unroll
        for (int ci = 0; ci < 16; ci++) {
            int base = ((l * 16 + ci) * 2 + ky2) * 2;
            float w1v = sw2[base + 1], w0v = sw2[base + 0];
            s0A += w1v * tA[ci]; s1A += w0v * tA[ci];
            s0B += w1v * tB[ci]; s1B += w0v * tB[ci];
        }
        float g0 = 1.0f / (1.0f + expf(-s0A));
        float g1 = 1.0f / (1.0f + expf(-s1A));
        float g2 = 1.0f / (1.0f + expf(-s0B));
        float g3 = 1.0f / (1.0f + expf(-s1B));
        size_t off = (size_t)l * NV * NV + (size_t)y * NV + 4 * q;
        float4 a = *(const float4*)&A[off];
        float4 v = make_float4(a.x * g0, a.y * g1, a.z * g2, a.w * g3);
        *(float4*)&att[off] = v;
        if (l == 0) { d0 = v.x; d1 = v.y; d2 = v.z; d3 = v.w; }
    }

    float s = (d0 + d1) + (d2 + d3);
#pragma unroll
    for (int o = 16; o > 0; o >>= 1) s += __shfl_xor_sync(0xFFFFFFFF, s, o);
    if ((threadIdx.x & 31) == 0) atomicAdd(&deg[y], s);
    if ((y >> 2) == q) {
        int sel = y & 3;
        diag[y] = sel == 0 ? d0 : sel == 1 ? d1 : sel == 2 ? d2 : d3;
    }
}

__global__ void ftconv_att_both(FAtt fa) {
    __shared__ float sw1[256], sb1[16], sw2[192], sb2[3];
    int gidx = blockIdx.x * blockDim.x + threadIdx.x;
    const int PL = NV * 256;
    int path = gidx / PL;
    int idx = gidx - path * PL;
    int q = idx & 255, y = idx >> 8;
    const int L = (path == 0) ? 2 : 3;
    int t = threadIdx.x;
    if (t < 256) sw1[t] = fa.w1[path][t];
    if (t < 16) sb1[t] = fa.b1[path][t];
    for (int i = t; i < L * 64; i += 256) sw2[i] = fa.w2[path][i];
    if (t < L) sb2[t] = fa.b2[path][t];
    __syncthreads();
    if (path == 0)
        ftconv4_impl<2>(fa.p2[0], sw1, sb1, sw2, sb2, fa.A[0], fa.att[0],
                        fa.deg[0], fa.diag[0], q, y);
    else
        ftconv4_impl<3>(fa.p2[1], sw1, sb1, sw2, sb2, fa.A[1], fa.att[1],
                        fa.deg[1], fa.diag[1], q, y);
}

// ---- dinv from accumulated deg/diag ----
__global__ void dinv_fix(const float* __restrict__ deg, const float* __restrict__ diag,
                         float* __restrict__ dv, int n) {
    int i = blockIdx.x * blockDim.x + threadIdx.x;
    if (i < n) {
        float d = deg[i];
        if (diag[i] == 0.0f) d += 1.0f;
        dv[i] = d > 0.0f ? rsqrtf(d) : 0.0f;
    }
}

// ---- scaled max-merge + row-sum/dinv ----
__global__ void emax_dinv(const float* __restrict__ a, const float* __restrict__ dva,
                          const float* __restrict__ b, const float* __restrict__ dvb,
                          float* __restrict__ o, float* __restrict__ dv) {
    int row = blockIdx.x;
    float dar = dva[row], dbr = dvb[row];
    __shared__ float sh[256];
    __shared__ float sdiag;
    float s = 0.0f;
    for (int j = threadIdx.x; j < NV; j += 256) {
        float va = a[(size_t)row * NV + j];
        if (j == row && va == 0.0f) va = 1.0f;
        va *= dar * dva[j];
        float vb = b[(size_t)row * NV + j];
        if (j == row && vb == 0.0f) vb = 1.0f;
        vb *= dbr * dvb[j];
        float v = fmaxf(va, vb);
        o[(size_t)row * NV + j] = v;
        if (j == row) sdiag = v;
        s += v;
    }
    sh[threadIdx.x] = s;
    __syncthreads();
    for (int off = 128; off > 0; off >>= 1) {
        if (threadIdx.x < off) sh[threadIdx.x] += sh[threadIdx.x + off];
        __syncthreads();
    }
    if (threadIdx.x == 0) {
        float d = sh[0];
        if (sdiag == 0.0f) d += 1.0f;
        dv[row] = d > 0.0f ? rsqrtf(d) : 0.0f;
    }
}

// ---------------- tf32 GEMM: dv computed in prologue from deg/diag; norm fused ----
__device__ __forceinline__ void fix_scale4(float4& v, int row, int kc, float dvr,
                                           const float* __restrict__ dv) {
    float4 dk = *(const float4*)&dv[kc];
    float* p = &v.x;
#pragma unroll
    for (int q = 0; q < 4; q++)
        if (row == kc + q && p[q] == 0.0f) p[q] = 1.0f;
    v.x *= dvr * dk.x; v.y *= dvr * dk.y; v.z *= dvr * dk.z; v.w *= dvr * dk.w;
}

__global__ void __launch_bounds__(256) tf32gemm_s(GemS g) {
    const float* __restrict__ A = g.A[blockIdx.z];
    const float* __restrict__ B = g.B[blockIdx.z];
    float* __restrict__ C = g.C[blockIdx.z];
    const float* __restrict__ degIn = g.degIn[blockIdx.z];
    const float* __restrict__ diagIn = g.diagIn[blockIdx.z];
    float* __restrict__ deg = g.deg[blockIdx.z];
    float* __restrict__ diag = g.diag[blockIdx.z];
    const int Nn = NV, K = NV;

    __shared__ float As[2][16][136];
    __shared__ float Bs[2][16][72];
    __shared__ __align__(16) float sdv[NV];

    const int tid = threadIdx.x;
    const int lane = tid & 31;
    const int wid = tid >> 5;
    const int wr = wid & 3;
    const int wc = wid >> 2;
    const int m0 = blockIdx.y * 128;
    const int n0 = blockIdx.x * 64;

    for (int i = tid; i < NV; i += 256) {
        float d = degIn[i];
        if (diagIn[i] == 0.0f) d += 1.0f;
        sdv[i] = d > 0.0f ? rsqrtf(d) : 0.0f;
    }
    __syncthreads();

    float acc[2][4][4];
#pragma unroll
    for (int mi = 0; mi < 2; mi++)
#pragma unroll
        for (int ni = 0; ni < 4; ni++)
#pragma unroll
            for (int r = 0; r < 4; r++) acc[mi][ni][r] = 0.0f;

    const int ar = tid >> 2;
    const int ac4 = (tid & 3) << 2;
    const int bk = tid >> 4;
    const int bn4 = (tid & 15) << 2;
    const int rowA0 = m0 + ar, rowA1 = m0 + 64 + ar;
    const float dvr0 = sdv[rowA0], dvr1 = sdv[rowA1];

    float4 av0, av1, bv;
    const int T = K >> 4;

    av0 = *(const float4*)&A[(size_t)rowA0 * K + ac4];
    av1 = *(const float4*)&A[(size_t)rowA1 * K + ac4];
    bv  = *(const float4*)&B[(size_t)bk * Nn + n0 + bn4];
    fix_scale4(av0, rowA0, ac4, dvr0, sdv);
    fix_scale4(av1, rowA1, ac4, dvr1, sdv);

    As[0][ac4 + 0][ar] = __uint_as_float(f2tf(av0.x));
    As[0][ac4 + 1][ar] = __uint_as_float(f2tf(av0.y));
    As[0][ac4 + 2][ar] = __uint_as_float(f2tf(av0.z));
    As[0][ac4 + 3][ar] = __uint_as_float(f2tf(av0.w));
    As[0][ac4 + 0][ar + 64] = __uint_as_float(f2tf(av1.x));
    As[0][ac4 + 1][ar + 64] = __uint_as_float(f2tf(av1.y));
    As[0][ac4 + 2][ar + 64] = __uint_as_float(f2tf(av1.z));
    As[0][ac4 + 3][ar + 64] = __uint_as_float(f2tf(av1.w));
    {
        float4 bt;
        bt.x = __uint_as_float(f2tf(bv.x));
        bt.y = __uint_as_float(f2tf(bv.y));
        bt.z = __uint_as_float(f2tf(bv.z));
        bt.w = __uint_as_float(f2tf(bv.w));
        *(float4*)&Bs[0][bk][bn4] = bt;
    }
    __syncthreads();

    for (int t = 0; t < T; t++) {
        int cur = t & 1;
        if (t + 1 < T) {
            int kb = (t + 1) << 4;
            av0 = *(const float4*)&A[(size_t)rowA0 * K + kb + ac4];
            av1 = *(const float4*)&A[(size_t)rowA1 * K + kb + ac4];
            bv  = *(const float4*)&B[(size_t)(kb + bk) * Nn + n0 + bn4];
            fix_scale4(av0, rowA0, kb + ac4, dvr0, sdv);
            fix_scale4(av1, rowA1, kb + ac4, dvr1, sdv);
        }
#pragma unroll
        for (int ks = 0; ks < 2; ks++) {
            const int k0 = ks * 8;
            uint32_t a[2][4], b[4][2];
            const int kl = k0 + (lane & 3);
            const int rl = lane >> 2;
#pragma unroll
            for (int mi = 0; mi < 2; mi++) {
                int m = wr * 32 + mi * 16 + rl;
                a[mi][0] = __float_as_uint(As[cur][kl][m]);
                a[mi][1] = __float_as_uint(As[cur][kl][m + 8]);
                a[mi][2] = __float_as_uint(As[cur][kl + 4][m]);
                a[mi][3] = __float_as_uint(As[cur][kl + 4][m + 8]);
            }
#pragma unroll
            for (int ni = 0; ni < 4; ni++) {
                int n = wc * 32 + ni * 8 + rl;
                b[ni][0] = __float_as_uint(Bs[cur][kl][n]);
                b[ni][1] = __float_as_uint(Bs[cur][kl + 4][n]);
            }
#pragma unroll
            for (int mi = 0; mi < 2; mi++)
#pragma unroll
                for (int ni = 0; ni < 4; ni++) {
                    asm volatile(
                        "mma.sync.aligned.m16n8k8.row.col.f32.tf32.tf32.f32 "
                        "{%0,%1,%2,%3}, {%4,%5,%6,%7}, {%8,%9}, {%0,%1,%2,%3};"
                        : "+f"(acc[mi][ni][0]), "+f"(acc[mi][ni][1]),
                          "+f"(acc[mi][ni][2]), "+f"(acc[mi][ni][3])
                        : "r"(a[mi][0]), "r"(a[mi][1]), "r"(a[mi][2]), "r"(a[mi][3]),
                          "r"(b[ni][0]), "r"(b[ni][1]));
                }
        }
        if (t + 1 < T) {
            int nxt = (t + 1) & 1;
            As[nxt][ac4 + 0][ar] = __uint_as_float(f2tf(av0.x));
            As[nxt][ac4 + 1][ar] = __uint_as_float(f2tf(av0.y));
            As[nxt][ac4 + 2][ar] = __uint_as_float(f2tf(av0.z));
            As[nxt][ac4 + 3][ar] = __uint_as_float(f2tf(av0.w));
            As[nxt][ac4 + 0][ar + 64] = __uint_as_float(f2tf(av1.x));
            As[nxt][ac4 + 1][ar + 64] = __uint_as_float(f2tf(av1.y));
            As[nxt][ac4 + 2][ar + 64] = __uint_as_float(f2tf(av1.z));
            As[nxt][ac4 + 3][ar + 64] = __uint_as_float(f2tf(av1.w));
            float4 bt;
            bt.x = __uint_as_float(f2tf(bv.x));
            bt.y = __uint_as_float(f2tf(bv.y));
            bt.z = __uint_as_float(f2tf(bv.z));
            bt.w = __uint_as_float(f2tf(bv.w));
            *(float4*)&Bs[nxt][bk][bn4] = bt;
            __syncthreads();
        }
    }

    const int rl = lane >> 2;
#pragma unroll
    for (int mi = 0; mi < 2; mi++) {
        int row = m0 + wr * 32 + mi * 16 + rl;
#pragma unroll
        for (int ni = 0; ni < 4; ni++) {
            int col = n0 + wc * 32 + ni * 8 + ((lane & 3) << 1);
            if (row == col) diag[row] = acc[mi][ni][0];
            if (row == col + 1) diag[row] = acc[mi][ni][1];
            if (row + 8 == col) diag[row + 8] = acc[mi][ni][2];
            if (row + 8 == col + 1) diag[row + 8] = acc[mi][ni][3];
            *(float2*)&C[(size_t)row * Nn + col] = make_float2(acc[mi][ni][0], acc[mi][ni][1]);
            *(float2*)&C[(size_t)(row + 8) * Nn + col] = make_float2(acc[mi][ni][2], acc[mi][ni][3]);
        }
    }
    float rs[4] = {0.0f, 0.0f, 0.0f, 0.0f};
#pragma unroll
    for (int mi = 0; mi < 2; mi++)
#pragma unroll
        for (int ni = 0; ni < 4; ni++) {
            rs[mi * 2 + 0] += acc[mi][ni][0] + acc[mi][ni][1];
            rs[mi * 2 + 1] += acc[mi][ni][2] + acc[mi][ni][3];
        }
#pragma unroll
    for (int q = 0; q < 4; q++) {
        rs[q] += __shfl_xor_sync(0xFFFFFFFF, rs[q], 1);
        rs[q] += __shfl_xor_sync(0xFFFFFFFF, rs[q], 2);
    }
    if ((lane & 3) == 0) {
        int rbase = m0 + wr * 32 + rl;
        atomicAdd(&deg[rbase], rs[0]);
        atomicAdd(&deg[rbase + 8], rs[1]);
        atomicAdd(&deg[rbase + 16], rs[2]);
        atomicAdd(&deg[rbase + 24], rs[3]);
    }
}

// plain fp32 64x64 tile GEMM; optional bias+relu applied to A-operand on load.
__global__ void sgemm64(const float* __restrict__ A, const float* __restrict__ B,
                        float* __restrict__ C, int M, int Nn, int K,
                        const float* __restrict__ abias) {
    __shared__ float As[16][64];
    __shared__ float Bs[16][64];
    int tx = threadIdx.x, ty = threadIdx.y;
    int tid = ty * 16 + tx;
    int m0 = blockIdx.y * 64, n0 = blockIdx.x * 64;
    float acc[4][4];
#pragma unroll
    for (int i = 0; i < 4; i++)
#pragma unroll
        for (int j = 0; j < 4; j++) acc[i][j] = 0.0f;
    int la_r = tid / 16, la_k = tid % 16;
    int lb_k = tid / 64, lb_n = tid % 64;
    for (int k0 = 0; k0 < K; k0 += 16) {
#pragma unroll
        for (int r = 0; r < 4; r++) {
            float v = A[(size_t)(m0 + la_r + 16 * r) * K + k0 + la_k];
            if (abias != nullptr) v = fmaxf(v + abias[k0 + la_k], 0.0f);
            As[la_k][la_r + 16 * r] = v;
        }
#pragma unroll
        for (int r = 0; r < 4; r++) {
            int kk = lb_k + 4 * r;
            Bs[kk][lb_n] = (n0 + lb_n < Nn) ? B[(size_t)(k0 + kk) * Nn + n0 + lb_n] : 0.0f;
        }
        __syncthreads();
#pragma unroll
        for (int k = 0; k < 16; k++) {
            float a[4], b[4];
#pragma unroll
            for (int i = 0; i < 4; i++) a[i] = As[k][ty * 4 + i];
#pragma unroll
            for (int j = 0; j < 4; j++) b[j] = Bs[k][tx * 4 + j];
#pragma unroll
            for (int i = 0; i < 4; i++)
#pragma unroll
                for (int j = 0; j < 4; j++) acc[i][j] += a[i] * b[j];
        }
        __syncthreads();
    }
#pragma unroll
    for (int i = 0; i < 4; i++) {
        int row = m0 + ty * 4 + i;
#pragma unroll
        for (int j = 0; j < 4; j++) {
            int col = n0 + tx * 4 + j;
            if (col < Nn) C[(size_t)row * Nn + col] = acc[i][j];
        }
    }
}

// split-K fp32 GEMM with fused gcn-norm on A: C += (Dv fix(A) Dv) @ B.
__global__ void sgemmKS(const float* __restrict__ A, const float* __restrict__ dv,
                        const float* __restrict__ B, float* __restrict__ C,
                        int Nn, int K, int KS, const float* __restrict__ bias) {
    __shared__ float As[16][64];
    __shared__ float Bs[16][64];
    int tx = threadIdx.x, ty = threadIdx.y;
    int tid = ty * 16 + tx;
    int m0 = blockIdx.y * 64;
    int kLen = K / KS;
    int kStart = blockIdx.x * kLen;
    float acc[4][4];
#pragma unroll
    for (int i = 0; i < 4; i++)
#pragma unroll
        for (int j = 0; j < 4; j++) acc[i][j] = 0.0f;
    int la_r = tid / 16, la_k = tid % 16;
    int lb_k = tid / 64, lb_n = tid % 64;
    for (int k0 = kStart; k0 < kStart + kLen; k0 += 16) {
#pragma unroll
        for (int r = 0; r < 4; r++) {
            int row = m0 + la_r + 16 * r;
            int kc = k0 + la_k;
            float v = A[(size_t)row * K + kc];
            if (row == kc && v == 0.0f) v = 1.0f;
            As[la_k][la_r + 16 * r] = v * dv[row] * dv[kc];
        }
#pragma unroll
        for (int r = 0; r < 4; r++) {
            int kk = lb_k + 4 * r;
            Bs[kk][lb_n] = (lb_n < Nn) ? B[(size_t)(k0 + kk) * Nn + lb_n] : 0.0f;
        }
        __syncthreads();
#pragma unroll
        for (int k = 0; k < 16; k++) {
            float a[4], b[4];
#pragma unroll
            for (int i = 0; i < 4; i++) a[i] = As[k][ty * 4 + i];
#pragma unroll
            for (int j = 0; j < 4; j++) b[j] = Bs[k][tx * 4 + j];
#pragma unroll
            for (int i = 0; i < 4; i++)
#pragma unroll
                for (int j = 0; j < 4; j++) acc[i][j] += a[i] * b[j];
        }
        __syncthreads();
    }
#pragma unroll
    for (int i = 0; i < 4; i++) {
        int row = m0 + ty * 4 + i;
#pragma unroll
        for (int j = 0; j < 4; j++) {
            int col = tx * 4 + j;
            if (col < Nn) {
                float v = acc[i][j];
                if (bias != nullptr && kStart == 0) v += bias[col];
                atomicAdd(&C[(size_t)row * Nn + col], v);
            }
        }
    }
}

// ---------------- host orchestration ----------------

extern "C" void kernel_launch(void* const* d_in, const int* in_sizes, int n_in,
                              void* d_out, int out_size) {
    const float* x = (const float*)d_in[0];
    const int* edges[5];
    for (int i = 0; i < 5; i++) edges[i] = (const int*)d_in[1 + i];
    const float* pbp[2][8];
    for (int b = 0; b < 2; b++)
        for (int i = 0; i < 8; i++) pbp[b][i] = (const float*)d_in[6 + b * 8 + i];
    const float* w1    = (const float*)d_in[22];
    const float* bias1 = (const float*)d_in[23];
    const float* w2    = (const float*)d_in[24];
    const float* bias2 = (const float*)d_in[25];
    float* out = (float*)d_out;

    float *A_, *p1_, *p2_, *att_, *M_, *Mt_, *An_, *dinv_, *deg_, *diag_, *XW_, *H_, *HW_;
    cudaGetSymbolAddress((void**)&A_,    g_A);
    cudaGetSymbolAddress((void**)&p1_,   g_p1);
    cudaGetSymbolAddress((void**)&p2_,   g_p2);
    cudaGetSymbolAddress((void**)&att_,  g_att);
    cudaGetSymbolAddress((void**)&M_,    g_M);
    cudaGetSymbolAddress((void**)&Mt_,   g_Mt);
    cudaGetSymbolAddress((void**)&An_,   g_An);
    cudaGetSymbolAddress((void**)&dinv_, g_dinv);
    cudaGetSymbolAddress((void**)&deg_,  g_deg);
    cudaGetSymbolAddress((void**)&diag_, g_diag);
    cudaGetSymbolAddress((void**)&XW_,   g_XW);
    cudaGetSymbolAddress((void**)&H_,    g_H);
    cudaGetSymbolAddress((void**)&HW_,   g_HW);

    const size_t PLANE = (size_t)NV * NV;
    dim3 blk16(16, 16);

    float* Ab[2]   = { A_,   A_   + 3 * PLANE };
    float* p1b[2]  = { p1_,  p1_  + (size_t)16 * 512 * 512 };
    float* p2b[2]  = { p2_,  p2_  + (size_t)4 * 257 * 257 };
    float* attb[2] = { att_, att_ + 3 * PLANE };
    float* Mb[2]   = { M_,   M_   + PLANE };
    float* Mtb[2]  = { Mt_,  Mt_  + PLANE };

    // -------- setup --------
    cudaMemsetAsync(A_, 0, 6 * PLANE * sizeof(float), 0);
    cudaMemsetAsync(H_, 0, (size_t)NV * HIDD * sizeof(float), 0);
    cudaMemsetAsync(out, 0, (size_t)NV * REPD * sizeof(float), 0);
    sgemm64<<<dim3(1, NV / 64), blk16>>>(x, w1, XW_, NV, HIDD, EMBD, nullptr);

    // -------- scatter all 5 edge lists (also zeros deg) --------
    Sc5 sc;
    sc.e[0] = edges[0]; sc.A[0] = Ab[0];
    sc.e[1] = edges[1]; sc.A[1] = Ab[0] + PLANE;
    sc.e[2] = edges[2]; sc.A[2] = Ab[1];
    sc.e[3] = edges[3]; sc.A[3] = Ab[1] + PLANE;
    sc.e[4] = edges[4]; sc.A[4] = Ab[1] + 2 * PLANE;
    sc.degz = deg_;
    scatter_all<<<dim3((NE + 255) / 256, 5), 256>>>(sc);

    // -------- conv encoder (both paths batched) --------
    PathPtrs c1 = {{Ab[0], Ab[1]}, {pbp[0][0], pbp[1][0]}, {pbp[0][1], pbp[1][1]}, {p1b[0], p1b[1]}};
    conv1mma_both<<<dim3(32, 32, 2), blk16>>>(c1);

    PathPtrs c2 = {{p1b[0], p1b[1]}, {pbp[0][2], pbp[1][2]}, {pbp[0][3], pbp[1][3]}, {p2b[0], p2b[1]}};
    conv2pool_both<<<dim3(17, 17, 2), blk16>>>(c2);

    // fused tconv1 + tconv2 + sigmoid + adjacency multiply + att0 deg/diag (4-wide)
    FAtt fa;
    for (int p = 0; p < 2; p++) {
        fa.p2[p] = p2b[p];
        fa.w1[p] = pbp[p][4]; fa.b1[p] = pbp[p][5];
        fa.w2[p] = pbp[p][6]; fa.b2[p] = pbp[p][7];
        fa.A[p] = Ab[p]; fa.att[p] = attb[p];
        fa.deg[p] = deg_ + p * NV; fa.diag[p] = diag_ + p * NV;
    }
    ftconv_att_both<<<2 * NV, 256>>>(fa);

    // -------- M-chain, norms + dv computed inside GEMMs --------
    {
        GemS gs;
        gs.A[0] = attb[0];          gs.A[1] = attb[1];
        gs.B[0] = attb[0] + PLANE;  gs.B[1] = attb[1] + PLANE;
        gs.C[0] = Mtb[0];           gs.C[1] = Mtb[1];
        gs.degIn[0] = deg_;         gs.degIn[1] = deg_ + NV;
        gs.diagIn[0] = diag_;       gs.diagIn[1] = diag_ + NV;
        gs.deg[0] = deg_ + 2 * NV;  gs.deg[1] = deg_ + 3 * NV;
        gs.diag[0] = diag_ + 2 * NV; gs.diag[1] = diag_ + 3 * NV;
        tf32gemm_s<<<dim3(NV / 64, NV / 128, 2), 256>>>(gs);
    }
    {
        GemS gs;
        gs.A[0] = Mtb[1];
        gs.B[0] = attb[1] + 2 * PLANE;
        gs.C[0] = Mb[1];
        gs.degIn[0] = deg_ + 3 * NV;
        gs.diagIn[0] = diag_ + 3 * NV;
        gs.deg[0] = deg_ + 4 * NV;
        gs.diag[0] = diag_ + 4 * NV;
        gs.A[1] = gs.A[0]; gs.B[1] = gs.B[0]; gs.C[1] = gs.C[0];
        gs.degIn[1] = gs.degIn[0]; gs.diagIn[1] = gs.diagIn[0];
        gs.deg[1] = gs.deg[0]; gs.diag[1] = gs.diag[0];
        tf32gemm_s<<<dim3(NV / 64, NV / 128, 1), 256>>>(gs);
    }
    dinv_fix<<<(3 * NV + 255) / 256, 256>>>(deg_ + 2 * NV, diag_ + 2 * NV, dinv_ + 2 * NV, 3 * NV);

    // -------- scaled merge + final dinv --------
    emax_dinv<<<NV, 256>>>(Mtb[0], dinv_ + 2 * NV, Mb[1], dinv_ + 4 * NV, An_, dinv_ + 5 * NV);

    // -------- GCN layers, final norm fused into A-loads --------
    sgemmKS<<<dim3(8, NV / 64), blk16>>>(An_, dinv_ + 5 * NV, XW_, H_, HIDD, NV, 8, nullptr);
    sgemm64<<<dim3(1, NV / 64), blk16>>>(H_, w2, HW_, NV, REPD, HIDD, bias1);  // relu(H+bias1) @ w2
    sgemmKS<<<dim3(8, NV / 64), blk16>>>(An_, dinv_ + 5 * NV, HW_, out, REPD, NV, 8, bias2);
}

// round 13
// speedup vs baseline: 1.0599x; 1.0079x over previous
#include <cuda_runtime.h>
#include <math.h>
#include <stdint.h>

// Problem constants
#define NV 1024
#define NE 32768
#define EMBD 128
#define HIDD 64
#define REPD 32

// ---------------- scratch (static device globals) ----------------
__device__ float g_A[2][3][NV][NV];
__device__ float g_p1[2][16][512][512];
__device__ float g_p2[2][4][257][257];
__device__ float g_att[2][3][NV][NV];
__device__ float g_M[2][NV][NV];
__device__ float g_Mt[2][NV][NV];
__device__ float g_An[NV][NV];
__device__ float g_dinv[6][NV];
__device__ float g_deg[5][NV];
__device__ float g_diag[5][NV];
__device__ float g_XW[NV][HIDD];
__device__ float g_H[NV][HIDD];
__device__ float g_HW[NV][REPD];

// ---------------- param structs ----------------
struct Sc5 { const int* e[5]; float* A[5]; float* degz; float* Hz; float* outz; };
struct PathPtrs {
    const float* in[2]; const float* w[2]; const float* b[2]; float* out[2];
};
struct FAtt {
    const float* p2[2]; const float* w1[2]; const float* b1[2];
    const float* w2[2]; const float* b2[2]; const float* A[2]; float* att[2];
    float* deg[2]; float* diag[2];
};
struct GemS {
    const float* A[2]; const float* B[2]; float* C[2];
    const float* degIn[2]; const float* diagIn[2];
    float* deg[2]; float* diag[2];
};

// ---------------- helpers ----------------
__device__ __forceinline__ uint32_t f2tf(float f) {
    uint32_t r;
    asm("cvt.rna.tf32.f32 %0, %1;" : "=r"(r) : "f"(f));
    return r;
}

__device__ __forceinline__ float fsigmoid(float s) {
    return 1.0f / (1.0f + __expf(-s));
}

__device__ __forceinline__ void mma_tf32(float* c, const uint32_t* a, uint32_t b0, uint32_t b1) {
    asm volatile(
        "mma.sync.aligned.m16n8k8.row.col.f32.tf32.tf32.f32 "
        "{%0,%1,%2,%3}, {%4,%5,%6,%7}, {%8,%9}, {%0,%1,%2,%3};"
        : "+f"(c[0]), "+f"(c[1]), "+f"(c[2]), "+f"(c[3])
        : "r"(a[0]), "r"(a[1]), "r"(a[2]), "r"(a[3]), "r"(b0), "r"(b1));
}

// ---------------- kernels ----------------

__global__ void scatter_all(Sc5 s) {
    int j = blockIdx.y;
    int k = blockIdx.x * blockDim.x + threadIdx.x;
    // fold small zero-fills into idle lanes (grid.x*256 = 32768 threads per j)
    if (j == 0 && k < 5 * NV) s.degz[k] = 0.0f;
    if (j == 1) s.Hz[k] = 0.0f;               // H first half (32768)
    if (j == 2) s.Hz[32768 + k] = 0.0f;       // H second half
    if (j == 3) s.outz[k] = 0.0f;             // out (32768)
    if (k < NE) {
        const int* e = s.e[j];
        atomicAdd(&s.A[j][e[k] * NV + e[NE + k]], 1.0f);
    }
}

// ---- conv1 (3x3, pad1, L->16) + relu + maxpool2 via tf32 MMA (fp32-exact hi/lo) ----
template <int L>
__device__ __forceinline__ void conv1mma_impl(const float* __restrict__ A,
                                              const float* __restrict__ w,
                                              const float* __restrict__ b,
                                              float* __restrict__ p1,
                                              float* __restrict__ tile,
                                              float* __restrict__ whi,
                                              float* __restrict__ wlo,
                                              float* __restrict__ sb) {
    constexpr int KS = (L * 9 + 7) / 8;
    int t = threadIdx.y * 16 + threadIdx.x;
    int lane = t & 31, wid = t >> 5;

    for (int i = t; i < 512; i += 256) {
        int oc = i >> 5, k = i & 31;
        float wv = (k < L * 9) ? w[oc * L * 9 + k] : 0.0f;
        float hi = __uint_as_float(f2tf(wv));
        whi[i] = hi;
        wlo[i] = __uint_as_float(f2tf(wv - hi));
    }
    if (t < 16) sb[t] = b[t];

    int gy0 = blockIdx.y * 32 - 1, gx0 = blockIdx.x * 32 - 1;
    for (int l = 0; l < L; l++)
        for (int i = t; i < 34 * 34; i += 256) {
            int r = i / 34, c = i % 34;
            int gy = gy0 + r, gx = gx0 + c;
            tile[(l * 34 + r) * 36 + c] = (gy >= 0 && gy < NV && gx >= 0 && gx < NV)
                                              ? A[((size_t)l * NV + gy) * NV + gx] : 0.0f;
        }
    __syncthreads();

    uint32_t ahi[KS][4], alo[KS][4];
    int r0 = (lane >> 2) * 32, r1 = ((lane >> 2) + 8) * 32;
#pragma unroll
    for (int s = 0; s < KS; s++) {
        int c0 = 8 * s + (lane & 3);
        ahi[s][0] = __float_as_uint(whi[r0 + c0]);
        ahi[s][1] = __float_as_uint(whi[r1 + c0]);
        ahi[s][2] = __float_as_uint(whi[r0 + c0 + 4]);
        ahi[s][3] = __float_as_uint(whi[r1 + c0 + 4]);
        alo[s][0] = __float_as_uint(wlo[r0 + c0]);
        alo[s][1] = __float_as_uint(wlo[r1 + c0]);
        alo[s][2] = __float_as_uint(wlo[r0 + c0 + 4]);
        alo[s][3] = __float_as_uint(wlo[r1 + c0 + 4]);
    }

    int boff[KS][2];
#pragma unroll
    for (int s = 0; s < KS; s++)
#pragma unroll
        for (int h = 0; h < 2; h++) {
            int k = 8 * s + (lane & 3) + 4 * h;
            if (k >= L * 9) k = 0;
            int l = k / 9, r = k % 9;
            boff[s][h] = (l * 34 + r / 3) * 36 + (r % 3) + (lane >> 2);
        }

    for (int u = wid; u < 64; u += 8) {
        int py = u >> 2, ux = u & 3;
        int base0 = (2 * py) * 36 + 8 * ux;
        int base1 = base0 + 36;
        float acc0[4] = {0.f, 0.f, 0.f, 0.f};
        float acc1[4] = {0.f, 0.f, 0.f, 0.f};
#pragma unroll
        for (int s = 0; s < KS; s++) {
            uint32_t b00 = __float_as_uint(tile[boff[s][0] + base0]);
            uint32_t b01 = __float_as_uint(tile[boff[s][1] + base0]);
            mma_tf32(acc0, ahi[s], b00, b01);
            mma_tf32(acc0, alo[s], b00, b01);
            uint32_t b10 = __float_as_uint(tile[boff[s][0] + base1]);
            uint32_t b11 = __float_as_uint(tile[boff[s][1] + base1]);
            mma_tf32(acc1, ahi[s], b10, b11);
            mma_tf32(acc1, alo[s], b10, b11);
        }
        int oc0 = lane >> 2, oc1 = oc0 + 8;
        int ox = blockIdx.x * 16 + 4 * ux + (lane & 3);
        int oy = blockIdx.y * 16 + py;
        float m0 = fmaxf(fmaxf(acc0[0], acc0[1]), fmaxf(acc1[0], acc1[1]));
        float m1 = fmaxf(fmaxf(acc0[2], acc0[3]), fmaxf(acc1[2], acc1[3]));
        p1[((size_t)oc0 * 512 + oy) * 512 + ox] = fmaxf(m0 + sb[oc0], 0.0f);
        p1[((size_t)oc1 * 512 + oy) * 512 + ox] = fmaxf(m1 + sb[oc1], 0.0f);
    }
}

__global__ void __launch_bounds__(256) conv1mma_both(PathPtrs p) {
    __shared__ float tile[3 * 34 * 36];
    __shared__ float whi[512], wlo[512];
    __shared__ float sb[16];
    int path = blockIdx.z;
    if (path == 0)
        conv1mma_impl<2>(p.in[0], p.w[0], p.b[0], p.out[0], tile, whi, wlo, sb);
    else
        conv1mma_impl<3>(p.in[1], p.w[1], p.b[1], p.out[1], tile, whi, wlo, sb);
}

// ---- conv2 (3x3, pad2, 16->4) + relu + maxpool2 (stride-40 float2 LDS, best) ----
__global__ void conv2pool_both(PathPtrs pp) {
    __shared__ float tile[36 * 40];
    __shared__ float sw[576];
    __shared__ float sb[4];
    int path = blockIdx.z;
    const float* p1 = pp.in[path];
    float* p2 = pp.out[path];
    int tx = threadIdx.x, ty = threadIdx.y;
    int t = ty * 16 + tx;
    for (int i = t; i < 576; i += 256) sw[i] = pp.w[path][i];
    if (t < 4) sb[t] = pp.b[path][t];

    int gy0 = blockIdx.y * 32 - 2, gx0 = blockIdx.x * 32 - 2;

    int srow[6], scol[6], sok[6];
    float r[6];
#pragma unroll
    for (int s = 0; s < 6; s++) {
        int i = t + s * 256;
        srow[s] = i / 36; scol[s] = i % 36;
        sok[s] = (i < 1296);
    }
#pragma unroll
    for (int s = 0; s < 6; s++) {
        if (sok[s]) {
            int gy = gy0 + srow[s], gx = gx0 + scol[s];
            r[s] = (gy >= 0 && gy < 512 && gx >= 0 && gx < 512)
                       ? p1[(size_t)gy * 512 + gx] : 0.0f;
        }
    }

    float acc[4][2][2];
#pragma unroll
    for (int oc = 0; oc < 4; oc++)
#pragma unroll
        for (int py = 0; py < 2; py++)
#pragma unroll
            for (int px = 0; px < 2; px++) acc[oc][py][px] = 0.0f;

    __syncthreads();

    for (int ci = 0; ci < 16; ci++) {
#pragma unroll
        for (int s = 0; s < 6; s++)
            if (sok[s]) tile[srow[s] * 40 + scol[s]] = r[s];
        __syncthreads();
        if (ci < 15) {
#pragma unroll
            for (int s = 0; s < 6; s++) {
                if (sok[s]) {
                    int gy = gy0 + srow[s], gx = gx0 + scol[s];
                    r[s] = (gy >= 0 && gy < 512 && gx >= 0 && gx < 512)
                               ? p1[((size_t)(ci + 1) * 512 + gy) * 512 + gx] : 0.0f;
                }
            }
        }
        float patch[4][4];
#pragma unroll
        for (int rw = 0; rw < 4; rw++) {
            const float2* rp = (const float2*)&tile[(2 * ty + rw) * 40 + 2 * tx];
            float2 a = rp[0], b = rp[1];
            patch[rw][0] = a.x; patch[rw][1] = a.y;
            patch[rw][2] = b.x; patch[rw][3] = b.y;
        }
#pragma unroll
        for (int oc = 0; oc < 4; oc++)
#pragma unroll
            for (int ky = 0; ky < 3; ky++)
#pragma unroll
                for (int kx = 0; kx < 3; kx++) {
                    float wv = sw[((oc * 16 + ci) * 3 + ky) * 3 + kx];
                    acc[oc][0][0] += wv * patch[ky][kx];
                    acc[oc][0][1] += wv * patch[ky][kx + 1];
                    acc[oc][1][0] += wv * patch[ky + 1][kx];
                    acc[oc][1][1] += wv * patch[ky + 1][kx + 1];
                }
        __syncthreads();
    }
    int x = blockIdx.x * 16 + tx, y = blockIdx.y * 16 + ty;
    if (x < 257 && y < 257) {
#pragma unroll
        for (int oc = 0; oc < 4; oc++) {
            float m = fmaxf(fmaxf(acc[oc][0][0], acc[oc][0][1]),
                            fmaxf(acc[oc][1][0], acc[oc][1][1])) + sb[oc];
            p2[((size_t)oc * 257 + y) * 257 + x] = fmaxf(m, 0.0f);
        }
    }
}

// ---- fused tconv1 + tconv2 + sigmoid + crop + adjacency multiply + att0 deg/diag ----
template <int L>
__device__ __forceinline__ void ftconv4_impl(const float* __restrict__ p2,
                                             const float* __restrict__ sw1,
                                             const float* __restrict__ sb1,
                                             const float* __restrict__ sw2,
                                             const float* __restrict__ sb2,
                                             const float* __restrict__ A,
                                             float* __restrict__ att,
                                             float* __restrict__ deg,
                                             float* __restrict__ diag,
                                             int q, int y) {
    int ky2 = (y + 1) & 1;
    int iy1 = (y - 1 + ky2) >> 1;
    int ky1 = (iy1 + 1) & 1;
    int iy0 = (iy1 - 1 + ky1) >> 1;

    float p[4];
#pragma unroll
    for (int cj = 0; cj < 4; cj++) p[cj] = p2[((size_t)cj * 257 + iy0) * 257 + q];

    float tA[16], tB[16];
#pragma unroll
    for (int ci = 0; ci < 16; ci++) {
        float sA = sb1[ci], sB = sb1[ci];
#pragma unroll
        for (int cj = 0; cj < 4; cj++) {
            int base = ((ci * 4 + cj) * 2 + ky1) * 2;
            sA += sw1[base + 1] * p[cj];
            sB += sw1[base + 0] * p[cj];
        }
        tA[ci] = fmaxf(sA, 0.0f);
        tB[ci] = fmaxf(sB, 0.0f);
    }

    float d0 = 0.f, d1 = 0.f, d2 = 0.f, d3 = 0.f;
#pragma unroll
    for (int l = 0; l < L; l++) {
        float s0A = sb2[l], s1A = sb2[l], s0B = sb2[l], s1B = sb2[l];
#pragma unroll
        for (int ci = 0; ci < 16; ci++) {
            int base = ((l * 16 + ci) * 2 + ky2) * 2;
            float w1v = sw2[base + 1], w0v = sw2[base + 0];
            s0A += w1v * tA[ci]; s1A += w0v * tA[ci];
            s0B += w1v * tB[ci]; s1B += w0v * tB[ci];
        }
        float g0 = fsigmoid(s0A);
        float g1 = fsigmoid(s1A);
        float g2 = fsigmoid(s0B);
        float g3 = fsigmoid(s1B);
        size_t off = (size_t)l * NV * NV + (size_t)y * NV + 4 * q;
        float4 a = *(const float4*)&A[off];
        float4 v = make_float4(a.x * g0, a.y * g1, a.z * g2, a.w * g3);
        *(float4*)&att[off] = v;
        if (l == 0) { d0 = v.x; d1 = v.y; d2 = v.z; d3 = v.w; }
    }

    float s = (d0 + d1) + (d2 + d3);
#pragma unroll
    for (int o = 16; o > 0; o >>= 1) s += __shfl_xor_sync(0xFFFFFFFF, s, o);
    if ((threadIdx.x & 31) == 0) atomicAdd(&deg[y], s);
    if ((y >> 2) == q) {
        int sel = y & 3;
        diag[y] = sel == 0 ? d0 : sel == 1 ? d1 : sel == 2 ? d2 : d3;
    }
}

__global__ void ftconv_att_both(FAtt fa) {
    __shared__ float sw1[256], sb1[16], sw2[192], sb2[3];
    int gidx = blockIdx.x * blockDim.x + threadIdx.x;
    const int PL = NV * 256;
    int path = gidx / PL;
    int idx = gidx - path * PL;
    int q = idx & 255, y = idx >> 8;
    const int L = (path == 0) ? 2 : 3;
    int t = threadIdx.x;
    if (t < 256) sw1[t] = fa.w1[path][t];
    if (t < 16) sb1[t] = fa.b1[path][t];
    for (int i = t; i < L * 64; i += 256) sw2[i] = fa.w2[path][i];
    if (t < L) sb2[t] = fa.b2[path][t];
    __syncthreads();
    if (path == 0)
        ftconv4_impl<2>(fa.p2[0], sw1, sb1, sw2, sb2, fa.A[0], fa.att[0],
                        fa.deg[0], fa.diag[0], q, y);
    else
        ftconv4_impl<3>(fa.p2[1], sw1, sb1, sw2, sb2, fa.A[1], fa.att[1],
                        fa.deg[1], fa.diag[1], q, y);
}

// ---- dinv from accumulated deg/diag ----
__global__ void dinv_fix(const float* __restrict__ deg, const float* __restrict__ diag,
                         float* __restrict__ dv, int n) {
    int i = blockIdx.x * blockDim.x + threadIdx.x;
    if (i < n) {
        float d = deg[i];
        if (diag[i] == 0.0f) d += 1.0f;
        dv[i] = d > 0.0f ? rsqrtf(d) : 0.0f;
    }
}

// ---- scaled max-merge + row-sum/dinv (float4: one float4 per thread per row) ----
__global__ void emax_dinv(const float* __restrict__ a, const float* __restrict__ dva,
                          const float* __restrict__ b, const float* __restrict__ dvb,
                          float* __restrict__ o, float* __restrict__ dv) {
    int row = blockIdx.x;
    float dar = dva[row], dbr = dvb[row];
    __shared__ float sh[256];
    __shared__ float sdiag;
    int j0 = threadIdx.x << 2;
    float4 va = *(const float4*)&a[(size_t)row * NV + j0];
    float4 vb = *(const float4*)&b[(size_t)row * NV + j0];
    float4 da = *(const float4*)&dva[j0];
    float4 db = *(const float4*)&dvb[j0];
    // diag fill (fill=1 when zero) applies only at j==row
    if (j0 <= row && row < j0 + 4) {
        float* pa = &va.x;
        float* pb = &vb.x;
        int sel = row - j0;
        if (pa[sel] == 0.0f) pa[sel] = 1.0f;
        if (pb[sel] == 0.0f) pb[sel] = 1.0f;
    }
    float4 v;
    v.x = fmaxf(va.x * dar * da.x, vb.x * dbr * db.x);
    v.y = fmaxf(va.y * dar * da.y, vb.y * dbr * db.y);
    v.z = fmaxf(va.z * dar * da.z, vb.z * dbr * db.z);
    v.w = fmaxf(va.w * dar * da.w, vb.w * dbr * db.w);
    *(float4*)&o[(size_t)row * NV + j0] = v;
    if (j0 <= row && row < j0 + 4) {
        const float* pv = &v.x;
        sdiag = pv[row - j0];
    }
    sh[threadIdx.x] = (v.x + v.y) + (v.z + v.w);
    __syncthreads();
    for (int off = 128; off > 0; off >>= 1) {
        if (threadIdx.x < off) sh[threadIdx.x] += sh[threadIdx.x + off];
        __syncthreads();
    }
    if (threadIdx.x == 0) {
        float d = sh[0];
        if (sdiag == 0.0f) d += 1.0f;
        dv[row] = d > 0.0f ? rsqrtf(d) : 0.0f;
    }
}

// ---------------- tf32 GEMM: dv computed in prologue from deg/diag; norm fused ----
__device__ __forceinline__ void fix_scale4(float4& v, int row, int kc, float dvr,
                                           const float* __restrict__ dv) {
    float4 dk = *(const float4*)&dv[kc];
    float* p = &v.x;
#pragma unroll
    for (int q = 0; q < 4; q++)
        if (row == kc + q && p[q] == 0.0f) p[q] = 1.0f;
    v.x *= dvr * dk.x; v.y *= dvr * dk.y; v.z *= dvr * dk.z; v.w *= dvr * dk.w;
}

__global__ void __launch_bounds__(256) tf32gemm_s(GemS g) {
    const float* __restrict__ A = g.A[blockIdx.z];
    const float* __restrict__ B = g.B[blockIdx.z];
    float* __restrict__ C = g.C[blockIdx.z];
    const float* __restrict__ degIn = g.degIn[blockIdx.z];
    const float* __restrict__ diagIn = g.diagIn[blockIdx.z];
    float* __restrict__ deg = g.deg[blockIdx.z];
    float* __restrict__ diag = g.diag[blockIdx.z];
    const int Nn = NV, K = NV;

    __shared__ float As[2][16][136];
    __shared__ float Bs[2][16][72];
    __shared__ __align__(16) float sdv[NV];

    const int tid = threadIdx.x;
    const int lane = tid & 31;
    const int wid = tid >> 5;
    const int wr = wid & 3;
    const int wc = wid >> 2;
    const int m0 = blockIdx.y * 128;
    const int n0 = blockIdx.x * 64;

    for (int i = tid; i < NV; i += 256) {
        float d = degIn[i];
        if (diagIn[i] == 0.0f) d += 1.0f;
        sdv[i] = d > 0.0f ? rsqrtf(d) : 0.0f;
    }
    __syncthreads();

    float acc[2][4][4];
#pragma unroll
    for (int mi = 0; mi < 2; mi++)
#pragma unroll
        for (int ni = 0; ni < 4; ni++)
#pragma unroll
            for (int r = 0; r < 4; r++) acc[mi][ni][r] = 0.0f;

    const int ar = tid >> 2;
    const int ac4 = (tid & 3) << 2;
    const int bk = tid >> 4;
    const int bn4 = (tid & 15) << 2;
    const int rowA0 = m0 + ar, rowA1 = m0 + 64 + ar;
    const float dvr0 = sdv[rowA0], dvr1 = sdv[rowA1];

    float4 av0, av1, bv;
    const int T = K >> 4;

    av0 = *(const float4*)&A[(size_t)rowA0 * K + ac4];
    av1 = *(const float4*)&A[(size_t)rowA1 * K + ac4];
    bv  = *(const float4*)&B[(size_t)bk * Nn + n0 + bn4];
    fix_scale4(av0, rowA0, ac4, dvr0, sdv);
    fix_scale4(av1, rowA1, ac4, dvr1, sdv);

    As[0][ac4 + 0][ar] = __uint_as_float(f2tf(av0.x));
    As[0][ac4 + 1][ar] = __uint_as_float(f2tf(av0.y));
    As[0][ac4 + 2][ar] = __uint_as_float(f2tf(av0.z));
    As[0][ac4 + 3][ar] = __uint_as_float(f2tf(av0.w));
    As[0][ac4 + 0][ar + 64] = __uint_as_float(f2tf(av1.x));
    As[0][ac4 + 1][ar + 64] = __uint_as_float(f2tf(av1.y));
    As[0][ac4 + 2][ar + 64] = __uint_as_float(f2tf(av1.z));
    As[0][ac4 + 3][ar + 64] = __uint_as_float(f2tf(av1.w));
    {
        float4 bt;
        bt.x = __uint_as_float(f2tf(bv.x));
        bt.y = __uint_as_float(f2tf(bv.y));
        bt.z = __uint_as_float(f2tf(bv.z));
        bt.w = __uint_as_float(f2tf(bv.w));
        *(float4*)&Bs[0][bk][bn4] = bt;
    }
    __syncthreads();

    for (int t = 0; t < T; t++) {
        int cur = t & 1;
        if (t + 1 < T) {
            int kb = (t + 1) << 4;
            av0 = *(const float4*)&A[(size_t)rowA0 * K + kb + ac4];
            av1 = *(const float4*)&A[(size_t)rowA1 * K + kb + ac4];
            bv  = *(const float4*)&B[(size_t)(kb + bk) * Nn + n0 + bn4];
            fix_scale4(av0, rowA0, kb + ac4, dvr0, sdv);
            fix_scale4(av1, rowA1, kb + ac4, dvr1, sdv);
        }
#pragma unroll
        for (int ks = 0; ks < 2; ks++) {
            const int k0 = ks * 8;
            uint32_t a[2][4], b[4][2];
            const int kl = k0 + (lane & 3);
            const int rl = lane >> 2;
#pragma unroll
            for (int mi = 0; mi < 2; mi++) {
                int m = wr * 32 + mi * 16 + rl;
                a[mi][0] = __float_as_uint(As[cur][kl][m]);
                a[mi][1] = __float_as_uint(As[cur][kl][m + 8]);
                a[mi][2] = __float_as_uint(As[cur][kl + 4][m]);
                a[mi][3] = __float_as_uint(As[cur][kl + 4][m + 8]);
            }
#pragma unroll
            for (int ni = 0; ni < 4; ni++) {
                int n = wc * 32 + ni * 8 + rl;
                b[ni][0] = __float_as_uint(Bs[cur][kl][n]);
                b[ni][1] = __float_as_uint(Bs[cur][kl + 4][n]);
            }
#pragma unroll
            for (int mi = 0; mi < 2; mi++)
#pragma unroll
                for (int ni = 0; ni < 4; ni++) {
                    asm volatile(
                        "mma.sync.aligned.m16n8k8.row.col.f32.tf32.tf32.f32 "
                        "{%0,%1,%2,%3}, {%4,%5,%6,%7}, {%8,%9}, {%0,%1,%2,%3};"
                        : "+f"(acc[mi][ni][0]), "+f"(acc[mi][ni][1]),
                          "+f"(acc[mi][ni][2]), "+f"(acc[mi][ni][3])
                        : "r"(a[mi][0]), "r"(a[mi][1]), "r"(a[mi][2]), "r"(a[mi][3]),
                          "r"(b[ni][0]), "r"(b[ni][1]));
                }
        }
        if (t + 1 < T) {
            int nxt = (t + 1) & 1;
            As[nxt][ac4 + 0][ar] = __uint_as_float(f2tf(av0.x));
            As[nxt][ac4 + 1][ar] = __uint_as_float(f2tf(av0.y));
            As[nxt][ac4 + 2][ar] = __uint_as_float(f2tf(av0.z));
            As[nxt][ac4 + 3][ar] = __uint_as_float(f2tf(av0.w));
            As[nxt][ac4 + 0][ar + 64] = __uint_as_float(f2tf(av1.x));
            As[nxt][ac4 + 1][ar + 64] = __uint_as_float(f2tf(av1.y));
            As[nxt][ac4 + 2][ar + 64] = __uint_as_float(f2tf(av1.z));
            As[nxt][ac4 + 3][ar + 64] = __uint_as_float(f2tf(av1.w));
            float4 bt;
            bt.x = __uint_as_float(f2tf(bv.x));
            bt.y = __uint_as_float(f2tf(bv.y));
            bt.z = __uint_as_float(f2tf(bv.z));
            bt.w = __uint_as_float(f2tf(bv.w));
            *(float4*)&Bs[nxt][bk][bn4] = bt;
            __syncthreads();
        }
    }

    const int rl = lane >> 2;
#pragma unroll
    for (int mi = 0; mi < 2; mi++) {
        int row = m0 + wr * 32 + mi * 16 + rl;
#pragma unroll
        for (int ni = 0; ni < 4; ni++) {
            int col = n0 + wc * 32 + ni * 8 + ((lane & 3) << 1);
            if (row == col) diag[row] = acc[mi][ni][0];
            if (row == col + 1) diag[row] = acc[mi][ni][1];
            if (row + 8 == col) diag[row + 8] = acc[mi][ni][2];
            if (row + 8 == col + 1) diag[row + 8] = acc[mi][ni][3];
            *(float2*)&C[(size_t)row * Nn + col] = make_float2(acc[mi][ni][0], acc[mi][ni][1]);
            *(float2*)&C[(size_t)(row + 8) * Nn + col] = make_float2(acc[mi][ni][2], acc[mi][ni][3]);
        }
    }
    float rs[4] = {0.0f, 0.0f, 0.0f, 0.0f};
#pragma unroll
    for (int mi = 0; mi < 2; mi++)
#pragma unroll
        for (int ni = 0; ni < 4; ni++) {
            rs[mi * 2 + 0] += acc[mi][ni][0] + acc[mi][ni][1];
            rs[mi * 2 + 1] += acc[mi][ni][2] + acc[mi][ni][3];
        }
#pragma unroll
    for (int q = 0; q < 4; q++) {
        rs[q] += __shfl_xor_sync(0xFFFFFFFF, rs[q], 1);
        rs[q] += __shfl_xor_sync(0xFFFFFFFF, rs[q], 2);
    }
    if ((lane & 3) == 0) {
        int rbase = m0 + wr * 32 + rl;
        atomicAdd(&deg[rbase], rs[0]);
        atomicAdd(&deg[rbase + 8], rs[1]);
        atomicAdd(&deg[rbase + 16], rs[2]);
        atomicAdd(&deg[rbase + 24], rs[3]);
    }
}

// plain fp32 64x64 tile GEMM; optional bias+relu applied to A-operand on load.
__global__ void sgemm64(const float* __restrict__ A, const float* __restrict__ B,
                        float* __restrict__ C, int M, int Nn, int K,
                        const float* __restrict__ abias) {
    __shared__ float As[16][64];
    __shared__ float Bs[16][64];
    int tx = threadIdx.x, ty = threadIdx.y;
    int tid = ty * 16 + tx;
    int m0 = blockIdx.y * 64, n0 = blockIdx.x * 64;
    float acc[4][4];
#pragma unroll
    for (int i = 0; i < 4; i++)
#pragma unroll
        for (int j = 0; j < 4; j++) acc[i][j] = 0.0f;
    int la_r = tid / 16, la_k = tid % 16;
    int lb_k = tid / 64, lb_n = tid % 64;
    for (int k0 = 0; k0 < K; k0 += 16) {
#pragma unroll
        for (int r = 0; r < 4; r++) {
            float v = A[(size_t)(m0 + la_r + 16 * r) * K + k0 + la_k];
            if (abias != nullptr) v = fmaxf(v + abias[k0 + la_k], 0.0f);
            As[la_k][la_r + 16 * r] = v;
        }
#pragma unroll
        for (int r = 0; r < 4; r++) {
            int kk = lb_k + 4 * r;
            Bs[kk][lb_n] = (n0 + lb_n < Nn) ? B[(size_t)(k0 + kk) * Nn + n0 + lb_n] : 0.0f;
        }
        __syncthreads();
#pragma unroll
        for (int k = 0; k < 16; k++) {
            float a[4], b[4];
#pragma unroll
            for (int i = 0; i < 4; i++) a[i] = As[k][ty * 4 + i];
#pragma unroll
            for (int j = 0; j < 4; j++) b[j] = Bs[k][tx * 4 + j];
#pragma unroll
            for (int i = 0; i < 4; i++)
#pragma unroll
                for (int j = 0; j < 4; j++) acc[i][j] += a[i] * b[j];
        }
        __syncthreads();
    }
#pragma unroll
    for (int i = 0; i < 4; i++) {
        int row = m0 + ty * 4 + i;
#pragma unroll
        for (int j = 0; j < 4; j++) {
            int col = n0 + tx * 4 + j;
            if (col < Nn) C[(size_t)row * Nn + col] = acc[i][j];
        }
    }
}

// split-K fp32 GEMM with fused gcn-norm on A: C += (Dv fix(A) Dv) @ B.
__global__ void sgemmKS(const float* __restrict__ A, const float* __restrict__ dv,
                        const float* __restrict__ B, float* __restrict__ C,
                        int Nn, int K, int KS, const float* __restrict__ bias) {
    __shared__ float As[16][64];
    __shared__ float Bs[16][64];
    int tx = threadIdx.x, ty = threadIdx.y;
    int tid = ty * 16 + tx;
    int m0 = blockIdx.y * 64;
    int kLen = K / KS;
    int kStart = blockIdx.x * kLen;
    float acc[4][4];
#pragma unroll
    for (int i = 0; i < 4; i++)
#pragma unroll
        for (int j = 0; j < 4; j++) acc[i][j] = 0.0f;
    int la_r = tid / 16, la_k = tid % 16;
    int lb_k = tid / 64, lb_n = tid % 64;
    for (int k0 = kStart; k0 < kStart + kLen; k0 += 16) {
#pragma unroll
        for (int r = 0; r < 4; r++) {
            int row = m0 + la_r + 16 * r;
            int kc = k0 + la_k;
            float v = A[(size_t)row * K + kc];
            if (row == kc && v == 0.0f) v = 1.0f;
            As[la_k][la_r + 16 * r] = v * dv[row] * dv[kc];
        }
#pragma unroll
        for (int r = 0; r < 4; r++) {
            int kk = lb_k + 4 * r;
            Bs[kk][lb_n] = (lb_n < Nn) ? B[(size_t)(k0 + kk) * Nn + lb_n] : 0.0f;
        }
        __syncthreads();
#pragma unroll
        for (int k = 0; k < 16; k++) {
            float a[4], b[4];
#pragma unroll
            for (int i = 0; i < 4; i++) a[i] = As[k][ty * 4 + i];
#pragma unroll
            for (int j = 0; j < 4; j++) b[j] = Bs[k][tx * 4 + j];
#pragma unroll
            for (int i = 0; i < 4; i++)
#pragma unroll
                for (int j = 0; j < 4; j++) acc[i][j] += a[i] * b[j];
        }
        __syncthreads();
    }
#pragma unroll
    for (int i = 0; i < 4; i++) {
        int row = m0 + ty * 4 + i;
#pragma unroll
        for (int j = 0; j < 4; j++) {
            int col = tx * 4 + j;
            if (col < Nn) {
                float v = acc[i][j];
                if (bias != nullptr && kStart == 0) v += bias[col];
                atomicAdd(&C[(size_t)row * Nn + col], v);
            }
        }
    }
}

// ---------------- host orchestration ----------------

extern "C" void kernel_launch(void* const* d_in, const int* in_sizes, int n_in,
                              void* d_out, int out_size) {
    const float* x = (const float*)d_in[0];
    const int* edges[5];
    for (int i = 0; i < 5; i++) edges[i] = (const int*)d_in[1 + i];
    const float* pbp[2][8];
    for (int b = 0; b < 2; b++)
        for (int i = 0; i < 8; i++) pbp[b][i] = (const float*)d_in[6 + b * 8 + i];
    const float* w1    = (const float*)d_in[22];
    const float* bias1 = (const float*)d_in[23];
    const float* w2    = (const float*)d_in[24];
    const float* bias2 = (const float*)d_in[25];
    float* out = (float*)d_out;

    float *A_, *p1_, *p2_, *att_, *M_, *Mt_, *An_, *dinv_, *deg_, *diag_, *XW_, *H_, *HW_;
    cudaGetSymbolAddress((void**)&A_,    g_A);
    cudaGetSymbolAddress((void**)&p1_,   g_p1);
    cudaGetSymbolAddress((void**)&p2_,   g_p2);
    cudaGetSymbolAddress((void**)&att_,  g_att);
    cudaGetSymbolAddress((void**)&M_,    g_M);
    cudaGetSymbolAddress((void**)&Mt_,   g_Mt);
    cudaGetSymbolAddress((void**)&An_,   g_An);
    cudaGetSymbolAddress((void**)&dinv_, g_dinv);
    cudaGetSymbolAddress((void**)&deg_,  g_deg);
    cudaGetSymbolAddress((void**)&diag_, g_diag);
    cudaGetSymbolAddress((void**)&XW_,   g_XW);
    cudaGetSymbolAddress((void**)&H_,    g_H);
    cudaGetSymbolAddress((void**)&HW_,   g_HW);

    const size_t PLANE = (size_t)NV * NV;
    dim3 blk16(16, 16);

    float* Ab[2]   = { A_,   A_   + 3 * PLANE };
    float* p1b[2]  = { p1_,  p1_  + (size_t)16 * 512 * 512 };
    float* p2b[2]  = { p2_,  p2_  + (size_t)4 * 257 * 257 };
    float* attb[2] = { att_, att_ + 3 * PLANE };
    float* Mb[2]   = { M_,   M_   + PLANE };
    float* Mtb[2]  = { Mt_,  Mt_  + PLANE };

    // -------- setup --------
    cudaMemsetAsync(A_, 0, 6 * PLANE * sizeof(float), 0);
    sgemm64<<<dim3(1, NV / 64), blk16>>>(x, w1, XW_, NV, HIDD, EMBD, nullptr);

    // -------- scatter all 5 edge lists (also zeros deg, H, out) --------
    Sc5 sc;
    sc.e[0] = edges[0]; sc.A[0] = Ab[0];
    sc.e[1] = edges[1]; sc.A[1] = Ab[0] + PLANE;
    sc.e[2] = edges[2]; sc.A[2] = Ab[1];
    sc.e[3] = edges[3]; sc.A[3] = Ab[1] + PLANE;
    sc.e[4] = edges[4]; sc.A[4] = Ab[1] + 2 * PLANE;
    sc.degz = deg_;
    sc.Hz = H_;
    sc.outz = out;
    scatter_all<<<dim3((NE + 255) / 256, 5), 256>>>(sc);

    // -------- conv encoder (both paths batched) --------
    PathPtrs c1 = {{Ab[0], Ab[1]}, {pbp[0][0], pbp[1][0]}, {pbp[0][1], pbp[1][1]}, {p1b[0], p1b[1]}};
    conv1mma_both<<<dim3(32, 32, 2), blk16>>>(c1);

    PathPtrs c2 = {{p1b[0], p1b[1]}, {pbp[0][2], pbp[1][2]}, {pbp[0][3], pbp[1][3]}, {p2b[0], p2b[1]}};
    conv2pool_both<<<dim3(17, 17, 2), blk16>>>(c2);

    // fused tconv1 + tconv2 + sigmoid + adjacency multiply + att0 deg/diag (4-wide)
    FAtt fa;
    for (int p = 0; p < 2; p++) {
        fa.p2[p] = p2b[p];
        fa.w1[p] = pbp[p][4]; fa.b1[p] = pbp[p][5];
        fa.w2[p] = pbp[p][6]; fa.b2[p] = pbp[p][7];
        fa.A[p] = Ab[p]; fa.att[p] = attb[p];
        fa.deg[p] = deg_ + p * NV; fa.diag[p] = diag_ + p * NV;
    }
    ftconv_att_both<<<2 * NV, 256>>>(fa);

    // -------- M-chain, norms + dv computed inside GEMMs --------
    {
        GemS gs;
        gs.A[0] = attb[0];          gs.A[1] = attb[1];
        gs.B[0] = attb[0] + PLANE;  gs.B[1] = attb[1] + PLANE;
        gs.C[0] = Mtb[0];           gs.C[1] = Mtb[1];
        gs.degIn[0] = deg_;         gs.degIn[1] = deg_ + NV;
        gs.diagIn[0] = diag_;       gs.diagIn[1] = diag_ + NV;
        gs.deg[0] = deg_ + 2 * NV;  gs.deg[1] = deg_ + 3 * NV;
        gs.diag[0] = diag_ + 2 * NV; gs.diag[1] = diag_ + 3 * NV;
        tf32gemm_s<<<dim3(NV / 64, NV / 128, 2), 256>>>(gs);
    }
    {
        GemS gs;
        gs.A[0] = Mtb[1];
        gs.B[0] = attb[1] + 2 * PLANE;
        gs.C[0] = Mb[1];
        gs.degIn[0] = deg_ + 3 * NV;
        gs.diagIn[0] = diag_ + 3 * NV;
        gs.deg[0] = deg_ + 4 * NV;
        gs.diag[0] = diag_ + 4 * NV;
        gs.A[1] = gs.A[0]; gs.B[1] = gs.B[0]; gs.C[1] = gs.C[0];
        gs.degIn[1] = gs.degIn[0]; gs.diagIn[1] = gs.diagIn[0];
        gs.deg[1] = gs.deg[0]; gs.diag[1] = gs.diag[0];
        tf32gemm_s<<<dim3(NV / 64, NV / 128, 1), 256>>>(gs);
    }
    dinv_fix<<<(3 * NV + 255) / 256, 256>>>(deg_ + 2 * NV, diag_ + 2 * NV, dinv_ + 2 * NV, 3 * NV);

    // -------- scaled merge + final dinv --------
    emax_dinv<<<NV, 256>>>(Mtb[0], dinv_ + 2 * NV, Mb[1], dinv_ + 4 * NV, An_, dinv_ + 5 * NV);

    // -------- GCN layers, final norm fused into A-loads --------
    sgemmKS<<<dim3(8, NV / 64), blk16>>>(An_, dinv_ + 5 * NV, XW_, H_, HIDD, NV, 8, nullptr);
    sgemm64<<<dim3(1, NV / 64), blk16>>>(H_, w2, HW_, NV, REPD, HIDD, bias1);  // relu(H+bias1) @ w2
    sgemmKS<<<dim3(8, NV / 64), blk16>>>(An_, dinv_ + 5 * NV, HW_, out, REPD, NV, 8, bias2);
}

// round 14
// speedup vs baseline: 1.0661x; 1.0059x over previous
#include <cuda_runtime.h>
#include <math.h>
#include <stdint.h>

// Problem constants
#define NV 1024
#define NE 32768
#define EMBD 128
#define HIDD 64
#define REPD 32

// ---------------- scratch (static device globals) ----------------
__device__ float g_A[2][3][NV][NV];
__device__ float g_p1[2][16][512][512];
__device__ float g_p2[2][4][257][257];
__device__ float g_att[2][3][NV][NV];
__device__ float g_M[2][NV][NV];
__device__ float g_Mt[2][NV][NV];
__device__ float g_An[NV][NV];
__device__ float g_dinv[6][NV];
__device__ float g_deg[5][NV];
__device__ float g_diag[5][NV];
__device__ float g_XW[NV][HIDD];
__device__ float g_H[NV][HIDD];
__device__ float g_HW[NV][REPD];

// ---------------- param structs ----------------
struct Sc5 { const int* e[5]; float* A[5]; float* degz; float* Hz; float* outz; };
struct PathPtrs {
    const float* in[2]; const float* w[2]; const float* b[2]; float* out[2];
};
struct FAtt {
    const float* p2[2]; const float* w1[2]; const float* b1[2];
    const float* w2[2]; const float* b2[2]; const float* A[2]; float* att[2];
    float* deg[2]; float* diag[2];
};
struct GemS {
    const float* A[2]; const float* B[2]; float* C[2];
    const float* degIn[2]; const float* diagIn[2];
    float* deg[2]; float* diag[2];
};

// ---------------- helpers ----------------
__device__ __forceinline__ uint32_t f2tf(float f) {
    uint32_t r;
    asm("cvt.rna.tf32.f32 %0, %1;" : "=r"(r) : "f"(f));
    return r;
}

__device__ __forceinline__ float fsigmoid(float s) {
    return 1.0f / (1.0f + __expf(-s));
}

__device__ __forceinline__ void mma_tf32(float* c, const uint32_t* a, uint32_t b0, uint32_t b1) {
    asm volatile(
        "mma.sync.aligned.m16n8k8.row.col.f32.tf32.tf32.f32 "
        "{%0,%1,%2,%3}, {%4,%5,%6,%7}, {%8,%9}, {%0,%1,%2,%3};"
        : "+f"(c[0]), "+f"(c[1]), "+f"(c[2]), "+f"(c[3])
        : "r"(a[0]), "r"(a[1]), "r"(a[2]), "r"(a[3]), "r"(b0), "r"(b1));
}

// ---------------- kernels ----------------

__global__ void scatter_all(Sc5 s) {
    int j = blockIdx.y;
    int k = blockIdx.x * blockDim.x + threadIdx.x;
    if (j == 0 && k < 5 * NV) s.degz[k] = 0.0f;
    if (j == 1) s.Hz[k] = 0.0f;
    if (j == 2) s.Hz[32768 + k] = 0.0f;
    if (j == 3) s.outz[k] = 0.0f;
    if (k < NE) {
        const int* e = s.e[j];
        atomicAdd(&s.A[j][e[k] * NV + e[NE + k]], 1.0f);
    }
}

// ---- conv1 (3x3, pad1, L->16) + relu + maxpool2 via tf32 MMA (fp32-exact hi/lo) ----
template <int L>
__device__ __forceinline__ void conv1mma_impl(const float* __restrict__ A,
                                              const float* __restrict__ w,
                                              const float* __restrict__ b,
                                              float* __restrict__ p1,
                                              float* __restrict__ tile,
                                              float* __restrict__ whi,
                                              float* __restrict__ wlo,
                                              float* __restrict__ sb) {
    constexpr int KS = (L * 9 + 7) / 8;
    int t = threadIdx.y * 16 + threadIdx.x;
    int lane = t & 31, wid = t >> 5;

    for (int i = t; i < 512; i += 256) {
        int oc = i >> 5, k = i & 31;
        float wv = (k < L * 9) ? w[oc * L * 9 + k] : 0.0f;
        float hi = __uint_as_float(f2tf(wv));
        whi[i] = hi;
        wlo[i] = __uint_as_float(f2tf(wv - hi));
    }
    if (t < 16) sb[t] = b[t];

    int gy0 = blockIdx.y * 32 - 1, gx0 = blockIdx.x * 32 - 1;
    for (int l = 0; l < L; l++)
        for (int i = t; i < 34 * 34; i += 256) {
            int r = i / 34, c = i % 34;
            int gy = gy0 + r, gx = gx0 + c;
            tile[(l * 34 + r) * 36 + c] = (gy >= 0 && gy < NV && gx >= 0 && gx < NV)
                                              ? A[((size_t)l * NV + gy) * NV + gx] : 0.0f;
        }
    __syncthreads();

    uint32_t ahi[KS][4], alo[KS][4];
    int r0 = (lane >> 2) * 32, r1 = ((lane >> 2) + 8) * 32;
#pragma unroll
    for (int s = 0; s < KS; s++) {
        int c0 = 8 * s + (lane & 3);
        ahi[s][0] = __float_as_uint(whi[r0 + c0]);
        ahi[s][1] = __float_as_uint(whi[r1 + c0]);
        ahi[s][2] = __float_as_uint(whi[r0 + c0 + 4]);
        ahi[s][3] = __float_as_uint(whi[r1 + c0 + 4]);
        alo[s][0] = __float_as_uint(wlo[r0 + c0]);
        alo[s][1] = __float_as_uint(wlo[r1 + c0]);
        alo[s][2] = __float_as_uint(wlo[r0 + c0 + 4]);
        alo[s][3] = __float_as_uint(wlo[r1 + c0 + 4]);
    }

    int boff[KS][2];
#pragma unroll
    for (int s = 0; s < KS; s++)
#pragma unroll
        for (int h = 0; h < 2; h++) {
            int k = 8 * s + (lane & 3) + 4 * h;
            if (k >= L * 9) k = 0;
            int l = k / 9, r = k % 9;
            boff[s][h] = (l * 34 + r / 3) * 36 + (r % 3) + (lane >> 2);
        }

    for (int u = wid; u < 64; u += 8) {
        int py = u >> 2, ux = u & 3;
        int base0 = (2 * py) * 36 + 8 * ux;
        int base1 = base0 + 36;
        float acc0[4] = {0.f, 0.f, 0.f, 0.f};
        float acc1[4] = {0.f, 0.f, 0.f, 0.f};
#pragma unroll
        for (int s = 0; s < KS; s++) {
            uint32_t b00 = __float_as_uint(tile[boff[s][0] + base0]);
            uint32_t b01 = __float_as_uint(tile[boff[s][1] + base0]);
            mma_tf32(acc0, ahi[s], b00, b01);
            mma_tf32(acc0, alo[s], b00, b01);
            uint32_t b10 = __float_as_uint(tile[boff[s][0] + base1]);
            uint32_t b11 = __float_as_uint(tile[boff[s][1] + base1]);
            mma_tf32(acc1, ahi[s], b10, b11);
            mma_tf32(acc1, alo[s], b10, b11);
        }
        int oc0 = lane >> 2, oc1 = oc0 + 8;
        int ox = blockIdx.x * 16 + 4 * ux + (lane & 3);
        int oy = blockIdx.y * 16 + py;
        float m0 = fmaxf(fmaxf(acc0[0], acc0[1]), fmaxf(acc1[0], acc1[1]));
        float m1 = fmaxf(fmaxf(acc0[2], acc0[3]), fmaxf(acc1[2], acc1[3]));
        p1[((size_t)oc0 * 512 + oy) * 512 + ox] = fmaxf(m0 + sb[oc0], 0.0f);
        p1[((size_t)oc1 * 512 + oy) * 512 + ox] = fmaxf(m1 + sb[oc1], 0.0f);
    }
}

__global__ void __launch_bounds__(256) conv1mma_both(PathPtrs p) {
    __shared__ float tile[3 * 34 * 36];
    __shared__ float whi[512], wlo[512];
    __shared__ float sb[16];
    int path = blockIdx.z;
    if (path == 0)
        conv1mma_impl<2>(p.in[0], p.w[0], p.b[0], p.out[0], tile, whi, wlo, sb);
    else
        conv1mma_impl<3>(p.in[1], p.w[1], p.b[1], p.out[1], tile, whi, wlo, sb);
}

// ---- conv2 (3x3, pad2, 16->4) + relu + maxpool2 (stride-40 float2 LDS, best) ----
__global__ void conv2pool_both(PathPtrs pp) {
    __shared__ float tile[36 * 40];
    __shared__ float sw[576];
    __shared__ float sb[4];
    int path = blockIdx.z;
    const float* p1 = pp.in[path];
    float* p2 = pp.out[path];
    int tx = threadIdx.x, ty = threadIdx.y;
    int t = ty * 16 + tx;
    for (int i = t; i < 576; i += 256) sw[i] = pp.w[path][i];
    if (t < 4) sb[t] = pp.b[path][t];

    int gy0 = blockIdx.y * 32 - 2, gx0 = blockIdx.x * 32 - 2;

    int srow[6], scol[6], sok[6];
    float r[6];
#pragma unroll
    for (int s = 0; s < 6; s++) {
        int i = t + s * 256;
        srow[s] = i / 36; scol[s] = i % 36;
        sok[s] = (i < 1296);
    }
#pragma unroll
    for (int s = 0; s < 6; s++) {
        if (sok[s]) {
            int gy = gy0 + srow[s], gx = gx0 + scol[s];
            r[s] = (gy >= 0 && gy < 512 && gx >= 0 && gx < 512)
                       ? p1[(size_t)gy * 512 + gx] : 0.0f;
        }
    }

    float acc[4][2][2];
#pragma unroll
    for (int oc = 0; oc < 4; oc++)
#pragma unroll
        for (int py = 0; py < 2; py++)
#pragma unroll
            for (int px = 0; px < 2; px++) acc[oc][py][px] = 0.0f;

    __syncthreads();

    for (int ci = 0; ci < 16; ci++) {
#pragma unroll
        for (int s = 0; s < 6; s++)
            if (sok[s]) tile[srow[s] * 40 + scol[s]] = r[s];
        __syncthreads();
        if (ci < 15) {
#pragma unroll
            for (int s = 0; s < 6; s++) {
                if (sok[s]) {
                    int gy = gy0 + srow[s], gx = gx0 + scol[s];
                    r[s] = (gy >= 0 && gy < 512 && gx >= 0 && gx < 512)
                               ? p1[((size_t)(ci + 1) * 512 + gy) * 512 + gx] : 0.0f;
                }
            }
        }
        float patch[4][4];
#pragma unroll
        for (int rw = 0; rw < 4; rw++) {
            const float2* rp = (const float2*)&tile[(2 * ty + rw) * 40 + 2 * tx];
            float2 a = rp[0], b = rp[1];
            patch[rw][0] = a.x; patch[rw][1] = a.y;
            patch[rw][2] = b.x; patch[rw][3] = b.y;
        }
#pragma unroll
        for (int oc = 0; oc < 4; oc++)
#pragma unroll
            for (int ky = 0; ky < 3; ky++)
#pragma unroll
                for (int kx = 0; kx < 3; kx++) {
                    float wv = sw[((oc * 16 + ci) * 3 + ky) * 3 + kx];
                    acc[oc][0][0] += wv * patch[ky][kx];
                    acc[oc][0][1] += wv * patch[ky][kx + 1];
                    acc[oc][1][0] += wv * patch[ky + 1][kx];
                    acc[oc][1][1] += wv * patch[ky + 1][kx + 1];
                }
        __syncthreads();
    }
    int x = blockIdx.x * 16 + tx, y = blockIdx.y * 16 + ty;
    if (x < 257 && y < 257) {
#pragma unroll
        for (int oc = 0; oc < 4; oc++) {
            float m = fmaxf(fmaxf(acc[oc][0][0], acc[oc][0][1]),
                            fmaxf(acc[oc][1][0], acc[oc][1][1])) + sb[oc];
            p2[((size_t)oc * 257 + y) * 257 + x] = fmaxf(m, 0.0f);
        }
    }
}

// ---- fused tconv1 + tconv2 + sigmoid + crop + adjacency multiply + att0 deg/diag ----
template <int L>
__device__ __forceinline__ void ftconv4_impl(const float* __restrict__ p2,
                                             const float* __restrict__ sw1,
                                             const float* __restrict__ sb1,
                                             const float* __restrict__ sw2,
                                             const float* __restrict__ sb2,
                                             const float* __restrict__ A,
                                             float* __restrict__ att,
                                             float* __restrict__ deg,
                                             float* __restrict__ diag,
                                             int q, int y) {
    int ky2 = (y + 1) & 1;
    int iy1 = (y - 1 + ky2) >> 1;
    int ky1 = (iy1 + 1) & 1;
    int iy0 = (iy1 - 1 + ky1) >> 1;

    float p[4];
#pragma unroll
    for (int cj = 0; cj < 4; cj++) p[cj] = p2[((size_t)cj * 257 + iy0) * 257 + q];

    float tA[16], tB[16];
#pragma unroll
    for (int ci = 0; ci < 16; ci++) {
        float sA = sb1[ci], sB = sb1[ci];
#pragma unroll
        for (int cj = 0; cj < 4; cj++) {
            int base = ((ci * 4 + cj) * 2 + ky1) * 2;
            sA += sw1[base + 1] * p[cj];
            sB += sw1[base + 0] * p[cj];
        }
        tA[ci] = fmaxf(sA, 0.0f);
        tB[ci] = fmaxf(sB, 0.0f);
    }

    float d0 = 0.f, d1 = 0.f, d2 = 0.f, d3 = 0.f;
#pragma unroll
    for (int l = 0; l < L; l++) {
        float s0A = sb2[l], s1A = sb2[l], s0B = sb2[l], s1B = sb2[l];
#pragma unroll
        for (int ci = 0; ci < 16; ci++) {
            int base = ((l * 16 + ci) * 2 + ky2) * 2;
            float w1v = sw2[base + 1], w0v = sw2[base + 0];
            s0A += w1v * tA[ci]; s1A += w0v * tA[ci];
            s0B += w1v * tB[ci]; s1B += w0v * tB[ci];
        }
        float g0 = fsigmoid(s0A);
        float g1 = fsigmoid(s1A);
        float g2 = fsigmoid(s0B);
        float g3 = fsigmoid(s1B);
        size_t off = (size_t)l * NV * NV + (size_t)y * NV + 4 * q;
        float4 a = *(const float4*)&A[off];
        float4 v = make_float4(a.x * g0, a.y * g1, a.z * g2, a.w * g3);
        *(float4*)&att[off] = v;
        if (l == 0) { d0 = v.x; d1 = v.y; d2 = v.z; d3 = v.w; }
    }

    float s = (d0 + d1) + (d2 + d3);
#pragma unroll
    for (int o = 16; o > 0; o >>= 1) s += __shfl_xor_sync(0xFFFFFFFF, s, o);
    if ((threadIdx.x & 31) == 0) atomicAdd(&deg[y], s);
    if ((y >> 2) == q) {
        int sel = y & 3;
        diag[y] = sel == 0 ? d0 : sel == 1 ? d1 : sel == 2 ? d2 : d3;
    }
}

__global__ void ftconv_att_both(FAtt fa) {
    __shared__ float sw1[256], sb1[16], sw2[192], sb2[3];
    int gidx = blockIdx.x * blockDim.x + threadIdx.x;
    const int PL = NV * 256;
    int path = gidx / PL;
    int idx = gidx - path * PL;
    int q = idx & 255, y = idx >> 8;
    const int L = (path == 0) ? 2 : 3;
    int t = threadIdx.x;
    if (t < 256) sw1[t] = fa.w1[path][t];
    if (t < 16) sb1[t] = fa.b1[path][t];
    for (int i = t; i < L * 64; i += 256) sw2[i] = fa.w2[path][i];
    if (t < L) sb2[t] = fa.b2[path][t];
    __syncthreads();
    if (path == 0)
        ftconv4_impl<2>(fa.p2[0], sw1, sb1, sw2, sb2, fa.A[0], fa.att[0],
                        fa.deg[0], fa.diag[0], q, y);
    else
        ftconv4_impl<3>(fa.p2[1], sw1, sb1, sw2, sb2, fa.A[1], fa.att[1],
                        fa.deg[1], fa.diag[1], q, y);
}

// ---- dinv from accumulated deg/diag ----
__global__ void dinv_fix(const float* __restrict__ deg, const float* __restrict__ diag,
                         float* __restrict__ dv, int n) {
    int i = blockIdx.x * blockDim.x + threadIdx.x;
    if (i < n) {
        float d = deg[i];
        if (diag[i] == 0.0f) d += 1.0f;
        dv[i] = d > 0.0f ? rsqrtf(d) : 0.0f;
    }
}

// ---- scaled max-merge + row-sum/dinv (float4) ----
__global__ void emax_dinv(const float* __restrict__ a, const float* __restrict__ dva,
                          const float* __restrict__ b, const float* __restrict__ dvb,
                          float* __restrict__ o, float* __restrict__ dv) {
    int row = blockIdx.x;
    float dar = dva[row], dbr = dvb[row];
    __shared__ float sh[256];
    __shared__ float sdiag;
    int j0 = threadIdx.x << 2;
    float4 va = *(const float4*)&a[(size_t)row * NV + j0];
    float4 vb = *(const float4*)&b[(size_t)row * NV + j0];
    float4 da = *(const float4*)&dva[j0];
    float4 db = *(const float4*)&dvb[j0];
    if (j0 <= row && row < j0 + 4) {
        float* pa = &va.x;
        float* pb = &vb.x;
        int sel = row - j0;
        if (pa[sel] == 0.0f) pa[sel] = 1.0f;
        if (pb[sel] == 0.0f) pb[sel] = 1.0f;
    }
    float4 v;
    v.x = fmaxf(va.x * dar * da.x, vb.x * dbr * db.x);
    v.y = fmaxf(va.y * dar * da.y, vb.y * dbr * db.y);
    v.z = fmaxf(va.z * dar * da.z, vb.z * dbr * db.z);
    v.w = fmaxf(va.w * dar * da.w, vb.w * dbr * db.w);
    *(float4*)&o[(size_t)row * NV + j0] = v;
    if (j0 <= row && row < j0 + 4) {
        const float* pv = &v.x;
        sdiag = pv[row - j0];
    }
    sh[threadIdx.x] = (v.x + v.y) + (v.z + v.w);
    __syncthreads();
    for (int off = 128; off > 0; off >>= 1) {
        if (threadIdx.x < off) sh[threadIdx.x] += sh[threadIdx.x + off];
        __syncthreads();
    }
    if (threadIdx.x == 0) {
        float d = sh[0];
        if (sdiag == 0.0f) d += 1.0f;
        dv[row] = d > 0.0f ? rsqrtf(d) : 0.0f;
    }
}

// ---------------- tf32 GEMM: dv prologue; norm fused; raw-fp32 tf32 operands ----
// (mma.sync reads operand regs as tf32 -> HW truncation; cvt.rna stream removed)
__device__ __forceinline__ void fix_scale4(float4& v, int row, int kc, float dvr,
                                           const float* __restrict__ dv) {
    float4 dk = *(const float4*)&dv[kc];
    float* p = &v.x;
#pragma unroll
    for (int q = 0; q < 4; q++)
        if (row == kc + q && p[q] == 0.0f) p[q] = 1.0f;
    v.x *= dvr * dk.x; v.y *= dvr * dk.y; v.z *= dvr * dk.z; v.w *= dvr * dk.w;
}

__global__ void __launch_bounds__(256) tf32gemm_s(GemS g) {
    const float* __restrict__ A = g.A[blockIdx.z];
    const float* __restrict__ B = g.B[blockIdx.z];
    float* __restrict__ C = g.C[blockIdx.z];
    const float* __restrict__ degIn = g.degIn[blockIdx.z];
    const float* __restrict__ diagIn = g.diagIn[blockIdx.z];
    float* __restrict__ deg = g.deg[blockIdx.z];
    float* __restrict__ diag = g.diag[blockIdx.z];
    const int Nn = NV, K = NV;

    __shared__ float As[2][16][136];
    __shared__ float Bs[2][16][72];
    __shared__ __align__(16) float sdv[NV];

    const int tid = threadIdx.x;
    const int lane = tid & 31;
    const int wid = tid >> 5;
    const int wr = wid & 3;
    const int wc = wid >> 2;
    const int m0 = blockIdx.y * 128;
    const int n0 = blockIdx.x * 64;

    for (int i = tid; i < NV; i += 256) {
        float d = degIn[i];
        if (diagIn[i] == 0.0f) d += 1.0f;
        sdv[i] = d > 0.0f ? rsqrtf(d) : 0.0f;
    }
    __syncthreads();

    float acc[2][4][4];
#pragma unroll
    for (int mi = 0; mi < 2; mi++)
#pragma unroll
        for (int ni = 0; ni < 4; ni++)
#pragma unroll
            for (int r = 0; r < 4; r++) acc[mi][ni][r] = 0.0f;

    const int ar = tid >> 2;
    const int ac4 = (tid & 3) << 2;
    const int bk = tid >> 4;
    const int bn4 = (tid & 15) << 2;
    const int rowA0 = m0 + ar, rowA1 = m0 + 64 + ar;
    const float dvr0 = sdv[rowA0], dvr1 = sdv[rowA1];

    float4 av0, av1, bv;
    const int T = K >> 4;

    av0 = *(const float4*)&A[(size_t)rowA0 * K + ac4];
    av1 = *(const float4*)&A[(size_t)rowA1 * K + ac4];
    bv  = *(const float4*)&B[(size_t)bk * Nn + n0 + bn4];
    fix_scale4(av0, rowA0, ac4, dvr0, sdv);
    fix_scale4(av1, rowA1, ac4, dvr1, sdv);

    As[0][ac4 + 0][ar] = av0.x;
    As[0][ac4 + 1][ar] = av0.y;
    As[0][ac4 + 2][ar] = av0.z;
    As[0][ac4 + 3][ar] = av0.w;
    As[0][ac4 + 0][ar + 64] = av1.x;
    As[0][ac4 + 1][ar + 64] = av1.y;
    As[0][ac4 + 2][ar + 64] = av1.z;
    As[0][ac4 + 3][ar + 64] = av1.w;
    *(float4*)&Bs[0][bk][bn4] = bv;
    __syncthreads();

    for (int t = 0; t < T; t++) {
        int cur = t & 1;
        if (t + 1 < T) {
            int kb = (t + 1) << 4;
            av0 = *(const float4*)&A[(size_t)rowA0 * K + kb + ac4];
            av1 = *(const float4*)&A[(size_t)rowA1 * K + kb + ac4];
            bv  = *(const float4*)&B[(size_t)(kb + bk) * Nn + n0 + bn4];
            fix_scale4(av0, rowA0, kb + ac4, dvr0, sdv);
            fix_scale4(av1, rowA1, kb + ac4, dvr1, sdv);
        }
#pragma unroll
        for (int ks = 0; ks < 2; ks++) {
            const int k0 = ks * 8;
            uint32_t a[2][4], b[4][2];
            const int kl = k0 + (lane & 3);
            const int rl = lane >> 2;
#pragma unroll
            for (int mi = 0; mi < 2; mi++) {
                int m = wr * 32 + mi * 16 + rl;
                a[mi][0] = __float_as_uint(As[cur][kl][m]);
                a[mi][1] = __float_as_uint(As[cur][kl][m + 8]);
                a[mi][2] = __float_as_uint(As[cur][kl + 4][m]);
                a[mi][3] = __float_as_uint(As[cur][kl + 4][m + 8]);
            }
#pragma unroll
            for (int ni = 0; ni < 4; ni++) {
                int n = wc * 32 + ni * 8 + rl;
                b[ni][0] = __float_as_uint(Bs[cur][kl][n]);
                b[ni][1] = __float_as_uint(Bs[cur][kl + 4][n]);
            }
#pragma unroll
            for (int mi = 0; mi < 2; mi++)
#pragma unroll
                for (int ni = 0; ni < 4; ni++) {
                    asm volatile(
                        "mma.sync.aligned.m16n8k8.row.col.f32.tf32.tf32.f32 "
                        "{%0,%1,%2,%3}, {%4,%5,%6,%7}, {%8,%9}, {%0,%1,%2,%3};"
                        : "+f"(acc[mi][ni][0]), "+f"(acc[mi][ni][1]),
                          "+f"(acc[mi][ni][2]), "+f"(acc[mi][ni][3])
                        : "r"(a[mi][0]), "r"(a[mi][1]), "r"(a[mi][2]), "r"(a[mi][3]),
                          "r"(b[ni][0]), "r"(b[ni][1]));
                }
        }
        if (t + 1 < T) {
            int nxt = (t + 1) & 1;
            As[nxt][ac4 + 0][ar] = av0.x;
            As[nxt][ac4 + 1][ar] = av0.y;
            As[nxt][ac4 + 2][ar] = av0.z;
            As[nxt][ac4 + 3][ar] = av0.w;
            As[nxt][ac4 + 0][ar + 64] = av1.x;
            As[nxt][ac4 + 1][ar + 64] = av1.y;
            As[nxt][ac4 + 2][ar + 64] = av1.z;
            As[nxt][ac4 + 3][ar + 64] = av1.w;
            *(float4*)&Bs[nxt][bk][bn4] = bv;
            __syncthreads();
        }
    }

    const int rl = lane >> 2;
#pragma unroll
    for (int mi = 0; mi < 2; mi++) {
        int row = m0 + wr * 32 + mi * 16 + rl;
#pragma unroll
        for (int ni = 0; ni < 4; ni++) {
            int col = n0 + wc * 32 + ni * 8 + ((lane & 3) << 1);
            if (row == col) diag[row] = acc[mi][ni][0];
            if (row == col + 1) diag[row] = acc[mi][ni][1];
            if (row + 8 == col) diag[row + 8] = acc[mi][ni][2];
            if (row + 8 == col + 1) diag[row + 8] = acc[mi][ni][3];
            *(float2*)&C[(size_t)row * Nn + col] = make_float2(acc[mi][ni][0], acc[mi][ni][1]);
            *(float2*)&C[(size_t)(row + 8) * Nn + col] = make_float2(acc[mi][ni][2], acc[mi][ni][3]);
        }
    }
    float rs[4] = {0.0f, 0.0f, 0.0f, 0.0f};
#pragma unroll
    for (int mi = 0; mi < 2; mi++)
#pragma unroll
        for (int ni = 0; ni < 4; ni++) {
            rs[mi * 2 + 0] += acc[mi][ni][0] + acc[mi][ni][1];
            rs[mi * 2 + 1] += acc[mi][ni][2] + acc[mi][ni][3];
        }
#pragma unroll
    for (int q = 0; q < 4; q++) {
        rs[q] += __shfl_xor_sync(0xFFFFFFFF, rs[q], 1);
        rs[q] += __shfl_xor_sync(0xFFFFFFFF, rs[q], 2);
    }
    if ((lane & 3) == 0) {
        int rbase = m0 + wr * 32 + rl;
        atomicAdd(&deg[rbase], rs[0]);
        atomicAdd(&deg[rbase + 8], rs[1]);
        atomicAdd(&deg[rbase + 16], rs[2]);
        atomicAdd(&deg[rbase + 24], rs[3]);
    }
}

// plain fp32 64x64 tile GEMM; optional bias+relu applied to A-operand on load.
__global__ void sgemm64(const float* __restrict__ A, const float* __restrict__ B,
                        float* __restrict__ C, int M, int Nn, int K,
                        const float* __restrict__ abias) {
    __shared__ float As[16][64];
    __shared__ float Bs[16][64];
    int tx = threadIdx.x, ty = threadIdx.y;
    int tid = ty * 16 + tx;
    int m0 = blockIdx.y * 64, n0 = blockIdx.x * 64;
    float acc[4][4];
#pragma unroll
    for (int i = 0; i < 4; i++)
#pragma unroll
        for (int j = 0; j < 4; j++) acc[i][j] = 0.0f;
    int la_r = tid / 16, la_k = tid % 16;
    int lb_k = tid / 64, lb_n = tid % 64;
    for (int k0 = 0; k0 < K; k0 += 16) {
#pragma unroll
        for (int r = 0; r < 4; r++) {
            float v = A[(size_t)(m0 + la_r + 16 * r) * K + k0 + la_k];
            if (abias != nullptr) v = fmaxf(v + abias[k0 + la_k], 0.0f);
            As[la_k][la_r + 16 * r] = v;
        }
#pragma unroll
        for (int r = 0; r < 4; r++) {
            int kk = lb_k + 4 * r;
            Bs[kk][lb_n] = (n0 + lb_n < Nn) ? B[(size_t)(k0 + kk) * Nn + n0 + lb_n] : 0.0f;
        }
        __syncthreads();
#pragma unroll
        for (int k = 0; k < 16; k++) {
            float a[4], b[4];
#pragma unroll
            for (int i = 0; i < 4; i++) a[i] = As[k][ty * 4 + i];
#pragma unroll
            for (int j = 0; j < 4; j++) b[j] = Bs[k][tx * 4 + j];
#pragma unroll
            for (int i = 0; i < 4; i++)
#pragma unroll
                for (int j = 0; j < 4; j++) acc[i][j] += a[i] * b[j];
        }
        __syncthreads();
    }
#pragma unroll
    for (int i = 0; i < 4; i++) {
        int row = m0 + ty * 4 + i;
#pragma unroll
        for (int j = 0; j < 4; j++) {
            int col = n0 + tx * 4 + j;
            if (col < Nn) C[(size_t)row * Nn + col] = acc[i][j];
        }
    }
}

// split-K fp32 GEMM with fused gcn-norm on A: C += (Dv fix(A) Dv) @ B.
__global__ void sgemmKS(const float* __restrict__ A, const float* __restrict__ dv,
                        const float* __restrict__ B, float* __restrict__ C,
                        int Nn, int K, int KS, const float* __restrict__ bias) {
    __shared__ float As[16][64];
    __shared__ float Bs[16][64];
    int tx = threadIdx.x, ty = threadIdx.y;
    int tid = ty * 16 + tx;
    int m0 = blockIdx.y * 64;
    int kLen = K / KS;
    int kStart = blockIdx.x * kLen;
    float acc[4][4];
#pragma unroll
    for (int i = 0; i < 4; i++)
#pragma unroll
        for (int j = 0; j < 4; j++) acc[i][j] = 0.0f;
    int la_r = tid / 16, la_k = tid % 16;
    int lb_k = tid / 64, lb_n = tid % 64;
    for (int k0 = kStart; k0 < kStart + kLen; k0 += 16) {
#pragma unroll
        for (int r = 0; r < 4; r++) {
            int row = m0 + la_r + 16 * r;
            int kc = k0 + la_k;
            float v = A[(size_t)row * K + kc];
            if (row == kc && v == 0.0f) v = 1.0f;
            As[la_k][la_r + 16 * r] = v * dv[row] * dv[kc];
        }
#pragma unroll
        for (int r = 0; r < 4; r++) {
            int kk = lb_k + 4 * r;
            Bs[kk][lb_n] = (lb_n < Nn) ? B[(size_t)(k0 + kk) * Nn + lb_n] : 0.0f;
        }
        __syncthreads();
#pragma unroll
        for (int k = 0; k < 16; k++) {
            float a[4], b[4];
#pragma unroll
            for (int i = 0; i < 4; i++) a[i] = As[k][ty * 4 + i];
#pragma unroll
            for (int j = 0; j < 4; j++) b[j] = Bs[k][tx * 4 + j];
#pragma unroll
            for (int i = 0; i < 4; i++)
#pragma unroll
                for (int j = 0; j < 4; j++) acc[i][j] += a[i] * b[j];
        }
        __syncthreads();
    }
#pragma unroll
    for (int i = 0; i < 4; i++) {
        int row = m0 + ty * 4 + i;
#pragma unroll
        for (int j = 0; j < 4; j++) {
            int col = tx * 4 + j;
            if (col < Nn) {
                float v = acc[i][j];
                if (bias != nullptr && kStart == 0) v += bias[col];
                atomicAdd(&C[(size_t)row * Nn + col], v);
            }
        }
    }
}

// ---------------- host orchestration ----------------

extern "C" void kernel_launch(void* const* d_in, const int* in_sizes, int n_in,
                              void* d_out, int out_size) {
    const float* x = (const float*)d_in[0];
    const int* edges[5];
    for (int i = 0; i < 5; i++) edges[i] = (const int*)d_in[1 + i];
    const float* pbp[2][8];
    for (int b = 0; b < 2; b++)
        for (int i = 0; i < 8; i++) pbp[b][i] = (const float*)d_in[6 + b * 8 + i];
    const float* w1    = (const float*)d_in[22];
    const float* bias1 = (const float*)d_in[23];
    const float* w2    = (const float*)d_in[24];
    const float* bias2 = (const float*)d_in[25];
    float* out = (float*)d_out;

    float *A_, *p1_, *p2_, *att_, *M_, *Mt_, *An_, *dinv_, *deg_, *diag_, *XW_, *H_, *HW_;
    cudaGetSymbolAddress((void**)&A_,    g_A);
    cudaGetSymbolAddress((void**)&p1_,   g_p1);
    cudaGetSymbolAddress((void**)&p2_,   g_p2);
    cudaGetSymbolAddress((void**)&att_,  g_att);
    cudaGetSymbolAddress((void**)&M_,    g_M);
    cudaGetSymbolAddress((void**)&Mt_,   g_Mt);
    cudaGetSymbolAddress((void**)&An_,   g_An);
    cudaGetSymbolAddress((void**)&dinv_, g_dinv);
    cudaGetSymbolAddress((void**)&deg_,  g_deg);
    cudaGetSymbolAddress((void**)&diag_, g_diag);
    cudaGetSymbolAddress((void**)&XW_,   g_XW);
    cudaGetSymbolAddress((void**)&H_,    g_H);
    cudaGetSymbolAddress((void**)&HW_,   g_HW);

    const size_t PLANE = (size_t)NV * NV;
    dim3 blk16(16, 16);

    float* Ab[2]   = { A_,   A_   + 3 * PLANE };
    float* p1b[2]  = { p1_,  p1_  + (size_t)16 * 512 * 512 };
    float* p2b[2]  = { p2_,  p2_  + (size_t)4 * 257 * 257 };
    float* attb[2] = { att_, att_ + 3 * PLANE };
    float* Mb[2]   = { M_,   M_   + PLANE };
    float* Mtb[2]  = { Mt_,  Mt_  + PLANE };

    // -------- setup --------
    cudaMemsetAsync(A_, 0, 6 * PLANE * sizeof(float), 0);
    sgemm64<<<dim3(1, NV / 64), blk16>>>(x, w1, XW_, NV, HIDD, EMBD, nullptr);

    // -------- scatter all 5 edge lists (also zeros deg, H, out) --------
    Sc5 sc;
    sc.e[0] = edges[0]; sc.A[0] = Ab[0];
    sc.e[1] = edges[1]; sc.A[1] = Ab[0] + PLANE;
    sc.e[2] = edges[2]; sc.A[2] = Ab[1];
    sc.e[3] = edges[3]; sc.A[3] = Ab[1] + PLANE;
    sc.e[4] = edges[4]; sc.A[4] = Ab[1] + 2 * PLANE;
    sc.degz = deg_;
    sc.Hz = H_;
    sc.outz = out;
    scatter_all<<<dim3((NE + 255) / 256, 5), 256>>>(sc);

    // -------- conv encoder (both paths batched) --------
    PathPtrs c1 = {{Ab[0], Ab[1]}, {pbp[0][0], pbp[1][0]}, {pbp[0][1], pbp[1][1]}, {p1b[0], p1b[1]}};
    conv1mma_both<<<dim3(32, 32, 2), blk16>>>(c1);

    PathPtrs c2 = {{p1b[0], p1b[1]}, {pbp[0][2], pbp[1][2]}, {pbp[0][3], pbp[1][3]}, {p2b[0], p2b[1]}};
    conv2pool_both<<<dim3(17, 17, 2), blk16>>>(c2);

    // fused tconv1 + tconv2 + sigmoid + adjacency multiply + att0 deg/diag (4-wide)
    FAtt fa;
    for (int p = 0; p < 2; p++) {
        fa.p2[p] = p2b[p];
        fa.w1[p] = pbp[p][4]; fa.b1[p] = pbp[p][5];
        fa.w2[p] = pbp[p][6]; fa.b2[p] = pbp[p][7];
        fa.A[p] = Ab[p]; fa.att[p] = attb[p];
        fa.deg[p] = deg_ + p * NV; fa.diag[p] = diag_ + p * NV;
    }
    ftconv_att_both<<<2 * NV, 256>>>(fa);

    // -------- M-chain, norms + dv computed inside GEMMs --------
    {
        GemS gs;
        gs.A[0] = attb[0];          gs.A[1] = attb[1];
        gs.B[0] = attb[0] + PLANE;  gs.B[1] = attb[1] + PLANE;
        gs.C[0] = Mtb[0];           gs.C[1] = Mtb[1];
        gs.degIn[0] = deg_;         gs.degIn[1] = deg_ + NV;
        gs.diagIn[0] = diag_;       gs.diagIn[1] = diag_ + NV;
        gs.deg[0] = deg_ + 2 * NV;  gs.deg[1] = deg_ + 3 * NV;
        gs.diag[0] = diag_ + 2 * NV; gs.diag[1] = diag_ + 3 * NV;
        tf32gemm_s<<<dim3(NV / 64, NV / 128, 2), 256>>>(gs);
    }
    {
        GemS gs;
        gs.A[0] = Mtb[1];
        gs.B[0] = attb[1] + 2 * PLANE;
        gs.C[0] = Mb[1];
        gs.degIn[0] = deg_ + 3 * NV;
        gs.diagIn[0] = diag_ + 3 * NV;
        gs.deg[0] = deg_ + 4 * NV;
        gs.diag[0] = diag_ + 4 * NV;
        gs.A[1] = gs.A[0]; gs.B[1] = gs.B[0]; gs.C[1] = gs.C[0];
        gs.degIn[1] = gs.degIn[0]; gs.diagIn[1] = gs.diagIn[0];
        gs.deg[1] = gs.deg[0]; gs.diag[1] = gs.diag[0];
        tf32gemm_s<<<dim3(NV / 64, NV / 128, 1), 256>>>(gs);
    }
    dinv_fix<<<(3 * NV + 255) / 256, 256>>>(deg_ + 2 * NV, diag_ + 2 * NV, dinv_ + 2 * NV, 3 * NV);

    // -------- scaled merge + final dinv --------
    emax_dinv<<<NV, 256>>>(Mtb[0], dinv_ + 2 * NV, Mb[1], dinv_ + 4 * NV, An_, dinv_ + 5 * NV);

    // -------- GCN layers, final norm fused into A-loads --------
    sgemmKS<<<dim3(8, NV / 64), blk16>>>(An_, dinv_ + 5 * NV, XW_, H_, HIDD, NV, 8, nullptr);
    sgemm64<<<dim3(1, NV / 64), blk16>>>(H_, w2, HW_, NV, REPD, HIDD, bias1);  // relu(H+bias1) @ w2
    sgemmKS<<<dim3(8, NV / 64), blk16>>>(An_, dinv_ + 5 * NV, HW_, out, REPD, NV, 8, bias2);
}

// round 15
// speedup vs baseline: 1.0751x; 1.0084x over previous
#include <cuda_runtime.h>
#include <math.h>
#include <stdint.h>

// Problem constants
#define NV 1024
#define NE 32768
#define EMBD 128
#define HIDD 64
#define REPD 32

// ---------------- scratch (static device globals) ----------------
__device__ float g_A[2][3][NV][NV];
__device__ float g_p1[2][16][512][512];
__device__ float g_p2[2][4][257][257];
__device__ float g_att[2][3][NV][NV];
__device__ float g_M[2][NV][NV];
__device__ float g_Mt[2][NV][NV];
__device__ float g_An[NV][NV];
__device__ float g_dinv[6][NV];
__device__ float g_deg[5][NV];
__device__ float g_diag[5][NV];
__device__ float g_XW[NV][HIDD];
__device__ float g_H[NV][HIDD];
__device__ float g_HW[NV][REPD];

// ---------------- param structs ----------------
struct Sc5 { const int* e[5]; float* A[5]; float* degz; float* Hz; float* outz; };
struct PathPtrs {
    const float* in[2]; const float* w[2]; const float* b[2]; float* out[2];
};
struct FAtt {
    const float* p2[2]; const float* w1[2]; const float* b1[2];
    const float* w2[2]; const float* b2[2]; const float* A[2]; float* att[2];
    float* deg[2]; float* diag[2];
};
struct GemS {
    const float* A[2]; const float* B[2]; float* C[2];
    const float* degIn[2]; const float* diagIn[2];
    float* deg[2]; float* diag[2];
};

// ---------------- helpers ----------------
__device__ __forceinline__ uint32_t f2tf(float f) {
    uint32_t r;
    asm("cvt.rna.tf32.f32 %0, %1;" : "=r"(r) : "f"(f));
    return r;
}

__device__ __forceinline__ float fsigmoid(float s) {
    return 1.0f / (1.0f + __expf(-s));
}

__device__ __forceinline__ void mma_tf32(float* c, const uint32_t* a, uint32_t b0, uint32_t b1) {
    asm volatile(
        "mma.sync.aligned.m16n8k8.row.col.f32.tf32.tf32.f32 "
        "{%0,%1,%2,%3}, {%4,%5,%6,%7}, {%8,%9}, {%0,%1,%2,%3};"
        : "+f"(c[0]), "+f"(c[1]), "+f"(c[2]), "+f"(c[3])
        : "r"(a[0]), "r"(a[1]), "r"(a[2]), "r"(a[3]), "r"(b0), "r"(b1));
}

// ---------------- kernels ----------------

__global__ void scatter_all(Sc5 s) {
    int j = blockIdx.y;
    int k = blockIdx.x * blockDim.x + threadIdx.x;
    if (j == 0 && k < 5 * NV) s.degz[k] = 0.0f;
    if (j == 1) s.Hz[k] = 0.0f;
    if (j == 2) s.Hz[32768 + k] = 0.0f;
    if (j == 3) s.outz[k] = 0.0f;
    if (k < NE) {
        const int* e = s.e[j];
        atomicAdd(&s.A[j][e[k] * NV + e[NE + k]], 1.0f);
    }
}

// ---- conv1 (3x3, pad1, L->16) + relu + maxpool2 via tf32 MMA (fp32-exact hi/lo) ----
template <int L>
__device__ __forceinline__ void conv1mma_impl(const float* __restrict__ A,
                                              const float* __restrict__ w,
                                              const float* __restrict__ b,
                                              float* __restrict__ p1,
                                              float* __restrict__ tile,
                                              float* __restrict__ whi,
                                              float* __restrict__ wlo,
                                              float* __restrict__ sb) {
    constexpr int KS = (L * 9 + 7) / 8;
    int t = threadIdx.y * 16 + threadIdx.x;
    int lane = t & 31, wid = t >> 5;

    for (int i = t; i < 512; i += 256) {
        int oc = i >> 5, k = i & 31;
        float wv = (k < L * 9) ? w[oc * L * 9 + k] : 0.0f;
        float hi = __uint_as_float(f2tf(wv));
        whi[i] = hi;
        wlo[i] = __uint_as_float(f2tf(wv - hi));
    }
    if (t < 16) sb[t] = b[t];

    int gy0 = blockIdx.y * 32 - 1, gx0 = blockIdx.x * 32 - 1;
    for (int l = 0; l < L; l++)
        for (int i = t; i < 34 * 34; i += 256) {
            int r = i / 34, c = i % 34;
            int gy = gy0 + r, gx = gx0 + c;
            tile[(l * 34 + r) * 36 + c] = (gy >= 0 && gy < NV && gx >= 0 && gx < NV)
                                              ? A[((size_t)l * NV + gy) * NV + gx] : 0.0f;
        }
    __syncthreads();

    uint32_t ahi[KS][4], alo[KS][4];
    int r0 = (lane >> 2) * 32, r1 = ((lane >> 2) + 8) * 32;
#pragma unroll
    for (int s = 0; s < KS; s++) {
        int c0 = 8 * s + (lane & 3);
        ahi[s][0] = __float_as_uint(whi[r0 + c0]);
        ahi[s][1] = __float_as_uint(whi[r1 + c0]);
        ahi[s][2] = __float_as_uint(whi[r0 + c0 + 4]);
        ahi[s][3] = __float_as_uint(whi[r1 + c0 + 4]);
        alo[s][0] = __float_as_uint(wlo[r0 + c0]);
        alo[s][1] = __float_as_uint(wlo[r1 + c0]);
        alo[s][2] = __float_as_uint(wlo[r0 + c0 + 4]);
        alo[s][3] = __float_as_uint(wlo[r1 + c0 + 4]);
    }

    int boff[KS][2];
#pragma unroll
    for (int s = 0; s < KS; s++)
#pragma unroll
        for (int h = 0; h < 2; h++) {
            int k = 8 * s + (lane & 3) + 4 * h;
            if (k >= L * 9) k = 0;
            int l = k / 9, r = k % 9;
            boff[s][h] = (l * 34 + r / 3) * 36 + (r % 3) + (lane >> 2);
        }

    for (int u = wid; u < 64; u += 8) {
        int py = u >> 2, ux = u & 3;
        int base0 = (2 * py) * 36 + 8 * ux;
        int base1 = base0 + 36;
        float acc0[4] = {0.f, 0.f, 0.f, 0.f};
        float acc1[4] = {0.f, 0.f, 0.f, 0.f};
#pragma unroll
        for (int s = 0; s < KS; s++) {
            uint32_t b00 = __float_as_uint(tile[boff[s][0] + base0]);
            uint32_t b01 = __float_as_uint(tile[boff[s][1] + base0]);
            mma_tf32(acc0, ahi[s], b00, b01);
            mma_tf32(acc0, alo[s], b00, b01);
            uint32_t b10 = __float_as_uint(tile[boff[s][0] + base1]);
            uint32_t b11 = __float_as_uint(tile[boff[s][1] + base1]);
            mma_tf32(acc1, ahi[s], b10, b11);
            mma_tf32(acc1, alo[s], b10, b11);
        }
        int oc0 = lane >> 2, oc1 = oc0 + 8;
        int ox = blockIdx.x * 16 + 4 * ux + (lane & 3);
        int oy = blockIdx.y * 16 + py;
        float m0 = fmaxf(fmaxf(acc0[0], acc0[1]), fmaxf(acc1[0], acc1[1]));
        float m1 = fmaxf(fmaxf(acc0[2], acc0[3]), fmaxf(acc1[2], acc1[3]));
        p1[((size_t)oc0 * 512 + oy) * 512 + ox] = fmaxf(m0 + sb[oc0], 0.0f);
        p1[((size_t)oc1 * 512 + oy) * 512 + ox] = fmaxf(m1 + sb[oc1], 0.0f);
    }
}

__global__ void __launch_bounds__(256) conv1mma_both(PathPtrs p) {
    __shared__ float tile[3 * 34 * 36];
    __shared__ float whi[512], wlo[512];
    __shared__ float sb[16];
    int path = blockIdx.z;
    if (path == 0)
        conv1mma_impl<2>(p.in[0], p.w[0], p.b[0], p.out[0], tile, whi, wlo, sb);
    else
        conv1mma_impl<3>(p.in[1], p.w[1], p.b[1], p.out[1], tile, whi, wlo, sb);
}

// ---- conv2 (3x3, pad2, 16->4) + relu + maxpool2 (stride-40 float2 LDS, best) ----
__global__ void conv2pool_both(PathPtrs pp) {
    __shared__ float tile[36 * 40];
    __shared__ float sw[576];
    __shared__ float sb[4];
    int path = blockIdx.z;
    const float* p1 = pp.in[path];
    float* p2 = pp.out[path];
    int tx = threadIdx.x, ty = threadIdx.y;
    int t = ty * 16 + tx;
    for (int i = t; i < 576; i += 256) sw[i] = pp.w[path][i];
    if (t < 4) sb[t] = pp.b[path][t];

    int gy0 = blockIdx.y * 32 - 2, gx0 = blockIdx.x * 32 - 2;

    int srow[6], scol[6], sok[6];
    float r[6];
#pragma unroll
    for (int s = 0; s < 6; s++) {
        int i = t + s * 256;
        srow[s] = i / 36; scol[s] = i % 36;
        sok[s] = (i < 1296);
    }
#pragma unroll
    for (int s = 0; s < 6; s++) {
        if (sok[s]) {
            int gy = gy0 + srow[s], gx = gx0 + scol[s];
            r[s] = (gy >= 0 && gy < 512 && gx >= 0 && gx < 512)
                       ? p1[(size_t)gy * 512 + gx] : 0.0f;
        }
    }

    float acc[4][2][2];
#pragma unroll
    for (int oc = 0; oc < 4; oc++)
#pragma unroll
        for (int py = 0; py < 2; py++)
#pragma unroll
            for (int px = 0; px < 2; px++) acc[oc][py][px] = 0.0f;

    __syncthreads();

    for (int ci = 0; ci < 16; ci++) {
#pragma unroll
        for (int s = 0; s < 6; s++)
            if (sok[s]) tile[srow[s] * 40 + scol[s]] = r[s];
        __syncthreads();
        if (ci < 15) {
#pragma unroll
            for (int s = 0; s < 6; s++) {
                if (sok[s]) {
                    int gy = gy0 + srow[s], gx = gx0 + scol[s];
                    r[s] = (gy >= 0 && gy < 512 && gx >= 0 && gx < 512)
                               ? p1[((size_t)(ci + 1) * 512 + gy) * 512 + gx] : 0.0f;
                }
            }
        }
        float patch[4][4];
#pragma unroll
        for (int rw = 0; rw < 4; rw++) {
            const float2* rp = (const float2*)&tile[(2 * ty + rw) * 40 + 2 * tx];
            float2 a = rp[0], b = rp[1];
            patch[rw][0] = a.x; patch[rw][1] = a.y;
            patch[rw][2] = b.x; patch[rw][3] = b.y;
        }
#pragma unroll
        for (int oc = 0; oc < 4; oc++)
#pragma unroll
            for (int ky = 0; ky < 3; ky++)
#pragma unroll
                for (int kx = 0; kx < 3; kx++) {
                    float wv = sw[((oc * 16 + ci) * 3 + ky) * 3 + kx];
                    acc[oc][0][0] += wv * patch[ky][kx];
                    acc[oc][0][1] += wv * patch[ky][kx + 1];
                    acc[oc][1][0] += wv * patch[ky + 1][kx];
                    acc[oc][1][1] += wv * patch[ky + 1][kx + 1];
                }
        __syncthreads();
    }
    int x = blockIdx.x * 16 + tx, y = blockIdx.y * 16 + ty;
    if (x < 257 && y < 257) {
#pragma unroll
        for (int oc = 0; oc < 4; oc++) {
            float m = fmaxf(fmaxf(acc[oc][0][0], acc[oc][0][1]),
                            fmaxf(acc[oc][1][0], acc[oc][1][1])) + sb[oc];
            p2[((size_t)oc * 257 + y) * 257 + x] = fmaxf(m, 0.0f);
        }
    }
}

// ---- fused tconv1 + tconv2 + sigmoid + crop + adjacency multiply + att0 deg/diag ----
template <int L>
__device__ __forceinline__ void ftconv4_impl(const float* __restrict__ p2,
                                             const float* __restrict__ sw1,
                                             const float* __restrict__ sb1,
                                             const float* __restrict__ sw2,
                                             const float* __restrict__ sb2,
                                             const float* __restrict__ A,
                                             float* __restrict__ att,
                                             float* __restrict__ deg,
                                             float* __restrict__ diag,
                                             int q, int y) {
    int ky2 = (y + 1) & 1;
    int iy1 = (y - 1 + ky2) >> 1;
    int ky1 = (iy1 + 1) & 1;
    int iy0 = (iy1 - 1 + ky1) >> 1;

    float p[4];
#pragma unroll
    for (int cj = 0; cj < 4; cj++) p[cj] = p2[((size_t)cj * 257 + iy0) * 257 + q];

    float tA[16], tB[16];
#pragma unroll
    for (int ci = 0; ci < 16; ci++) {
        float sA = sb1[ci], sB = sb1[ci];
#pragma unroll
        for (int cj = 0; cj < 4; cj++) {
            int base = ((ci * 4 + cj) * 2 + ky1) * 2;
            sA += sw1[base + 1] * p[cj];
            sB += sw1[base + 0] * p[cj];
        }
        tA[ci] = fmaxf(sA, 0.0f);
        tB[ci] = fmaxf(sB, 0.0f);
    }

    float d0 = 0.f, d1 = 0.f, d2 = 0.f, d3 = 0.f;
#pragma unroll
    for (int l = 0; l < L; l++) {
        float s0A = sb2[l], s1A = sb2[l], s0B = sb2[l], s1B = sb2[l];
#pragma unroll
        for (int ci = 0; ci < 16; ci++) {
            int base = ((l * 16 + ci) * 2 + ky2) * 2;
            float w1v = sw2[base + 1], w0v = sw2[base + 0];
            s0A += w1v * tA[ci]; s1A += w0v * tA[ci];
            s0B += w1v * tB[ci]; s1B += w0v * tB[ci];
        }
        float g0 = fsigmoid(s0A);
        float g1 = fsigmoid(s1A);
        float g2 = fsigmoid(s0B);
        float g3 = fsigmoid(s1B);
        size_t off = (size_t)l * NV * NV + (size_t)y * NV + 4 * q;
        float4 a = *(const float4*)&A[off];
        float4 v = make_float4(a.x * g0, a.y * g1, a.z * g2, a.w * g3);
        *(float4*)&att[off] = v;
        if (l == 0) { d0 = v.x; d1 = v.y; d2 = v.z; d3 = v.w; }
    }

    float s = (d0 + d1) + (d2 + d3);
#pragma unroll
    for (int o = 16; o > 0; o >>= 1) s += __shfl_xor_sync(0xFFFFFFFF, s, o);
    if ((threadIdx.x & 31) == 0) atomicAdd(&deg[y], s);
    if ((y >> 2) == q) {
        int sel = y & 3;
        diag[y] = sel == 0 ? d0 : sel == 1 ? d1 : sel == 2 ? d2 : d3;
    }
}

__global__ void ftconv_att_both(FAtt fa) {
    __shared__ float sw1[256], sb1[16], sw2[192], sb2[3];
    int gidx = blockIdx.x * blockDim.x + threadIdx.x;
    const int PL = NV * 256;
    int path = gidx / PL;
    int idx = gidx - path * PL;
    int q = idx & 255, y = idx >> 8;
    const int L = (path == 0) ? 2 : 3;
    int t = threadIdx.x;
    if (t < 256) sw1[t] = fa.w1[path][t];
    if (t < 16) sb1[t] = fa.b1[path][t];
    for (int i = t; i < L * 64; i += 256) sw2[i] = fa.w2[path][i];
    if (t < L) sb2[t] = fa.b2[path][t];
    __syncthreads();
    if (path == 0)
        ftconv4_impl<2>(fa.p2[0], sw1, sb1, sw2, sb2, fa.A[0], fa.att[0],
                        fa.deg[0], fa.diag[0], q, y);
    else
        ftconv4_impl<3>(fa.p2[1], sw1, sb1, sw2, sb2, fa.A[1], fa.att[1],
                        fa.deg[1], fa.diag[1], q, y);
}

// ---- scaled max-merge + row-sum/dinv; dv for both inputs computed from deg/diag ----
__global__ void emax_dinv(const float* __restrict__ a, const float* __restrict__ degA,
                          const float* __restrict__ diagA,
                          const float* __restrict__ b, const float* __restrict__ degB,
                          const float* __restrict__ diagB,
                          float* __restrict__ o, float* __restrict__ dv) {
    __shared__ __align__(16) float sdva[NV];
    __shared__ __align__(16) float sdvb[NV];
    __shared__ float sh[256];
    __shared__ float sdiag;
    int row = blockIdx.x;
    for (int i = threadIdx.x; i < NV; i += 256) {
        float d = degA[i];
        if (diagA[i] == 0.0f) d += 1.0f;
        sdva[i] = d > 0.0f ? rsqrtf(d) : 0.0f;
        float e = degB[i];
        if (diagB[i] == 0.0f) e += 1.0f;
        sdvb[i] = e > 0.0f ? rsqrtf(e) : 0.0f;
    }
    __syncthreads();
    float dar = sdva[row], dbr = sdvb[row];
    int j0 = threadIdx.x << 2;
    float4 va = *(const float4*)&a[(size_t)row * NV + j0];
    float4 vb = *(const float4*)&b[(size_t)row * NV + j0];
    float4 da = *(const float4*)&sdva[j0];
    float4 db = *(const float4*)&sdvb[j0];
    if (j0 <= row && row < j0 + 4) {
        float* pa = &va.x;
        float* pb = &vb.x;
        int sel = row - j0;
        if (pa[sel] == 0.0f) pa[sel] = 1.0f;
        if (pb[sel] == 0.0f) pb[sel] = 1.0f;
    }
    float4 v;
    v.x = fmaxf(va.x * dar * da.x, vb.x * dbr * db.x);
    v.y = fmaxf(va.y * dar * da.y, vb.y * dbr * db.y);
    v.z = fmaxf(va.z * dar * da.z, vb.z * dbr * db.z);
    v.w = fmaxf(va.w * dar * da.w, vb.w * dbr * db.w);
    *(float4*)&o[(size_t)row * NV + j0] = v;
    if (j0 <= row && row < j0 + 4) {
        const float* pv = &v.x;
        sdiag = pv[row - j0];
    }
    sh[threadIdx.x] = (v.x + v.y) + (v.z + v.w);
    __syncthreads();
    for (int off = 128; off > 0; off >>= 1) {
        if (threadIdx.x < off) sh[threadIdx.x] += sh[threadIdx.x + off];
        __syncthreads();
    }
    if (threadIdx.x == 0) {
        float d = sh[0];
        if (sdiag == 0.0f) d += 1.0f;
        dv[row] = d > 0.0f ? rsqrtf(d) : 0.0f;
    }
}

// ---------------- tf32 GEMM: dv prologue; norm fused; raw-fp32 tf32 operands ----
__device__ __forceinline__ void fix_scale4(float4& v, int row, int kc, float dvr,
                                           const float* __restrict__ dv) {
    float4 dk = *(const float4*)&dv[kc];
    float* p = &v.x;
#pragma unroll
    for (int q = 0; q < 4; q++)
        if (row == kc + q && p[q] == 0.0f) p[q] = 1.0f;
    v.x *= dvr * dk.x; v.y *= dvr * dk.y; v.z *= dvr * dk.z; v.w *= dvr * dk.w;
}

__global__ void __launch_bounds__(256) tf32gemm_s(GemS g) {
    const float* __restrict__ A = g.A[blockIdx.z];
    const float* __restrict__ B = g.B[blockIdx.z];
    float* __restrict__ C = g.C[blockIdx.z];
    const float* __restrict__ degIn = g.degIn[blockIdx.z];
    const float* __restrict__ diagIn = g.diagIn[blockIdx.z];
    float* __restrict__ deg = g.deg[blockIdx.z];
    float* __restrict__ diag = g.diag[blockIdx.z];
    const int Nn = NV, K = NV;

    __shared__ float As[2][16][136];
    __shared__ float Bs[2][16][72];
    __shared__ __align__(16) float sdv[NV];

    const int tid = threadIdx.x;
    const int lane = tid & 31;
    const int wid = tid >> 5;
    const int wr = wid & 3;
    const int wc = wid >> 2;
    const int m0 = blockIdx.y * 128;
    const int n0 = blockIdx.x * 64;

    for (int i = tid; i < NV; i += 256) {
        float d = degIn[i];
        if (diagIn[i] == 0.0f) d += 1.0f;
        sdv[i] = d > 0.0f ? rsqrtf(d) : 0.0f;
    }
    __syncthreads();

    float acc[2][4][4];
#pragma unroll
    for (int mi = 0; mi < 2; mi++)
#pragma unroll
        for (int ni = 0; ni < 4; ni++)
#pragma unroll
            for (int r = 0; r < 4; r++) acc[mi][ni][r] = 0.0f;

    const int ar = tid >> 2;
    const int ac4 = (tid & 3) << 2;
    const int bk = tid >> 4;
    const int bn4 = (tid & 15) << 2;
    const int rowA0 = m0 + ar, rowA1 = m0 + 64 + ar;
    const float dvr0 = sdv[rowA0], dvr1 = sdv[rowA1];

    float4 av0, av1, bv;
    const int T = K >> 4;

    av0 = *(const float4*)&A[(size_t)rowA0 * K + ac4];
    av1 = *(const float4*)&A[(size_t)rowA1 * K + ac4];
    bv  = *(const float4*)&B[(size_t)bk * Nn + n0 + bn4];
    fix_scale4(av0, rowA0, ac4, dvr0, sdv);
    fix_scale4(av1, rowA1, ac4, dvr1, sdv);

    As[0][ac4 + 0][ar] = av0.x;
    As[0][ac4 + 1][ar] = av0.y;
    As[0][ac4 + 2][ar] = av0.z;
    As[0][ac4 + 3][ar] = av0.w;
    As[0][ac4 + 0][ar + 64] = av1.x;
    As[0][ac4 + 1][ar + 64] = av1.y;
    As[0][ac4 + 2][ar + 64] = av1.z;
    As[0][ac4 + 3][ar + 64] = av1.w;
    *(float4*)&Bs[0][bk][bn4] = bv;
    __syncthreads();

    for (int t = 0; t < T; t++) {
        int cur = t & 1;
        if (t + 1 < T) {
            int kb = (t + 1) << 4;
            av0 = *(const float4*)&A[(size_t)rowA0 * K + kb + ac4];
            av1 = *(const float4*)&A[(size_t)rowA1 * K + kb + ac4];
            bv  = *(const float4*)&B[(size_t)(kb + bk) * Nn + n0 + bn4];
            fix_scale4(av0, rowA0, kb + ac4, dvr0, sdv);
            fix_scale4(av1, rowA1, kb + ac4, dvr1, sdv);
        }
#pragma unroll
        for (int ks = 0; ks < 2; ks++) {
            const int k0 = ks * 8;
            uint32_t a[2][4], b[4][2];
            const int kl = k0 + (lane & 3);
            const int rl = lane >> 2;
#pragma unroll
            for (int mi = 0; mi < 2; mi++) {
                int m = wr * 32 + mi * 16 + rl;
                a[mi][0] = __float_as_uint(As[cur][kl][m]);
                a[mi][1] = __float_as_uint(As[cur][kl][m + 8]);
                a[mi][2] = __float_as_uint(As[cur][kl + 4][m]);
                a[mi][3] = __float_as_uint(As[cur][kl + 4][m + 8]);
            }
#pragma unroll
            for (int ni = 0; ni < 4; ni++) {
                int n = wc * 32 + ni * 8 + rl;
                b[ni][0] = __float_as_uint(Bs[cur][kl][n]);
                b[ni][1] = __float_as_uint(Bs[cur][kl + 4][n]);
            }
#pragma unroll
            for (int mi = 0; mi < 2; mi++)
#pragma unroll
                for (int ni = 0; ni < 4; ni++) {
                    asm volatile(
                        "mma.sync.aligned.m16n8k8.row.col.f32.tf32.tf32.f32 "
                        "{%0,%1,%2,%3}, {%4,%5,%6,%7}, {%8,%9}, {%0,%1,%2,%3};"
                        : "+f"(acc[mi][ni][0]), "+f"(acc[mi][ni][1]),
                          "+f"(acc[mi][ni][2]), "+f"(acc[mi][ni][3])
                        : "r"(a[mi][0]), "r"(a[mi][1]), "r"(a[mi][2]), "r"(a[mi][3]),
                          "r"(b[ni][0]), "r"(b[ni][1]));
                }
        }
        if (t + 1 < T) {
            int nxt = (t + 1) & 1;
            As[nxt][ac4 + 0][ar] = av0.x;
            As[nxt][ac4 + 1][ar] = av0.y;
            As[nxt][ac4 + 2][ar] = av0.z;
            As[nxt][ac4 + 3][ar] = av0.w;
            As[nxt][ac4 + 0][ar + 64] = av1.x;
            As[nxt][ac4 + 1][ar + 64] = av1.y;
            As[nxt][ac4 + 2][ar + 64] = av1.z;
            As[nxt][ac4 + 3][ar + 64] = av1.w;
            *(float4*)&Bs[nxt][bk][bn4] = bv;
            __syncthreads();
        }
    }

    const int rl = lane >> 2;
#pragma unroll
    for (int mi = 0; mi < 2; mi++) {
        int row = m0 + wr * 32 + mi * 16 + rl;
#pragma unroll
        for (int ni = 0; ni < 4; ni++) {
            int col = n0 + wc * 32 + ni * 8 + ((lane & 3) << 1);
            if (row == col) diag[row] = acc[mi][ni][0];
            if (row == col + 1) diag[row] = acc[mi][ni][1];
            if (row + 8 == col) diag[row + 8] = acc[mi][ni][2];
            if (row + 8 == col + 1) diag[row + 8] = acc[mi][ni][3];
            *(float2*)&C[(size_t)row * Nn + col] = make_float2(acc[mi][ni][0], acc[mi][ni][1]);
            *(float2*)&C[(size_t)(row + 8) * Nn + col] = make_float2(acc[mi][ni][2], acc[mi][ni][3]);
        }
    }
    float rs[4] = {0.0f, 0.0f, 0.0f, 0.0f};
#pragma unroll
    for (int mi = 0; mi < 2; mi++)
#pragma unroll
        for (int ni = 0; ni < 4; ni++) {
            rs[mi * 2 + 0] += acc[mi][ni][0] + acc[mi][ni][1];
            rs[mi * 2 + 1] += acc[mi][ni][2] + acc[mi][ni][3];
        }
#pragma unroll
    for (int q = 0; q < 4; q++) {
        rs[q] += __shfl_xor_sync(0xFFFFFFFF, rs[q], 1);
        rs[q] += __shfl_xor_sync(0xFFFFFFFF, rs[q], 2);
    }
    if ((lane & 3) == 0) {
        int rbase = m0 + wr * 32 + rl;
        atomicAdd(&deg[rbase], rs[0]);
        atomicAdd(&deg[rbase + 8], rs[1]);
        atomicAdd(&deg[rbase + 16], rs[2]);
        atomicAdd(&deg[rbase + 24], rs[3]);
    }
}

// plain fp32 64x64 tile GEMM; optional bias+relu applied to A-operand on load.
__global__ void sgemm64(const float* __restrict__ A, const float* __restrict__ B,
                        float* __restrict__ C, int M, int Nn, int K,
                        const float* __restrict__ abias) {
    __shared__ float As[16][64];
    __shared__ float Bs[16][64];
    int tx = threadIdx.x, ty = threadIdx.y;
    int tid = ty * 16 + tx;
    int m0 = blockIdx.y * 64, n0 = blockIdx.x * 64;
    float acc[4][4];
#pragma unroll
    for (int i = 0; i < 4; i++)
#pragma unroll
        for (int j = 0; j < 4; j++) acc[i][j] = 0.0f;
    int la_r = tid / 16, la_k = tid % 16;
    int lb_k = tid / 64, lb_n = tid % 64;
    for (int k0 = 0; k0 < K; k0 += 16) {
#pragma unroll
        for (int r = 0; r < 4; r++) {
            float v = A[(size_t)(m0 + la_r + 16 * r) * K + k0 + la_k];
            if (abias != nullptr) v = fmaxf(v + abias[k0 + la_k], 0.0f);
            As[la_k][la_r + 16 * r] = v;
        }
#pragma unroll
        for (int r = 0; r < 4; r++) {
            int kk = lb_k + 4 * r;
            Bs[kk][lb_n] = (n0 + lb_n < Nn) ? B[(size_t)(k0 + kk) * Nn + n0 + lb_n] : 0.0f;
        }
        __syncthreads();
#pragma unroll
        for (int k = 0; k < 16; k++) {
            float a[4], b[4];
#pragma unroll
            for (int i = 0; i < 4; i++) a[i] = As[k][ty * 4 + i];
#pragma unroll
            for (int j = 0; j < 4; j++) b[j] = Bs[k][tx * 4 + j];
#pragma unroll
            for (int i = 0; i < 4; i++)
#pragma unroll
                for (int j = 0; j < 4; j++) acc[i][j] += a[i] * b[j];
        }
        __syncthreads();
    }
#pragma unroll
    for (int i = 0; i < 4; i++) {
        int row = m0 + ty * 4 + i;
#pragma unroll
        for (int j = 0; j < 4; j++) {
            int col = n0 + tx * 4 + j;
            if (col < Nn) C[(size_t)row * Nn + col] = acc[i][j];
        }
    }
}

// split-K fp32 GEMM with fused gcn-norm on A: C += (Dv fix(A) Dv) @ B.
__global__ void sgemmKS(const float* __restrict__ A, const float* __restrict__ dv,
                        const float* __restrict__ B, float* __restrict__ C,
                        int Nn, int K, int KS, const float* __restrict__ bias) {
    __shared__ float As[16][64];
    __shared__ float Bs[16][64];
    int tx = threadIdx.x, ty = threadIdx.y;
    int tid = ty * 16 + tx;
    int m0 = blockIdx.y * 64;
    int kLen = K / KS;
    int kStart = blockIdx.x * kLen;
    float acc[4][4];
#pragma unroll
    for (int i = 0; i < 4; i++)
#pragma unroll
        for (int j = 0; j < 4; j++) acc[i][j] = 0.0f;
    int la_r = tid / 16, la_k = tid % 16;
    int lb_k = tid / 64, lb_n = tid % 64;
    for (int k0 = kStart; k0 < kStart + kLen; k0 += 16) {
#pragma unroll
        for (int r = 0; r < 4; r++) {
            int row = m0 + la_r + 16 * r;
            int kc = k0 + la_k;
            float v = A[(size_t)row * K + kc];
            if (row == kc && v == 0.0f) v = 1.0f;
            As[la_k][la_r + 16 * r] = v * dv[row] * dv[kc];
        }
#pragma unroll
        for (int r = 0; r < 4; r++) {
            int kk = lb_k + 4 * r;
            Bs[kk][lb_n] = (lb_n < Nn) ? B[(size_t)(k0 + kk) * Nn + lb_n] : 0.0f;
        }
        __syncthreads();
#pragma unroll
        for (int k = 0; k < 16; k++) {
            float a[4], b[4];
#pragma unroll
            for (int i = 0; i < 4; i++) a[i] = As[k][ty * 4 + i];
#pragma unroll
            for (int j = 0; j < 4; j++) b[j] = Bs[k][tx * 4 + j];
#pragma unroll
            for (int i = 0; i < 4; i++)
#pragma unroll
                for (int j = 0; j < 4; j++) acc[i][j] += a[i] * b[j];
        }
        __syncthreads();
    }
#pragma unroll
    for (int i = 0; i < 4; i++) {
        int row = m0 + ty * 4 + i;
#pragma unroll
        for (int j = 0; j < 4; j++) {
            int col = tx * 4 + j;
            if (col < Nn) {
                float v = acc[i][j];
                if (bias != nullptr && kStart == 0) v += bias[col];
                atomicAdd(&C[(size_t)row * Nn + col], v);
            }
        }
    }
}

// ---------------- host orchestration ----------------

extern "C" void kernel_launch(void* const* d_in, const int* in_sizes, int n_in,
                              void* d_out, int out_size) {
    const float* x = (const float*)d_in[0];
    const int* edges[5];
    for (int i = 0; i < 5; i++) edges[i] = (const int*)d_in[1 + i];
    const float* pbp[2][8];
    for (int b = 0; b < 2; b++)
        for (int i = 0; i < 8; i++) pbp[b][i] = (const float*)d_in[6 + b * 8 + i];
    const float* w1    = (const float*)d_in[22];
    const float* bias1 = (const float*)d_in[23];
    const float* w2    = (const float*)d_in[24];
    const float* bias2 = (const float*)d_in[25];
    float* out = (float*)d_out;

    float *A_, *p1_, *p2_, *att_, *M_, *Mt_, *An_, *dinv_, *deg_, *diag_, *XW_, *H_, *HW_;
    cudaGetSymbolAddress((void**)&A_,    g_A);
    cudaGetSymbolAddress((void**)&p1_,   g_p1);
    cudaGetSymbolAddress((void**)&p2_,   g_p2);
    cudaGetSymbolAddress((void**)&att_,  g_att);
    cudaGetSymbolAddress((void**)&M_,    g_M);
    cudaGetSymbolAddress((void**)&Mt_,   g_Mt);
    cudaGetSymbolAddress((void**)&An_,   g_An);
    cudaGetSymbolAddress((void**)&dinv_, g_dinv);
    cudaGetSymbolAddress((void**)&deg_,  g_deg);
    cudaGetSymbolAddress((void**)&diag_, g_diag);
    cudaGetSymbolAddress((void**)&XW_,   g_XW);
    cudaGetSymbolAddress((void**)&H_,    g_H);
    cudaGetSymbolAddress((void**)&HW_,   g_HW);

    const size_t PLANE = (size_t)NV * NV;
    dim3 blk16(16, 16);

    float* Ab[2]   = { A_,   A_   + 3 * PLANE };
    float* p1b[2]  = { p1_,  p1_  + (size_t)16 * 512 * 512 };
    float* p2b[2]  = { p2_,  p2_  + (size_t)4 * 257 * 257 };
    float* attb[2] = { att_, att_ + 3 * PLANE };
    float* Mb[2]   = { M_,   M_   + PLANE };
    float* Mtb[2]  = { Mt_,  Mt_  + PLANE };

    // -------- setup --------
    cudaMemsetAsync(A_, 0, 6 * PLANE * sizeof(float), 0);
    sgemm64<<<dim3(1, NV / 64), blk16>>>(x, w1, XW_, NV, HIDD, EMBD, nullptr);

    // -------- scatter all 5 edge lists (also zeros deg, H, out) --------
    Sc5 sc;
    sc.e[0] = edges[0]; sc.A[0] = Ab[0];
    sc.e[1] = edges[1]; sc.A[1] = Ab[0] + PLANE;
    sc.e[2] = edges[2]; sc.A[2] = Ab[1];
    sc.e[3] = edges[3]; sc.A[3] = Ab[1] + PLANE;
    sc.e[4] = edges[4]; sc.A[4] = Ab[1] + 2 * PLANE;
    sc.degz = deg_;
    sc.Hz = H_;
    sc.outz = out;
    scatter_all<<<dim3((NE + 255) / 256, 5), 256>>>(sc);

    // -------- conv encoder (both paths batched) --------
    PathPtrs c1 = {{Ab[0], Ab[1]}, {pbp[0][0], pbp[1][0]}, {pbp[0][1], pbp[1][1]}, {p1b[0], p1b[1]}};
    conv1mma_both<<<dim3(32, 32, 2), blk16>>>(c1);

    PathPtrs c2 = {{p1b[0], p1b[1]}, {pbp[0][2], pbp[1][2]}, {pbp[0][3], pbp[1][3]}, {p2b[0], p2b[1]}};
    conv2pool_both<<<dim3(17, 17, 2), blk16>>>(c2);

    // fused tconv1 + tconv2 + sigmoid + adjacency multiply + att0 deg/diag (4-wide)
    FAtt fa;
    for (int p = 0; p < 2; p++) {
        fa.p2[p] = p2b[p];
        fa.w1[p] = pbp[p][4]; fa.b1[p] = pbp[p][5];
        fa.w2[p] = pbp[p][6]; fa.b2[p] = pbp[p][7];
        fa.A[p] = Ab[p]; fa.att[p] = attb[p];
        fa.deg[p] = deg_ + p * NV; fa.diag[p] = diag_ + p * NV;
    }
    ftconv_att_both<<<2 * NV, 256>>>(fa);

    // -------- M-chain, norms + dv computed inside GEMMs --------
    {
        GemS gs;
        gs.A[0] = attb[0];          gs.A[1] = attb[1];
        gs.B[0] = attb[0] + PLANE;  gs.B[1] = attb[1] + PLANE;
        gs.C[0] = Mtb[0];           gs.C[1] = Mtb[1];
        gs.degIn[0] = deg_;         gs.degIn[1] = deg_ + NV;
        gs.diagIn[0] = diag_;       gs.diagIn[1] = diag_ + NV;
        gs.deg[0] = deg_ + 2 * NV;  gs.deg[1] = deg_ + 3 * NV;
        gs.diag[0] = diag_ + 2 * NV; gs.diag[1] = diag_ + 3 * NV;
        tf32gemm_s<<<dim3(NV / 64, NV / 128, 2), 256>>>(gs);
    }
    {
        GemS gs;
        gs.A[0] = Mtb[1];
        gs.B[0] = attb[1] + 2 * PLANE;
        gs.C[0] = Mb[1];
        gs.degIn[0] = deg_ + 3 * NV;
        gs.diagIn[0] = diag_ + 3 * NV;
        gs.deg[0] = deg_ + 4 * NV;
        gs.diag[0] = diag_ + 4 * NV;
        gs.A[1] = gs.A[0]; gs.B[1] = gs.B[0]; gs.C[1] = gs.C[0];
        gs.degIn[1] = gs.degIn[0]; gs.diagIn[1] = gs.diagIn[0];
        gs.deg[1] = gs.deg[0]; gs.diag[1] = gs.diag[0];
        tf32gemm_s<<<dim3(NV / 64, NV / 128, 1), 256>>>(gs);
    }

    // -------- scaled merge + final dinv (dv2/dv4 computed inline from deg/diag) --------
    emax_dinv<<<NV, 256>>>(Mtb[0], deg_ + 2 * NV, diag_ + 2 * NV,
                           Mb[1], deg_ + 4 * NV, diag_ + 4 * NV,
                           An_, dinv_ + 5 * NV);

    // -------- GCN layers, final norm fused into A-loads (split-K 16) --------
    sgemmKS<<<dim3(16, NV / 64), blk16>>>(An_, dinv_ + 5 * NV, XW_, H_, HIDD, NV, 16, nullptr);
    sgemm64<<<dim3(1, NV / 64), blk16>>>(H_, w2, HW_, NV, REPD, HIDD, bias1);  // relu(H+bias1) @ w2
    sgemmKS<<<dim3(16, NV / 64), blk16>>>(An_, dinv_ + 5 * NV, HW_, out, REPD, NV, 16, bias2);
}

// round 16
// speedup vs baseline: 1.1346x; 1.0554x over previous
#include <cuda_runtime.h>
#include <math.h>
#include <stdint.h>

// Problem constants
#define NV 1024
#define NE 32768
#define EMBD 128
#define HIDD 64
#define REPD 32

// ---------------- scratch (static device globals) ----------------
__device__ float g_A[2][3][NV][NV];
__device__ float g_p1[2][16][512][512];
__device__ float g_p2[2][4][257][257];
__device__ float g_att[2][3][NV][NV];
__device__ float g_M[2][NV][NV];
__device__ float g_Mt[2][NV][NV];
__device__ float g_An[NV][NV];
__device__ float g_dinv[6][NV];
__device__ float g_deg[5][NV];
__device__ float g_diag[5][NV];
__device__ float g_XW[NV][HIDD];
__device__ float g_H[NV][HIDD];
__device__ float g_HW[NV][REPD];

// ---------------- param structs ----------------
struct Sc5 { const int* e[5]; float* A[5]; float* degz; float* Hz; float* outz; };
struct PathPtrs {
    const float* in[2]; const float* w[2]; const float* b[2]; float* out[2];
};
struct FAtt {
    const float* p2[2]; const float* w1[2]; const float* b1[2];
    const float* w2[2]; const float* b2[2]; const float* A[2]; float* att[2];
    float* deg[2]; float* diag[2];
};
struct GemS {
    const float* A[2]; const float* B[2]; float* C[2];
    const float* degIn[2]; const float* diagIn[2];
    float* deg[2]; float* diag[2];
};

// ---------------- helpers ----------------
__device__ __forceinline__ uint32_t f2tf(float f) {
    uint32_t r;
    asm("cvt.rna.tf32.f32 %0, %1;" : "=r"(r) : "f"(f));
    return r;
}

__device__ __forceinline__ float fsigmoid(float s) {
    return 1.0f / (1.0f + __expf(-s));
}

__device__ __forceinline__ void mma_tf32(float* c, const uint32_t* a, uint32_t b0, uint32_t b1) {
    asm volatile(
        "mma.sync.aligned.m16n8k8.row.col.f32.tf32.tf32.f32 "
        "{%0,%1,%2,%3}, {%4,%5,%6,%7}, {%8,%9}, {%0,%1,%2,%3};"
        : "+f"(c[0]), "+f"(c[1]), "+f"(c[2]), "+f"(c[3])
        : "r"(a[0]), "r"(a[1]), "r"(a[2]), "r"(a[3]), "r"(b0), "r"(b1));
}

// ---------------- kernels ----------------

__global__ void scatter_all(Sc5 s) {
    int j = blockIdx.y;
    int k = blockIdx.x * blockDim.x + threadIdx.x;
    if (j == 0 && k < 5 * NV) s.degz[k] = 0.0f;
    if (j == 1) s.Hz[k] = 0.0f;
    if (j == 2) s.Hz[32768 + k] = 0.0f;
    if (j == 3) s.outz[k] = 0.0f;
    if (k < NE) {
        const int* e = s.e[j];
        atomicAdd(&s.A[j][e[k] * NV + e[NE + k]], 1.0f);
    }
}

// ---- conv1 (3x3, pad1, L->16) + relu + maxpool2 via tf32 MMA ----
// Single-MMA: weights rna-rounded to tf32 (inputs are exact small ints).
template <int L>
__device__ __forceinline__ void conv1mma_impl(const float* __restrict__ A,
                                              const float* __restrict__ w,
                                              const float* __restrict__ b,
                                              float* __restrict__ p1,
                                              float* __restrict__ tile,
                                              float* __restrict__ whi,
                                              float* __restrict__ sb) {
    constexpr int KS = (L * 9 + 7) / 8;
    int t = threadIdx.y * 16 + threadIdx.x;
    int lane = t & 31, wid = t >> 5;

    for (int i = t; i < 512; i += 256) {
        int oc = i >> 5, k = i & 31;
        float wv = (k < L * 9) ? w[oc * L * 9 + k] : 0.0f;
        whi[i] = __uint_as_float(f2tf(wv));
    }
    if (t < 16) sb[t] = b[t];

    int gy0 = blockIdx.y * 32 - 1, gx0 = blockIdx.x * 32 - 1;
    for (int l = 0; l < L; l++)
        for (int i = t; i < 34 * 34; i += 256) {
            int r = i / 34, c = i % 34;
            int gy = gy0 + r, gx = gx0 + c;
            tile[(l * 34 + r) * 36 + c] = (gy >= 0 && gy < NV && gx >= 0 && gx < NV)
                                              ? A[((size_t)l * NV + gy) * NV + gx] : 0.0f;
        }
    __syncthreads();

    uint32_t ahi[KS][4];
    int r0 = (lane >> 2) * 32, r1 = ((lane >> 2) + 8) * 32;
#pragma unroll
    for (int s = 0; s < KS; s++) {
        int c0 = 8 * s + (lane & 3);
        ahi[s][0] = __float_as_uint(whi[r0 + c0]);
        ahi[s][1] = __float_as_uint(whi[r1 + c0]);
        ahi[s][2] = __float_as_uint(whi[r0 + c0 + 4]);
        ahi[s][3] = __float_as_uint(whi[r1 + c0 + 4]);
    }

    int boff[KS][2];
#pragma unroll
    for (int s = 0; s < KS; s++)
#pragma unroll
        for (int h = 0; h < 2; h++) {
            int k = 8 * s + (lane & 3) + 4 * h;
            if (k >= L * 9) k = 0;
            int l = k / 9, r = k % 9;
            boff[s][h] = (l * 34 + r / 3) * 36 + (r % 3) + (lane >> 2);
        }

    for (int u = wid; u < 64; u += 8) {
        int py = u >> 2, ux = u & 3;
        int base0 = (2 * py) * 36 + 8 * ux;
        int base1 = base0 + 36;
        float acc0[4] = {0.f, 0.f, 0.f, 0.f};
        float acc1[4] = {0.f, 0.f, 0.f, 0.f};
#pragma unroll
        for (int s = 0; s < KS; s++) {
            uint32_t b00 = __float_as_uint(tile[boff[s][0] + base0]);
            uint32_t b01 = __float_as_uint(tile[boff[s][1] + base0]);
            mma_tf32(acc0, ahi[s], b00, b01);
            uint32_t b10 = __float_as_uint(tile[boff[s][0] + base1]);
            uint32_t b11 = __float_as_uint(tile[boff[s][1] + base1]);
            mma_tf32(acc1, ahi[s], b10, b11);
        }
        int oc0 = lane >> 2, oc1 = oc0 + 8;
        int ox = blockIdx.x * 16 + 4 * ux + (lane & 3);
        int oy = blockIdx.y * 16 + py;
        float m0 = fmaxf(fmaxf(acc0[0], acc0[1]), fmaxf(acc1[0], acc1[1]));
        float m1 = fmaxf(fmaxf(acc0[2], acc0[3]), fmaxf(acc1[2], acc1[3]));
        p1[((size_t)oc0 * 512 + oy) * 512 + ox] = fmaxf(m0 + sb[oc0], 0.0f);
        p1[((size_t)oc1 * 512 + oy) * 512 + ox] = fmaxf(m1 + sb[oc1], 0.0f);
    }
}

__global__ void __launch_bounds__(256) conv1mma_both(PathPtrs p) {
    __shared__ float tile[3 * 34 * 36];
    __shared__ float whi[512];
    __shared__ float sb[16];
    int path = blockIdx.z;
    if (path == 0)
        conv1mma_impl<2>(p.in[0], p.w[0], p.b[0], p.out[0], tile, whi, sb);
    else
        conv1mma_impl<3>(p.in[1], p.w[1], p.b[1], p.out[1], tile, whi, sb);
}

// ---- conv2 (3x3, pad2, 16->4) + relu + maxpool2 (stride-40 float2 LDS, best) ----
__global__ void conv2pool_both(PathPtrs pp) {
    __shared__ float tile[36 * 40];
    __shared__ float sw[576];
    __shared__ float sb[4];
    int path = blockIdx.z;
    const float* p1 = pp.in[path];
    float* p2 = pp.out[path];
    int tx = threadIdx.x, ty = threadIdx.y;
    int t = ty * 16 + tx;
    for (int i = t; i < 576; i += 256) sw[i] = pp.w[path][i];
    if (t < 4) sb[t] = pp.b[path][t];

    int gy0 = blockIdx.y * 32 - 2, gx0 = blockIdx.x * 32 - 2;

    int srow[6], scol[6], sok[6];
    float r[6];
#pragma unroll
    for (int s = 0; s < 6; s++) {
        int i = t + s * 256;
        srow[s] = i / 36; scol[s] = i % 36;
        sok[s] = (i < 1296);
    }
#pragma unroll
    for (int s = 0; s < 6; s++) {
        if (sok[s]) {
            int gy = gy0 + srow[s], gx = gx0 + scol[s];
            r[s] = (gy >= 0 && gy < 512 && gx >= 0 && gx < 512)
                       ? p1[(size_t)gy * 512 + gx] : 0.0f;
        }
    }

    float acc[4][2][2];
#pragma unroll
    for (int oc = 0; oc < 4; oc++)
#pragma unroll
        for (int py = 0; py < 2; py++)
#pragma unroll
            for (int px = 0; px < 2; px++) acc[oc][py][px] = 0.0f;

    __syncthreads();

    for (int ci = 0; ci < 16; ci++) {
#pragma unroll
        for (int s = 0; s < 6; s++)
            if (sok[s]) tile[srow[s] * 40 + scol[s]] = r[s];
        __syncthreads();
        if (ci < 15) {
#pragma unroll
            for (int s = 0; s < 6; s++) {
                if (sok[s]) {
                    int gy = gy0 + srow[s], gx = gx0 + scol[s];
                    r[s] = (gy >= 0 && gy < 512 && gx >= 0 && gx < 512)
                               ? p1[((size_t)(ci + 1) * 512 + gy) * 512 + gx] : 0.0f;
                }
            }
        }
        float patch[4][4];
#pragma unroll
        for (int rw = 0; rw < 4; rw++) {
            const float2* rp = (const float2*)&tile[(2 * ty + rw) * 40 + 2 * tx];
            float2 a = rp[0], b = rp[1];
            patch[rw][0] = a.x; patch[rw][1] = a.y;
            patch[rw][2] = b.x; patch[rw][3] = b.y;
        }
#pragma unroll
        for (int oc = 0; oc < 4; oc++)
#pragma unroll
            for (int ky = 0; ky < 3; ky++)
#pragma unroll
                for (int kx = 0; kx < 3; kx++) {
                    float wv = sw[((oc * 16 + ci) * 3 + ky) * 3 + kx];
                    acc[oc][0][0] += wv * patch[ky][kx];
                    acc[oc][0][1] += wv * patch[ky][kx + 1];
                    acc[oc][1][0] += wv * patch[ky + 1][kx];
                    acc[oc][1][1] += wv * patch[ky + 1][kx + 1];
                }
        __syncthreads();
    }
    int x = blockIdx.x * 16 + tx, y = blockIdx.y * 16 + ty;
    if (x < 257 && y < 257) {
#pragma unroll
        for (int oc = 0; oc < 4; oc++) {
            float m = fmaxf(fmaxf(acc[oc][0][0], acc[oc][0][1]),
                            fmaxf(acc[oc][1][0], acc[oc][1][1])) + sb[oc];
            p2[((size_t)oc * 257 + y) * 257 + x] = fmaxf(m, 0.0f);
        }
    }
}

// ---- fused tconv1 + tconv2 + sigmoid + crop + adjacency multiply + att0 deg/diag ----
template <int L>
__device__ __forceinline__ void ftconv4_impl(const float* __restrict__ p2,
                                             const float* __restrict__ sw1,
                                             const float* __restrict__ sb1,
                                             const float* __restrict__ sw2,
                                             const float* __restrict__ sb2,
                                             const float* __restrict__ A,
                                             float* __restrict__ att,
                                             float* __restrict__ deg,
                                             float* __restrict__ diag,
                                             int q, int y) {
    int ky2 = (y + 1) & 1;
    int iy1 = (y - 1 + ky2) >> 1;
    int ky1 = (iy1 + 1) & 1;
    int iy0 = (iy1 - 1 + ky1) >> 1;

    float p[4];
#pragma unroll
    for (int cj = 0; cj < 4; cj++) p[cj] = p2[((size_t)cj * 257 + iy0) * 257 + q];

    float tA[16], tB[16];
#pragma unroll
    for (int ci = 0; ci < 16; ci++) {
        float sA = sb1[ci], sB = sb1[ci];
#pragma unroll
        for (int cj = 0; cj < 4; cj++) {
            int base = ((ci * 4 + cj) * 2 + ky1) * 2;
            sA += sw1[base + 1] * p[cj];
            sB += sw1[base + 0] * p[cj];
        }
        tA[ci] = fmaxf(sA, 0.0f);
        tB[ci] = fmaxf(sB, 0.0f);
    }

    float d0 = 0.f, d1 = 0.f, d2 = 0.f, d3 = 0.f;
#pragma unroll
    for (int l = 0; l < L; l++) {
        float s0A = sb2[l], s1A = sb2[l], s0B = sb2[l], s1B = sb2[l];
#pragma unroll
        for (int ci = 0; ci < 16; ci++) {
            int base = ((l * 16 + ci) * 2 + ky2) * 2;
            float w1v = sw2[base + 1], w0v = sw2[base + 0];
            s0A += w1v * tA[ci]; s1A += w0v * tA[ci];
            s0B += w1v * tB[ci]; s1B += w0v * tB[ci];
        }
        float g0 = fsigmoid(s0A);
        float g1 = fsigmoid(s1A);
        float g2 = fsigmoid(s0B);
        float g3 = fsigmoid(s1B);
        size_t off = (size_t)l * NV * NV + (size_t)y * NV + 4 * q;
        float4 a = *(const float4*)&A[off];
        float4 v = make_float4(a.x * g0, a.y * g1, a.z * g2, a.w * g3);
        *(float4*)&att[off] = v;
        if (l == 0) { d0 = v.x; d1 = v.y; d2 = v.z; d3 = v.w; }
    }

    float s = (d0 + d1) + (d2 + d3);
#pragma unroll
    for (int o = 16; o > 0; o >>= 1) s += __shfl_xor_sync(0xFFFFFFFF, s, o);
    if ((threadIdx.x & 31) == 0) atomicAdd(&deg[y], s);
    if ((y >> 2) == q) {
        int sel = y & 3;
        diag[y] = sel == 0 ? d0 : sel == 1 ? d1 : sel == 2 ? d2 : d3;
    }
}

__global__ void ftconv_att_both(FAtt fa) {
    __shared__ float sw1[256], sb1[16], sw2[192], sb2[3];
    int gidx = blockIdx.x * blockDim.x + threadIdx.x;
    const int PL = NV * 256;
    int path = gidx / PL;
    int idx = gidx - path * PL;
    int q = idx & 255, y = idx >> 8;
    const int L = (path == 0) ? 2 : 3;
    int t = threadIdx.x;
    if (t < 256) sw1[t] = fa.w1[path][t];
    if (t < 16) sb1[t] = fa.b1[path][t];
    for (int i = t; i < L * 64; i += 256) sw2[i] = fa.w2[path][i];
    if (t < L) sb2[t] = fa.b2[path][t];
    __syncthreads();
    if (path == 0)
        ftconv4_impl<2>(fa.p2[0], sw1, sb1, sw2, sb2, fa.A[0], fa.att[0],
                        fa.deg[0], fa.diag[0], q, y);
    else
        ftconv4_impl<3>(fa.p2[1], sw1, sb1, sw2, sb2, fa.A[1], fa.att[1],
                        fa.deg[1], fa.diag[1], q, y);
}

// ---- scaled max-merge + row-sum/dinv; dv for both inputs computed from deg/diag ----
__global__ void emax_dinv(const float* __restrict__ a, const float* __restrict__ degA,
                          const float* __restrict__ diagA,
                          const float* __restrict__ b, const float* __restrict__ degB,
                          const float* __restrict__ diagB,
                          float* __restrict__ o, float* __restrict__ dv) {
    __shared__ __align__(16) float sdva[NV];
    __shared__ __align__(16) float sdvb[NV];
    __shared__ float sh[256];
    __shared__ float sdiag;
    int row = blockIdx.x;
    for (int i = threadIdx.x; i < NV; i += 256) {
        float d = degA[i];
        if (diagA[i] == 0.0f) d += 1.0f;
        sdva[i] = d > 0.0f ? rsqrtf(d) : 0.0f;
        float e = degB[i];
        if (diagB[i] == 0.0f) e += 1.0f;
        sdvb[i] = e > 0.0f ? rsqrtf(e) : 0.0f;
    }
    __syncthreads();
    float dar = sdva[row], dbr = sdvb[row];
    int j0 = threadIdx.x << 2;
    float4 va = *(const float4*)&a[(size_t)row * NV + j0];
    float4 vb = *(const float4*)&b[(size_t)row * NV + j0];
    float4 da = *(const float4*)&sdva[j0];
    float4 db = *(const float4*)&sdvb[j0];
    if (j0 <= row && row < j0 + 4) {
        float* pa = &va.x;
        float* pb = &vb.x;
        int sel = row - j0;
        if (pa[sel] == 0.0f) pa[sel] = 1.0f;
        if (pb[sel] == 0.0f) pb[sel] = 1.0f;
    }
    float4 v;
    v.x = fmaxf(va.x * dar * da.x, vb.x * dbr * db.x);
    v.y = fmaxf(va.y * dar * da.y, vb.y * dbr * db.y);
    v.z = fmaxf(va.z * dar * da.z, vb.z * dbr * db.z);
    v.w = fmaxf(va.w * dar * da.w, vb.w * dbr * db.w);
    *(float4*)&o[(size_t)row * NV + j0] = v;
    if (j0 <= row && row < j0 + 4) {
        const float* pv = &v.x;
        sdiag = pv[row - j0];
    }
    sh[threadIdx.x] = (v.x + v.y) + (v.z + v.w);
    __syncthreads();
    for (int off = 128; off > 0; off >>= 1) {
        if (threadIdx.x < off) sh[threadIdx.x] += sh[threadIdx.x + off];
        __syncthreads();
    }
    if (threadIdx.x == 0) {
        float d = sh[0];
        if (sdiag == 0.0f) d += 1.0f;
        dv[row] = d > 0.0f ? rsqrtf(d) : 0.0f;
    }
}

// ---------------- tf32 GEMM: dv prologue; norm fused; raw-fp32 tf32 operands ----
__device__ __forceinline__ void fix_scale4(float4& v, int row, int kc, float dvr,
                                           const float* __restrict__ dv) {
    float4 dk = *(const float4*)&dv[kc];
    float* p = &v.x;
#pragma unroll
    for (int q = 0; q < 4; q++)
        if (row == kc + q && p[q] == 0.0f) p[q] = 1.0f;
    v.x *= dvr * dk.x; v.y *= dvr * dk.y; v.z *= dvr * dk.z; v.w *= dvr * dk.w;
}

__global__ void __launch_bounds__(256) tf32gemm_s(GemS g) {
    const float* __restrict__ A = g.A[blockIdx.z];
    const float* __restrict__ B = g.B[blockIdx.z];
    float* __restrict__ C = g.C[blockIdx.z];
    const float* __restrict__ degIn = g.degIn[blockIdx.z];
    const float* __restrict__ diagIn = g.diagIn[blockIdx.z];
    float* __restrict__ deg = g.deg[blockIdx.z];
    float* __restrict__ diag = g.diag[blockIdx.z];
    const int Nn = NV, K = NV;

    __shared__ float As[2][16][136];
    __shared__ float Bs[2][16][72];
    __shared__ __align__(16) float sdv[NV];

    const int tid = threadIdx.x;
    const int lane = tid & 31;
    const int wid = tid >> 5;
    const int wr = wid & 3;
    const int wc = wid >> 2;
    const int m0 = blockIdx.y * 128;
    const int n0 = blockIdx.x * 64;

    for (int i = tid; i < NV; i += 256) {
        float d = degIn[i];
        if (diagIn[i] == 0.0f) d += 1.0f;
        sdv[i] = d > 0.0f ? rsqrtf(d) : 0.0f;
    }
    __syncthreads();

    float acc[2][4][4];
#pragma unroll
    for (int mi = 0; mi < 2; mi++)
#pragma unroll
        for (int ni = 0; ni < 4; ni++)
#pragma unroll
            for (int r = 0; r < 4; r++) acc[mi][ni][r] = 0.0f;

    const int ar = tid >> 2;
    const int ac4 = (tid & 3) << 2;
    const int bk = tid >> 4;
    const int bn4 = (tid & 15) << 2;
    const int rowA0 = m0 + ar, rowA1 = m0 + 64 + ar;
    const float dvr0 = sdv[rowA0], dvr1 = sdv[rowA1];

    float4 av0, av1, bv;
    const int T = K >> 4;

    av0 = *(const float4*)&A[(size_t)rowA0 * K + ac4];
    av1 = *(const float4*)&A[(size_t)rowA1 * K + ac4];
    bv  = *(const float4*)&B[(size_t)bk * Nn + n0 + bn4];
    fix_scale4(av0, rowA0, ac4, dvr0, sdv);
    fix_scale4(av1, rowA1, ac4, dvr1, sdv);

    As[0][ac4 + 0][ar] = av0.x;
    As[0][ac4 + 1][ar] = av0.y;
    As[0][ac4 + 2][ar] = av0.z;
    As[0][ac4 + 3][ar] = av0.w;
    As[0][ac4 + 0][ar + 64] = av1.x;
    As[0][ac4 + 1][ar + 64] = av1.y;
    As[0][ac4 + 2][ar + 64] = av1.z;
    As[0][ac4 + 3][ar + 64] = av1.w;
    *(float4*)&Bs[0][bk][bn4] = bv;
    __syncthreads();

    for (int t = 0; t < T; t++) {
        int cur = t & 1;
        if (t + 1 < T) {
            int kb = (t + 1) << 4;
            av0 = *(const float4*)&A[(size_t)rowA0 * K + kb + ac4];
            av1 = *(const float4*)&A[(size_t)rowA1 * K + kb + ac4];
            bv  = *(const float4*)&B[(size_t)(kb + bk) * Nn + n0 + bn4];
            fix_scale4(av0, rowA0, kb + ac4, dvr0, sdv);
            fix_scale4(av1, rowA1, kb + ac4, dvr1, sdv);
        }
#pragma unroll
        for (int ks = 0; ks < 2; ks++) {
            const int k0 = ks * 8;
            uint32_t a[2][4], b[4][2];
            const int kl = k0 + (lane & 3);
            const int rl = lane >> 2;
#pragma unroll
            for (int mi = 0; mi < 2; mi++) {
                int m = wr * 32 + mi * 16 + rl;
                a[mi][0] = __float_as_uint(As[cur][kl][m]);
                a[mi][1] = __float_as_uint(As[cur][kl][m + 8]);
                a[mi][2] = __float_as_uint(As[cur][kl + 4][m]);
                a[mi][3] = __float_as_uint(As[cur][kl + 4][m + 8]);
            }
#pragma unroll
            for (int ni = 0; ni < 4; ni++) {
                int n = wc * 32 + ni * 8 + rl;
                b[ni][0] = __float_as_uint(Bs[cur][kl][n]);
                b[ni][1] = __float_as_uint(Bs[cur][kl + 4][n]);
            }
#pragma unroll
            for (int mi = 0; mi < 2; mi++)
#pragma unroll
                for (int ni = 0; ni < 4; ni++) {
                    asm volatile(
                        "mma.sync.aligned.m16n8k8.row.col.f32.tf32.tf32.f32 "
                        "{%0,%1,%2,%3}, {%4,%5,%6,%7}, {%8,%9}, {%0,%1,%2,%3};"
                        : "+f"(acc[mi][ni][0]), "+f"(acc[mi][ni][1]),
                          "+f"(acc[mi][ni][2]), "+f"(acc[mi][ni][3])
                        : "r"(a[mi][0]), "r"(a[mi][1]), "r"(a[mi][2]), "r"(a[mi][3]),
                          "r"(b[ni][0]), "r"(b[ni][1]));
                }
        }
        if (t + 1 < T) {
            int nxt = (t + 1) & 1;
            As[nxt][ac4 + 0][ar] = av0.x;
            As[nxt][ac4 + 1][ar] = av0.y;
            As[nxt][ac4 + 2][ar] = av0.z;
            As[nxt][ac4 + 3][ar] = av0.w;
            As[nxt][ac4 + 0][ar + 64] = av1.x;
            As[nxt][ac4 + 1][ar + 64] = av1.y;
            As[nxt][ac4 + 2][ar + 64] = av1.z;
            As[nxt][ac4 + 3][ar + 64] = av1.w;
            *(float4*)&Bs[nxt][bk][bn4] = bv;
            __syncthreads();
        }
    }

    const int rl = lane >> 2;
#pragma unroll
    for (int mi = 0; mi < 2; mi++) {
        int row = m0 + wr * 32 + mi * 16 + rl;
#pragma unroll
        for (int ni = 0; ni < 4; ni++) {
            int col = n0 + wc * 32 + ni * 8 + ((lane & 3) << 1);
            if (row == col) diag[row] = acc[mi][ni][0];
            if (row == col + 1) diag[row] = acc[mi][ni][1];
            if (row + 8 == col) diag[row + 8] = acc[mi][ni][2];
            if (row + 8 == col + 1) diag[row + 8] = acc[mi][ni][3];
            *(float2*)&C[(size_t)row * Nn + col] = make_float2(acc[mi][ni][0], acc[mi][ni][1]);
            *(float2*)&C[(size_t)(row + 8) * Nn + col] = make_float2(acc[mi][ni][2], acc[mi][ni][3]);
        }
    }
    float rs[4] = {0.0f, 0.0f, 0.0f, 0.0f};
#pragma unroll
    for (int mi = 0; mi < 2; mi++)
#pragma unroll
        for (int ni = 0; ni < 4; ni++) {
            rs[mi * 2 + 0] += acc[mi][ni][0] + acc[mi][ni][1];
            rs[mi * 2 + 1] += acc[mi][ni][2] + acc[mi][ni][3];
        }
#pragma unroll
    for (int q = 0; q < 4; q++) {
        rs[q] += __shfl_xor_sync(0xFFFFFFFF, rs[q], 1);
        rs[q] += __shfl_xor_sync(0xFFFFFFFF, rs[q], 2);
    }
    if ((lane & 3) == 0) {
        int rbase = m0 + wr * 32 + rl;
        atomicAdd(&deg[rbase], rs[0]);
        atomicAdd(&deg[rbase + 8], rs[1]);
        atomicAdd(&deg[rbase + 16], rs[2]);
        atomicAdd(&deg[rbase + 24], rs[3]);
    }
}

// plain fp32 64x64 tile GEMM; optional bias+relu applied to A-operand on load.
__global__ void sgemm64(const float* __restrict__ A, const float* __restrict__ B,
                        float* __restrict__ C, int M, int Nn, int K,
                        const float* __restrict__ abias) {
    __shared__ float As[16][64];
    __shared__ float Bs[16][64];
    int tx = threadIdx.x, ty = threadIdx.y;
    int tid = ty * 16 + tx;
    int m0 = blockIdx.y * 64, n0 = blockIdx.x * 64;
    float acc[4][4];
#pragma unroll
    for (int i = 0; i < 4; i++)
#pragma unroll
        for (int j = 0; j < 4; j++) acc[i][j] = 0.0f;
    int la_r = tid / 16, la_k = tid % 16;
    int lb_k = tid / 64, lb_n = tid % 64;
    for (int k0 = 0; k0 < K; k0 += 16) {
#pragma unroll
        for (int r = 0; r < 4; r++) {
            float v = A[(size_t)(m0 + la_r + 16 * r) * K + k0 + la_k];
            if (abias != nullptr) v = fmaxf(v + abias[k0 + la_k], 0.0f);
            As[la_k][la_r + 16 * r] = v;
        }
#pragma unroll
        for (int r = 0; r < 4; r++) {
            int kk = lb_k + 4 * r;
            Bs[kk][lb_n] = (n0 + lb_n < Nn) ? B[(size_t)(k0 + kk) * Nn + n0 + lb_n] : 0.0f;
        }
        __syncthreads();
#pragma unroll
        for (int k = 0; k < 16; k++) {
            float a[4], b[4];
#pragma unroll
            for (int i = 0; i < 4; i++) a[i] = As[k][ty * 4 + i];
#pragma unroll
            for (int j = 0; j < 4; j++) b[j] = Bs[k][tx * 4 + j];
#pragma unroll
            for (int i = 0; i < 4; i++)
#pragma unroll
                for (int j = 0; j < 4; j++) acc[i][j] += a[i] * b[j];
        }
        __syncthreads();
    }
#pragma unroll
    for (int i = 0; i < 4; i++) {
        int row = m0 + ty * 4 + i;
#pragma unroll
        for (int j = 0; j < 4; j++) {
            int col = n0 + tx * 4 + j;
            if (col < Nn) C[(size_t)row * Nn + col] = acc[i][j];
        }
    }
}

// split-K fp32 GEMM with fused gcn-norm on A: C += (Dv fix(A) Dv) @ B.
__global__ void sgemmKS(const float* __restrict__ A, const float* __restrict__ dv,
                        const float* __restrict__ B, float* __restrict__ C,
                        int Nn, int K, int KS, const float* __restrict__ bias) {
    __shared__ float As[16][64];
    __shared__ float Bs[16][64];
    int tx = threadIdx.x, ty = threadIdx.y;
    int tid = ty * 16 + tx;
    int m0 = blockIdx.y * 64;
    int kLen = K / KS;
    int kStart = blockIdx.x * kLen;
    float acc[4][4];
#pragma unroll
    for (int i = 0; i < 4; i++)
#pragma unroll
        for (int j = 0; j < 4; j++) acc[i][j] = 0.0f;
    int la_r = tid / 16, la_k = tid % 16;
    int lb_k = tid / 64, lb_n = tid % 64;
    for (int k0 = kStart; k0 < kStart + kLen; k0 += 16) {
#pragma unroll
        for (int r = 0; r < 4; r++) {
            int row = m0 + la_r + 16 * r;
            int kc = k0 + la_k;
            float v = A[(size_t)row * K + kc];
            if (row == kc && v == 0.0f) v = 1.0f;
            As[la_k][la_r + 16 * r] = v * dv[row] * dv[kc];
        }
#pragma unroll
        for (int r = 0; r < 4; r++) {
            int kk = lb_k + 4 * r;
            Bs[kk][lb_n] = (lb_n < Nn) ? B[(size_t)(k0 + kk) * Nn + lb_n] : 0.0f;
        }
        __syncthreads();
#pragma unroll
        for (int k = 0; k < 16; k++) {
            float a[4], b[4];
#pragma unroll
            for (int i = 0; i < 4; i++) a[i] = As[k][ty * 4 + i];
#pragma unroll
            for (int j = 0; j < 4; j++) b[j] = Bs[k][tx * 4 + j];
#pragma unroll
            for (int i = 0; i < 4; i++)
#pragma unroll
                for (int j = 0; j < 4; j++) acc[i][j] += a[i] * b[j];
        }
        __syncthreads();
    }
#pragma unroll
    for (int i = 0; i < 4; i++) {
        int row = m0 + ty * 4 + i;
#pragma unroll
        for (int j = 0; j < 4; j++) {
            int col = tx * 4 + j;
            if (col < Nn) {
                float v = acc[i][j];
                if (bias != nullptr && kStart == 0) v += bias[col];
                atomicAdd(&C[(size_t)row * Nn + col], v);
            }
        }
    }
}

// ---------------- host orchestration ----------------

extern "C" void kernel_launch(void* const* d_in, const int* in_sizes, int n_in,
                              void* d_out, int out_size) {
    const float* x = (const float*)d_in[0];
    const int* edges[5];
    for (int i = 0; i < 5; i++) edges[i] = (const int*)d_in[1 + i];
    const float* pbp[2][8];
    for (int b = 0; b < 2; b++)
        for (int i = 0; i < 8; i++) pbp[b][i] = (const float*)d_in[6 + b * 8 + i];
    const float* w1    = (const float*)d_in[22];
    const float* bias1 = (const float*)d_in[23];
    const float* w2    = (const float*)d_in[24];
    const float* bias2 = (const float*)d_in[25];
    float* out = (float*)d_out;

    float *A_, *p1_, *p2_, *att_, *M_, *Mt_, *An_, *dinv_, *deg_, *diag_, *XW_, *H_, *HW_;
    cudaGetSymbolAddress((void**)&A_,    g_A);
    cudaGetSymbolAddress((void**)&p1_,   g_p1);
    cudaGetSymbolAddress((void**)&p2_,   g_p2);
    cudaGetSymbolAddress((void**)&att_,  g_att);
    cudaGetSymbolAddress((void**)&M_,    g_M);
    cudaGetSymbolAddress((void**)&Mt_,   g_Mt);
    cudaGetSymbolAddress((void**)&An_,   g_An);
    cudaGetSymbolAddress((void**)&dinv_, g_dinv);
    cudaGetSymbolAddress((void**)&deg_,  g_deg);
    cudaGetSymbolAddress((void**)&diag_, g_diag);
    cudaGetSymbolAddress((void**)&XW_,   g_XW);
    cudaGetSymbolAddress((void**)&H_,    g_H);
    cudaGetSymbolAddress((void**)&HW_,   g_HW);

    const size_t PLANE = (size_t)NV * NV;
    dim3 blk16(16, 16);

    float* Ab[2]   = { A_,   A_   + 3 * PLANE };
    float* p1b[2]  = { p1_,  p1_  + (size_t)16 * 512 * 512 };
    float* p2b[2]  = { p2_,  p2_  + (size_t)4 * 257 * 257 };
    float* attb[2] = { att_, att_ + 3 * PLANE };
    float* Mb[2]   = { M_,   M_   + PLANE };
    float* Mtb[2]  = { Mt_,  Mt_  + PLANE };

    // -------- setup --------
    cudaMemsetAsync(A_, 0, 6 * PLANE * sizeof(float), 0);
    sgemm64<<<dim3(1, NV / 64), blk16>>>(x, w1, XW_, NV, HIDD, EMBD, nullptr);

    // -------- scatter all 5 edge lists (also zeros deg, H, out) --------
    Sc5 sc;
    sc.e[0] = edges[0]; sc.A[0] = Ab[0];
    sc.e[1] = edges[1]; sc.A[1] = Ab[0] + PLANE;
    sc.e[2] = edges[2]; sc.A[2] = Ab[1];
    sc.e[3] = edges[3]; sc.A[3] = Ab[1] + PLANE;
    sc.e[4] = edges[4]; sc.A[4] = Ab[1] + 2 * PLANE;
    sc.degz = deg_;
    sc.Hz = H_;
    sc.outz = out;
    scatter_all<<<dim3((NE + 255) / 256, 5), 256>>>(sc);

    // -------- conv encoder (both paths batched) --------
    PathPtrs c1 = {{Ab[0], Ab[1]}, {pbp[0][0], pbp[1][0]}, {pbp[0][1], pbp[1][1]}, {p1b[0], p1b[1]}};
    conv1mma_both<<<dim3(32, 32, 2), blk16>>>(c1);

    PathPtrs c2 = {{p1b[0], p1b[1]}, {pbp[0][2], pbp[1][2]}, {pbp[0][3], pbp[1][3]}, {p2b[0], p2b[1]}};
    conv2pool_both<<<dim3(17, 17, 2), blk16>>>(c2);

    // fused tconv1 + tconv2 + sigmoid + adjacency multiply + att0 deg/diag (4-wide)
    FAtt fa;
    for (int p = 0; p < 2; p++) {
        fa.p2[p] = p2b[p];
        fa.w1[p] = pbp[p][4]; fa.b1[p] = pbp[p][5];
        fa.w2[p] = pbp[p][6]; fa.b2[p] = pbp[p][7];
        fa.A[p] = Ab[p]; fa.att[p] = attb[p];
        fa.deg[p] = deg_ + p * NV; fa.diag[p] = diag_ + p * NV;
    }
    ftconv_att_both<<<2 * NV, 256>>>(fa);

    // -------- M-chain, norms + dv computed inside GEMMs --------
    {
        GemS gs;
        gs.A[0] = attb[0];          gs.A[1] = attb[1];
        gs.B[0] = attb[0] + PLANE;  gs.B[1] = attb[1] + PLANE;
        gs.C[0] = Mtb[0];           gs.C[1] = Mtb[1];
        gs.degIn[0] = deg_;         gs.degIn[1] = deg_ + NV;
        gs.diagIn[0] = diag_;       gs.diagIn[1] = diag_ + NV;
        gs.deg[0] = deg_ + 2 * NV;  gs.deg[1] = deg_ + 3 * NV;
        gs.diag[0] = diag_ + 2 * NV; gs.diag[1] = diag_ + 3 * NV;
        tf32gemm_s<<<dim3(NV / 64, NV / 128, 2), 256>>>(gs);
    }
    {
        GemS gs;
        gs.A[0] = Mtb[1];
        gs.B[0] = attb[1] + 2 * PLANE;
        gs.C[0] = Mb[1];
        gs.degIn[0] = deg_ + 3 * NV;
        gs.diagIn[0] = diag_ + 3 * NV;
        gs.deg[0] = deg_ + 4 * NV;
        gs.diag[0] = diag_ + 4 * NV;
        gs.A[1] = gs.A[0]; gs.B[1] = gs.B[0]; gs.C[1] = gs.C[0];
        gs.degIn[1] = gs.degIn[0]; gs.diagIn[1] = gs.diagIn[0];
        gs.deg[1] = gs.deg[0]; gs.diag[1] = gs.diag[0];
        tf32gemm_s<<<dim3(NV / 64, NV / 128, 1), 256>>>(gs);
    }

    // -------- scaled merge + final dinv (dv2/dv4 computed inline from deg/diag) --------
    emax_dinv<<<NV, 256>>>(Mtb[0], deg_ + 2 * NV, diag_ + 2 * NV,
                           Mb[1], deg_ + 4 * NV, diag_ + 4 * NV,
                           An_, dinv_ + 5 * NV);

    // -------- GCN layers, final norm fused into A-loads (split-K 16) --------
    sgemmKS<<<dim3(16, NV / 64), blk16>>>(An_, dinv_ + 5 * NV, XW_, H_, HIDD, NV, 16, nullptr);
    sgemm64<<<dim3(1, NV / 64), blk16>>>(H_, w2, HW_, NV, REPD, HIDD, bias1);  // relu(H+bias1) @ w2
    sgemmKS<<<dim3(16, NV / 64), blk16>>>(An_, dinv_ + 5 * NV, HW_, out, REPD, NV, 16, bias2);
}